// round 2
// baseline (speedup 1.0000x reference)
#include <cuda_runtime.h>
#include <cuda_bf16.h>
#include <math.h>

// Problem constants
#define BSZ 8
#define NN  15135
#define FF  64
#define GG  73
#define HH  256
#define HFCC 512
#define CCLS 2
#define EE  242160
#define KIN (FF + GG)        // 137
#define MM  (BSZ * NN)       // 121080

// ---------------- scratch (device globals; no dynamic alloc allowed) -------
__device__ float d_deg[NN];
__device__ float d_dis[NN];
__device__ float d_deginv[NN];
__device__ float d_hw[(size_t)MM * HH];   // ~124 MB
__device__ float d_h1[(size_t)MM * HH];
__device__ float d_h2[(size_t)MM * HH];
__device__ float d_h3[(size_t)MM * HH];
__device__ float d_g[MM];
__device__ float d_zacc[BSZ * HFCC];

__device__ __forceinline__ float eluf(float v) {
    return v > 0.0f ? v : expm1f(v);
}

// ---------------- degree kernels ----------------
__global__ void zero_deg_kernel() {
    int i = blockIdx.x * blockDim.x + threadIdx.x;
    if (i < NN) d_deg[i] = 0.0f;
}

__global__ void count_deg_kernel(const int* __restrict__ ei) {
    int e = blockIdx.x * blockDim.x + threadIdx.x;
    if (e < EE) {
        int c = ei[EE + e];
        atomicAdd(&d_deg[c], 1.0f);
    }
}

__global__ void fin_deg_kernel() {
    int i = blockIdx.x * blockDim.x + threadIdx.x;
    if (i < NN) {
        float d = d_deg[i] + 1.0f;
        d_dis[i]    = rsqrtf(d);
        d_deginv[i] = 1.0f / d;
    }
}

// ---------------- GEMM: layer 1 (concat input, K=137) ----------------
// A[m,k] = k<64 ? x[m*64+k] : pe[(m%NN)*73 + k-64]
// out: hw[m,j] = sum_k A*W1 ; hout[m,j] = hw*deginv[n] + bias[j]
__global__ __launch_bounds__(256) void gemm_l1_kernel(
    const float* __restrict__ x, const float* __restrict__ pe,
    const float* __restrict__ W, const float* __restrict__ bias,
    float* __restrict__ hw, float* __restrict__ hout)
{
    __shared__ float As[16][64];
    __shared__ float Bs[16][64];
    const int m0 = blockIdx.x * 64;
    const int j0 = blockIdx.y * 64;
    const int t  = threadIdx.x;
    const int tx = t % 16, ty = t / 16;

    // A-load coords (fixed per thread)
    const int ai  = t / 4;           // row within tile 0..63
    const int akk = (t % 4) * 4;     // k offset within tile
    const int am  = m0 + ai;
    const int an  = am % NN;         // node index (am < MM checked at use)

    // B-load coords
    const int bkk = t / 16;          // 0..15
    const int bjj = (t % 16) * 4;

    float acc[4][4];
    #pragma unroll
    for (int p = 0; p < 4; p++)
        #pragma unroll
        for (int q = 0; q < 4; q++) acc[p][q] = 0.0f;

    for (int k0 = 0; k0 < 144; k0 += 16) {
        // load A tile (scalar, concat + zero-pad)
        #pragma unroll
        for (int q = 0; q < 4; q++) {
            int k = k0 + akk + q;
            float v = 0.0f;
            if (am < MM && k < KIN) {
                v = (k < FF) ? x[(size_t)am * FF + k]
                             : pe[(size_t)an * GG + (k - FF)];
            }
            As[akk + q][ai] = v;
        }
        // load B tile
        {
            int k = k0 + bkk;
            #pragma unroll
            for (int q = 0; q < 4; q++) {
                Bs[bkk][bjj + q] = (k < KIN) ? W[(size_t)k * HH + j0 + bjj + q] : 0.0f;
            }
        }
        __syncthreads();
        #pragma unroll
        for (int kk = 0; kk < 16; kk++) {
            float a[4], b[4];
            #pragma unroll
            for (int q = 0; q < 4; q++) a[q] = As[kk][ty * 4 + q];
            #pragma unroll
            for (int q = 0; q < 4; q++) b[q] = Bs[kk][tx * 4 + q];
            #pragma unroll
            for (int p = 0; p < 4; p++)
                #pragma unroll
                for (int q = 0; q < 4; q++) acc[p][q] += a[p] * b[q];
        }
        __syncthreads();
    }

    #pragma unroll
    for (int p = 0; p < 4; p++) {
        int m = m0 + ty * 4 + p;
        if (m >= MM) continue;
        int n = m % NN;
        float di = d_deginv[n];
        #pragma unroll
        for (int q = 0; q < 4; q++) {
            int j = j0 + tx * 4 + q;
            float v = acc[p][q];
            hw[(size_t)m * HH + j]   = v;
            hout[(size_t)m * HH + j] = v * di + bias[j];
        }
    }
}

// ---------------- GEMM: K=256 layers ----------------
__global__ __launch_bounds__(256) void gemm256_kernel(
    const float* __restrict__ A, const float* __restrict__ W,
    const float* __restrict__ bias,
    float* __restrict__ hw, float* __restrict__ hout)
{
    __shared__ float As[16][64];
    __shared__ float Bs[16][64];
    const int m0 = blockIdx.x * 64;
    const int j0 = blockIdx.y * 64;
    const int t  = threadIdx.x;
    const int tx = t % 16, ty = t / 16;

    const int ai  = t / 4;
    const int akk = (t % 4) * 4;
    const int am  = m0 + ai;

    const int bkk = t / 16;
    const int bjj = (t % 16) * 4;

    float acc[4][4];
    #pragma unroll
    for (int p = 0; p < 4; p++)
        #pragma unroll
        for (int q = 0; q < 4; q++) acc[p][q] = 0.0f;

    for (int k0 = 0; k0 < 256; k0 += 16) {
        float4 av = make_float4(0.f, 0.f, 0.f, 0.f);
        if (am < MM)
            av = *reinterpret_cast<const float4*>(A + (size_t)am * 256 + k0 + akk);
        As[akk + 0][ai] = av.x;
        As[akk + 1][ai] = av.y;
        As[akk + 2][ai] = av.z;
        As[akk + 3][ai] = av.w;

        float4 bv = *reinterpret_cast<const float4*>(W + (size_t)(k0 + bkk) * HH + j0 + bjj);
        *reinterpret_cast<float4*>(&Bs[bkk][bjj]) = bv;
        __syncthreads();
        #pragma unroll
        for (int kk = 0; kk < 16; kk++) {
            float a[4], b[4];
            #pragma unroll
            for (int q = 0; q < 4; q++) a[q] = As[kk][ty * 4 + q];
            #pragma unroll
            for (int q = 0; q < 4; q++) b[q] = Bs[kk][tx * 4 + q];
            #pragma unroll
            for (int p = 0; p < 4; p++)
                #pragma unroll
                for (int q = 0; q < 4; q++) acc[p][q] += a[p] * b[q];
        }
        __syncthreads();
    }

    #pragma unroll
    for (int p = 0; p < 4; p++) {
        int m = m0 + ty * 4 + p;
        if (m >= MM) continue;
        int n = m % NN;
        float di = d_deginv[n];
        #pragma unroll
        for (int q = 0; q < 4; q++) {
            int j = j0 + tx * 4 + q;
            float v = acc[p][q];
            hw[(size_t)m * HH + j]   = v;
            hout[(size_t)m * HH + j] = v * di + bias[j];
        }
    }
}

// ---------------- edge scatter (message passing) ----------------
// grid: (ceil(E/16), BSZ); blockIdx.x fastest -> batch-serial waves => L2-resident
#define EPB 16
__global__ __launch_bounds__(256) void scatter_kernel(
    const float* __restrict__ hw, const int* __restrict__ ei,
    float* __restrict__ hout)
{
    const int b   = blockIdx.y;
    const int e0  = blockIdx.x * EPB;
    const int tid = threadIdx.x;
    const float* hwb = hw + (size_t)b * NN * HH;
    float* hob = hout + (size_t)b * NN * HH;
    #pragma unroll 1
    for (int ee = 0; ee < EPB; ee++) {
        int e = e0 + ee;
        if (e >= EE) break;
        int r = ei[e];
        int c = ei[EE + e];
        float nm = d_dis[r] * d_dis[c];
        float v = hwb[(size_t)r * HH + tid] * nm;
        atomicAdd(&hob[(size_t)c * HH + tid], v);
    }
}

// ---------------- ELU in-place ----------------
__global__ void elu_kernel(float* __restrict__ h, int n4) {
    int i = blockIdx.x * blockDim.x + threadIdx.x;
    if (i < n4) {
        float4 v = reinterpret_cast<float4*>(h)[i];
        v.x = eluf(v.x); v.y = eluf(v.y); v.z = eluf(v.z); v.w = eluf(v.w);
        reinterpret_cast<float4*>(h)[i] = v;
    }
}

// ---------------- fc: jumping-knowledge cat + 768->1 ----------------
__global__ __launch_bounds__(256) void fc_kernel(
    const float* __restrict__ fcW, const float* __restrict__ fcb)
{
    const int m = blockIdx.x;
    const int t = threadIdx.x;
    size_t base = (size_t)m * HH + t;
    float v = d_h1[base] * fcW[3 * t + 0]
            + d_h2[base] * fcW[3 * t + 1]
            + d_h3[base] * fcW[3 * t + 2];
    // block reduce 256
    __shared__ float red[8];
    int lane = t & 31, warp = t >> 5;
    #pragma unroll
    for (int o = 16; o > 0; o >>= 1) v += __shfl_down_sync(0xffffffffu, v, o);
    if (lane == 0) red[warp] = v;
    __syncthreads();
    if (t == 0) {
        float s = 0.0f;
        #pragma unroll
        for (int w = 0; w < 8; w++) s += red[w];
        d_g[m] = s + fcb[0];
    }
}

// ---------------- lin1: g[b,N] @ lin1_W[N,512] (accumulate) ----------------
__global__ void zero_zacc_kernel() {
    int i = blockIdx.x * blockDim.x + threadIdx.x;
    if (i < BSZ * HFCC) d_zacc[i] = 0.0f;
}

#define NCH 256
__global__ __launch_bounds__(128) void lin1_kernel(const float* __restrict__ W)
{
    __shared__ float gs[BSZ][NCH];
    const int j  = blockIdx.x * 128 + threadIdx.x;
    const int n0 = blockIdx.y * NCH;
    const int cn = min(NCH, NN - n0);
    for (int idx = threadIdx.x; idx < BSZ * NCH; idx += 128) {
        int b = idx >> 8;       // NCH == 256
        int nl = idx & (NCH - 1);
        gs[b][nl] = (nl < cn) ? d_g[(size_t)b * NN + n0 + nl] : 0.0f;
    }
    __syncthreads();
    float acc[BSZ];
    #pragma unroll
    for (int b = 0; b < BSZ; b++) acc[b] = 0.0f;
    for (int nl = 0; nl < cn; nl++) {
        float w = W[(size_t)(n0 + nl) * HFCC + j];
        #pragma unroll
        for (int b = 0; b < BSZ; b++) acc[b] += gs[b][nl] * w;
    }
    #pragma unroll
    for (int b = 0; b < BSZ; b++) atomicAdd(&d_zacc[b * HFCC + j], acc[b]);
}

// ---------------- lin2 + log_softmax ----------------
__global__ __launch_bounds__(256) void lin2_kernel(
    const float* __restrict__ lin1b, const float* __restrict__ lin2W,
    const float* __restrict__ lin2b, float* __restrict__ out)
{
    const int b = blockIdx.x;
    const int t = threadIdx.x;
    float s0 = 0.0f, s1 = 0.0f;
    for (int j = t; j < HFCC; j += 256) {
        float z = d_zacc[b * HFCC + j] + lin1b[j];
        z = eluf(z);
        s0 += z * lin2W[j * 2 + 0];
        s1 += z * lin2W[j * 2 + 1];
    }
    __shared__ float r0[256], r1[256];
    r0[t] = s0; r1[t] = s1;
    __syncthreads();
    for (int o = 128; o > 0; o >>= 1) {
        if (t < o) { r0[t] += r0[t + o]; r1[t] += r1[t + o]; }
        __syncthreads();
    }
    if (t == 0) {
        float o0 = r0[0] + lin2b[0];
        float o1 = r1[0] + lin2b[1];
        float mx = fmaxf(o0, o1);
        float lse = mx + logf(expf(o0 - mx) + expf(o1 - mx));
        out[b * CCLS + 0] = o0 - lse;
        out[b * CCLS + 1] = o1 - lse;
    }
}

// ---------------- launcher ----------------
extern "C" void kernel_launch(void* const* d_in, const int* in_sizes, int n_in,
                              void* d_out, int out_size)
{
    const float* x     = (const float*)d_in[0];
    // d_in[1] = batch (all zeros, unused)
    const int*   ei    = (const int*)d_in[2];   // int32 [2, E] (JAX x64 disabled)
    const float* pe    = (const float*)d_in[3];
    const float* W1    = (const float*)d_in[4];
    const float* b1    = (const float*)d_in[5];
    const float* W2    = (const float*)d_in[6];
    const float* b2    = (const float*)d_in[7];
    const float* W3    = (const float*)d_in[8];
    const float* b3    = (const float*)d_in[9];
    const float* fcW   = (const float*)d_in[10];
    const float* fcb   = (const float*)d_in[11];
    const float* lin1W = (const float*)d_in[12];
    const float* lin1b = (const float*)d_in[13];
    const float* lin2W = (const float*)d_in[14];
    const float* lin2b = (const float*)d_in[15];
    float* out = (float*)d_out;

    float *hwp, *h1p, *h2p, *h3p;
    cudaGetSymbolAddress((void**)&hwp, d_hw);
    cudaGetSymbolAddress((void**)&h1p, d_h1);
    cudaGetSymbolAddress((void**)&h2p, d_h2);
    cudaGetSymbolAddress((void**)&h3p, d_h3);

    // degrees
    zero_deg_kernel<<<(NN + 255) / 256, 256>>>();
    count_deg_kernel<<<(EE + 255) / 256, 256>>>(ei);
    fin_deg_kernel<<<(NN + 255) / 256, 256>>>();

    const dim3 ggrid((MM + 63) / 64, HH / 64);
    const dim3 sgrid((EE + EPB - 1) / EPB, BSZ);
    const int n4 = MM * HH / 4;
    const int eluBlocks = (n4 + 255) / 256;

    // layer 1
    gemm_l1_kernel<<<ggrid, 256>>>(x, pe, W1, b1, hwp, h1p);
    scatter_kernel<<<sgrid, 256>>>(hwp, ei, h1p);
    elu_kernel<<<eluBlocks, 256>>>(h1p, n4);

    // layer 2
    gemm256_kernel<<<ggrid, 256>>>(h1p, W2, b2, hwp, h2p);
    scatter_kernel<<<sgrid, 256>>>(hwp, ei, h2p);
    elu_kernel<<<eluBlocks, 256>>>(h2p, n4);

    // layer 3
    gemm256_kernel<<<ggrid, 256>>>(h2p, W3, b3, hwp, h3p);
    scatter_kernel<<<sgrid, 256>>>(hwp, ei, h3p);
    elu_kernel<<<eluBlocks, 256>>>(h3p, n4);

    // heads
    fc_kernel<<<MM, 256>>>(fcW, fcb);
    zero_zacc_kernel<<<(BSZ * HFCC + 255) / 256, 256>>>();
    lin1_kernel<<<dim3(HFCC / 128, (NN + NCH - 1) / NCH), 128>>>(lin1W);
    lin2_kernel<<<BSZ, 256>>>(lin1b, lin2W, lin2b, out);
}

// round 3
// speedup vs baseline: 1.6530x; 1.6530x over previous
#include <cuda_runtime.h>
#include <cuda_bf16.h>
#include <math.h>

// Problem constants
#define BSZ 8
#define NN  15135
#define FF  64
#define GG  73
#define HH  256
#define HFCC 512
#define CCLS 2
#define EE  242160
#define KIN (FF + GG)        // 137
#define MM  (BSZ * NN)       // 121080

typedef unsigned long long u64;

// ---------------- scratch (device globals; no dynamic alloc allowed) -------
__device__ int   d_degi[NN];
__device__ float d_dis[NN];
__device__ float d_deginv[NN];
__device__ int   d_csr_ptr[NN + 1];
__device__ int   d_cursor[NN];
__device__ int   d_csr_src[EE];
__device__ float d_csr_w[EE];
__device__ float d_hw[(size_t)MM * HH];   // ~124 MB
__device__ float d_h1[(size_t)MM * HH];
__device__ float d_h2[(size_t)MM * HH];
__device__ float d_g[MM];
__device__ float d_zacc[BSZ * HFCC];

__device__ __forceinline__ float eluf(float v) {
    return v > 0.0f ? v : expm1f(v);
}

// packed fp32x2 FMA (Blackwell): d = a*b + d elementwise on packed pairs
#define FFMA2(d, a, b) asm("fma.rn.f32x2 %0, %1, %2, %0;" : "+l"(d) : "l"(a), "l"(b))
#define PACK2_DUP(d, x) asm("mov.b64 %0, {%1, %1};" : "=l"(d) : "f"(x))
#define UNPACK2(lo, hi, d) asm("mov.b64 {%0, %1}, %2;" : "=f"(lo), "=f"(hi) : "l"(d))

// ---------------- degree / CSR build ----------------
__global__ void zero_deg_kernel() {
    int i = blockIdx.x * blockDim.x + threadIdx.x;
    if (i < NN) d_degi[i] = 0;
}

__global__ void count_deg_kernel(const int* __restrict__ ei) {
    int e = blockIdx.x * blockDim.x + threadIdx.x;
    if (e < EE) atomicAdd(&d_degi[ei[EE + e]], 1);
}

__global__ void fin_deg_kernel() {
    int i = blockIdx.x * blockDim.x + threadIdx.x;
    if (i < NN) {
        float d = (float)d_degi[i] + 1.0f;
        d_dis[i]    = rsqrtf(d);
        d_deginv[i] = 1.0f / d;
    }
}

// single-block exclusive prefix sum over d_degi -> d_csr_ptr, d_cursor
__global__ __launch_bounds__(1024) void scan_kernel() {
    __shared__ int sh[1024];
    __shared__ int soff;
    const int t = threadIdx.x;
    if (t == 0) soff = 0;
    __syncthreads();
    for (int base = 0; base < NN; base += 1024) {
        int v = (base + t < NN) ? d_degi[base + t] : 0;
        sh[t] = v;
        __syncthreads();
        for (int off = 1; off < 1024; off <<= 1) {
            int add = (t >= off) ? sh[t - off] : 0;
            __syncthreads();
            sh[t] += add;
            __syncthreads();
        }
        int excl = sh[t] - v + soff;
        if (base + t < NN) {
            d_csr_ptr[base + t] = excl;
            d_cursor[base + t]  = excl;
        }
        __syncthreads();
        if (t == 1023) soff += sh[1023];
        __syncthreads();
    }
    if (t == 0) d_csr_ptr[NN] = soff;
}

__global__ void fill_csr_kernel(const int* __restrict__ ei) {
    int e = blockIdx.x * blockDim.x + threadIdx.x;
    if (e < EE) {
        int r = ei[e];
        int c = ei[EE + e];
        int pos = atomicAdd(&d_cursor[c], 1);
        d_csr_src[pos] = r;
        d_csr_w[pos]   = d_dis[r] * d_dis[c];
    }
}

// ---------------- GEMM common: 128x128 block, 8x8/thread, FFMA2 ----------------
#define ASTR 132   // padded shared stride (floats)

// K=256 layers. A row-major [MM,256], W [256,256]. Writes hw only.
__global__ __launch_bounds__(256, 2) void gemm256_kernel(
    const float* __restrict__ A, const float* __restrict__ W,
    float* __restrict__ hw)
{
    __shared__ float As[16][ASTR];
    __shared__ float Bs[16][ASTR];
    const int m0 = blockIdx.x * 128;
    const int j0 = blockIdx.y * 128;
    const int t  = threadIdx.x;
    const int tx = t % 16, ty = t / 16;

    u64 acc2[8][4];
    #pragma unroll
    for (int p = 0; p < 8; p++)
        #pragma unroll
        for (int q = 0; q < 4; q++) acc2[p][q] = 0ull;

    for (int k0 = 0; k0 < 256; k0 += 16) {
        // A tile: 128 rows x 16 k, transposed store
        #pragma unroll
        for (int r = 0; r < 2; r++) {
            int l   = t + r * 256;
            int row = l >> 2;
            int kq  = (l & 3) * 4;
            int am  = m0 + row;
            float4 v = make_float4(0.f, 0.f, 0.f, 0.f);
            if (am < MM)
                v = *reinterpret_cast<const float4*>(A + (size_t)am * 256 + k0 + kq);
            As[kq + 0][row] = v.x;
            As[kq + 1][row] = v.y;
            As[kq + 2][row] = v.z;
            As[kq + 3][row] = v.w;
        }
        // B tile: 16 k x 128 cols
        #pragma unroll
        for (int r = 0; r < 2; r++) {
            int l    = t + r * 256;
            int krow = l >> 5;
            int cq   = (l & 31) * 4;
            float4 v = *reinterpret_cast<const float4*>(W + (size_t)(k0 + krow) * HH + j0 + cq);
            *reinterpret_cast<float4*>(&Bs[krow][cq]) = v;
        }
        __syncthreads();
        #pragma unroll
        for (int kk = 0; kk < 16; kk++) {
            float4 av0 = *reinterpret_cast<const float4*>(&As[kk][ty * 8]);
            float4 av1 = *reinterpret_cast<const float4*>(&As[kk][ty * 8 + 4]);
            ulonglong2 bv0 = *reinterpret_cast<const ulonglong2*>(&Bs[kk][tx * 8]);
            ulonglong2 bv1 = *reinterpret_cast<const ulonglong2*>(&Bs[kk][tx * 8 + 4]);
            u64 b2[4] = {bv0.x, bv0.y, bv1.x, bv1.y};
            float av[8] = {av0.x, av0.y, av0.z, av0.w, av1.x, av1.y, av1.z, av1.w};
            #pragma unroll
            for (int p = 0; p < 8; p++) {
                u64 a2;
                PACK2_DUP(a2, av[p]);
                #pragma unroll
                for (int q = 0; q < 4; q++) FFMA2(acc2[p][q], a2, b2[q]);
            }
        }
        __syncthreads();
    }

    #pragma unroll
    for (int p = 0; p < 8; p++) {
        int m = m0 + ty * 8 + p;
        if (m >= MM) continue;
        float c[8];
        #pragma unroll
        for (int q = 0; q < 4; q++) UNPACK2(c[2 * q], c[2 * q + 1], acc2[p][q]);
        float* dst = hw + (size_t)m * HH + j0 + tx * 8;
        *reinterpret_cast<float4*>(dst)     = make_float4(c[0], c[1], c[2], c[3]);
        *reinterpret_cast<float4*>(dst + 4) = make_float4(c[4], c[5], c[6], c[7]);
    }
}

// Layer 1: A[m,k] = k<64 ? x : pe (concat), K padded to 144
__global__ __launch_bounds__(256, 2) void gemm_l1_kernel(
    const float* __restrict__ x, const float* __restrict__ pe,
    const float* __restrict__ W, float* __restrict__ hw)
{
    __shared__ float As[16][ASTR];
    __shared__ float Bs[16][ASTR];
    const int m0 = blockIdx.x * 128;
    const int j0 = blockIdx.y * 128;
    const int t  = threadIdx.x;
    const int tx = t % 16, ty = t / 16;

    u64 acc2[8][4];
    #pragma unroll
    for (int p = 0; p < 8; p++)
        #pragma unroll
        for (int q = 0; q < 4; q++) acc2[p][q] = 0ull;

    for (int k0 = 0; k0 < 144; k0 += 16) {
        #pragma unroll
        for (int r = 0; r < 2; r++) {
            int l   = t + r * 256;
            int row = l >> 2;
            int kq  = (l & 3) * 4;
            int am  = m0 + row;
            int an  = am % NN;
            #pragma unroll
            for (int i = 0; i < 4; i++) {
                int k = k0 + kq + i;
                float v = 0.0f;
                if (am < MM && k < KIN) {
                    v = (k < FF) ? x[(size_t)am * FF + k]
                                 : pe[(size_t)an * GG + (k - FF)];
                }
                As[kq + i][row] = v;
            }
        }
        #pragma unroll
        for (int r = 0; r < 2; r++) {
            int l    = t + r * 256;
            int krow = l >> 5;
            int cq   = (l & 31) * 4;
            int k    = k0 + krow;
            float4 v = make_float4(0.f, 0.f, 0.f, 0.f);
            if (k < KIN)
                v = *reinterpret_cast<const float4*>(W + (size_t)k * HH + j0 + cq);
            *reinterpret_cast<float4*>(&Bs[krow][cq]) = v;
        }
        __syncthreads();
        #pragma unroll
        for (int kk = 0; kk < 16; kk++) {
            float4 av0 = *reinterpret_cast<const float4*>(&As[kk][ty * 8]);
            float4 av1 = *reinterpret_cast<const float4*>(&As[kk][ty * 8 + 4]);
            ulonglong2 bv0 = *reinterpret_cast<const ulonglong2*>(&Bs[kk][tx * 8]);
            ulonglong2 bv1 = *reinterpret_cast<const ulonglong2*>(&Bs[kk][tx * 8 + 4]);
            u64 b2[4] = {bv0.x, bv0.y, bv1.x, bv1.y};
            float av[8] = {av0.x, av0.y, av0.z, av0.w, av1.x, av1.y, av1.z, av1.w};
            #pragma unroll
            for (int p = 0; p < 8; p++) {
                u64 a2;
                PACK2_DUP(a2, av[p]);
                #pragma unroll
                for (int q = 0; q < 4; q++) FFMA2(acc2[p][q], a2, b2[q]);
            }
        }
        __syncthreads();
    }

    #pragma unroll
    for (int p = 0; p < 8; p++) {
        int m = m0 + ty * 8 + p;
        if (m >= MM) continue;
        float c[8];
        #pragma unroll
        for (int q = 0; q < 4; q++) UNPACK2(c[2 * q], c[2 * q + 1], acc2[p][q]);
        float* dst = hw + (size_t)m * HH + j0 + tx * 8;
        *reinterpret_cast<float4*>(dst)     = make_float4(c[0], c[1], c[2], c[3]);
        *reinterpret_cast<float4*>(dst + 4) = make_float4(c[4], c[5], c[6], c[7]);
    }
}

// ---------------- CSR gather: agg + self-loop + bias + ELU ----------------
// grid: (NN, BSZ); block 256 = feature dim. FUSE_FC additionally computes the
// jumping-knowledge fc dot (h1,h2,h3) and writes d_g instead of storing h3.
template <bool FUSE_FC>
__global__ __launch_bounds__(256) void gather_kernel(
    const float* __restrict__ hw, const float* __restrict__ bias,
    float* __restrict__ hout,
    const float* __restrict__ fcW, const float* __restrict__ fcb)
{
    __shared__ int   ssrc[256];
    __shared__ float swt[256];
    const int n = blockIdx.x;
    const int b = blockIdx.y;
    const int t = threadIdx.x;
    const float* hwb = hw + (size_t)b * NN * HH;

    const int p0 = d_csr_ptr[n];
    const int p1 = d_csr_ptr[n + 1];

    float acc = 0.0f;
    for (int base = p0; base < p1; base += 256) {
        int idx = base + t;
        if (idx < p1) {
            ssrc[t] = d_csr_src[idx];
            swt[t]  = d_csr_w[idx];
        }
        __syncthreads();
        int cnt = min(256, p1 - base);
        #pragma unroll 4
        for (int i = 0; i < cnt; i++) {
            acc += hwb[(size_t)ssrc[i] * HH + t] * swt[i];
        }
        __syncthreads();
    }
    float v = acc + hwb[(size_t)n * HH + t] * d_deginv[n] + bias[t];
    v = eluf(v);

    size_t mbase = ((size_t)b * NN + n) * HH + t;
    if (!FUSE_FC) {
        hout[mbase] = v;
    } else {
        // fc: g[m] = sum_t (h1*w0 + h2*w1 + h3*w2) + fcb
        float s = d_h1[mbase] * fcW[3 * t + 0]
                + d_h2[mbase] * fcW[3 * t + 1]
                + v           * fcW[3 * t + 2];
        __shared__ float red[8];
        int lane = t & 31, warp = t >> 5;
        #pragma unroll
        for (int o = 16; o > 0; o >>= 1) s += __shfl_down_sync(0xffffffffu, s, o);
        if (lane == 0) red[warp] = s;
        __syncthreads();
        if (t == 0) {
            float g = 0.0f;
            #pragma unroll
            for (int w = 0; w < 8; w++) g += red[w];
            d_g[(size_t)b * NN + n] = g + fcb[0];
        }
    }
}

// ---------------- lin1: g[b,N] @ lin1_W[N,512] (accumulate) ----------------
__global__ void zero_zacc_kernel() {
    int i = blockIdx.x * blockDim.x + threadIdx.x;
    if (i < BSZ * HFCC) d_zacc[i] = 0.0f;
}

#define NCH 256
__global__ __launch_bounds__(128) void lin1_kernel(const float* __restrict__ W)
{
    __shared__ float gs[BSZ][NCH];
    const int j  = blockIdx.x * 128 + threadIdx.x;
    const int n0 = blockIdx.y * NCH;
    const int cn = min(NCH, NN - n0);
    for (int idx = threadIdx.x; idx < BSZ * NCH; idx += 128) {
        int b  = idx >> 8;       // NCH == 256
        int nl = idx & (NCH - 1);
        gs[b][nl] = (nl < cn) ? d_g[(size_t)b * NN + n0 + nl] : 0.0f;
    }
    __syncthreads();
    float acc[BSZ];
    #pragma unroll
    for (int b = 0; b < BSZ; b++) acc[b] = 0.0f;
    for (int nl = 0; nl < cn; nl++) {
        float w = W[(size_t)(n0 + nl) * HFCC + j];
        #pragma unroll
        for (int b = 0; b < BSZ; b++) acc[b] += gs[b][nl] * w;
    }
    #pragma unroll
    for (int b = 0; b < BSZ; b++) atomicAdd(&d_zacc[b * HFCC + j], acc[b]);
}

// ---------------- lin2 + log_softmax ----------------
__global__ __launch_bounds__(256) void lin2_kernel(
    const float* __restrict__ lin1b, const float* __restrict__ lin2W,
    const float* __restrict__ lin2b, float* __restrict__ out)
{
    const int b = blockIdx.x;
    const int t = threadIdx.x;
    float s0 = 0.0f, s1 = 0.0f;
    for (int j = t; j < HFCC; j += 256) {
        float z = d_zacc[b * HFCC + j] + lin1b[j];
        z = eluf(z);
        s0 += z * lin2W[j * 2 + 0];
        s1 += z * lin2W[j * 2 + 1];
    }
    __shared__ float r0[256], r1[256];
    r0[t] = s0; r1[t] = s1;
    __syncthreads();
    for (int o = 128; o > 0; o >>= 1) {
        if (t < o) { r0[t] += r0[t + o]; r1[t] += r1[t + o]; }
        __syncthreads();
    }
    if (t == 0) {
        float o0 = r0[0] + lin2b[0];
        float o1 = r1[0] + lin2b[1];
        float mx = fmaxf(o0, o1);
        float lse = mx + logf(expf(o0 - mx) + expf(o1 - mx));
        out[b * CCLS + 0] = o0 - lse;
        out[b * CCLS + 1] = o1 - lse;
    }
}

// ---------------- launcher ----------------
extern "C" void kernel_launch(void* const* d_in, const int* in_sizes, int n_in,
                              void* d_out, int out_size)
{
    const float* x     = (const float*)d_in[0];
    // d_in[1] = batch (all zeros, unused)
    const int*   ei    = (const int*)d_in[2];   // int32 [2, E]
    const float* pe    = (const float*)d_in[3];
    const float* W1    = (const float*)d_in[4];
    const float* b1    = (const float*)d_in[5];
    const float* W2    = (const float*)d_in[6];
    const float* b2    = (const float*)d_in[7];
    const float* W3    = (const float*)d_in[8];
    const float* b3    = (const float*)d_in[9];
    const float* fcW   = (const float*)d_in[10];
    const float* fcb   = (const float*)d_in[11];
    const float* lin1W = (const float*)d_in[12];
    const float* lin1b = (const float*)d_in[13];
    const float* lin2W = (const float*)d_in[14];
    const float* lin2b = (const float*)d_in[15];
    float* out = (float*)d_out;

    float *hwp, *h1p, *h2p;
    cudaGetSymbolAddress((void**)&hwp, d_hw);
    cudaGetSymbolAddress((void**)&h1p, d_h1);
    cudaGetSymbolAddress((void**)&h2p, d_h2);

    // degrees + CSR
    zero_deg_kernel<<<(NN + 255) / 256, 256>>>();
    count_deg_kernel<<<(EE + 255) / 256, 256>>>(ei);
    fin_deg_kernel<<<(NN + 255) / 256, 256>>>();
    scan_kernel<<<1, 1024>>>();
    fill_csr_kernel<<<(EE + 255) / 256, 256>>>(ei);

    const dim3 ggrid((MM + 127) / 128, HH / 128);
    const dim3 agrid(NN, BSZ);

    // layer 1
    gemm_l1_kernel<<<ggrid, 256>>>(x, pe, W1, hwp);
    gather_kernel<false><<<agrid, 256>>>(hwp, b1, h1p, nullptr, nullptr);

    // layer 2
    gemm256_kernel<<<ggrid, 256>>>(h1p, W2, hwp);
    gather_kernel<false><<<agrid, 256>>>(hwp, b2, h2p, nullptr, nullptr);

    // layer 3 (+ fused fc head -> d_g; h3 never materialized)
    gemm256_kernel<<<ggrid, 256>>>(h2p, W3, hwp);
    gather_kernel<true><<<agrid, 256>>>(hwp, b3, nullptr, fcW, fcb);

    // heads
    zero_zacc_kernel<<<(BSZ * HFCC + 255) / 256, 256>>>();
    lin1_kernel<<<dim3(HFCC / 128, (NN + NCH - 1) / NCH), 128>>>(lin1W);
    lin2_kernel<<<BSZ, 256>>>(lin1b, lin2W, lin2b, out);
}

// round 5
// speedup vs baseline: 3.0266x; 1.8310x over previous
#include <cuda_runtime.h>
#include <cuda_bf16.h>
#include <math.h>
#include <cstdint>

// Problem constants
#define BSZ 8
#define NN  15135
#define FF  64
#define GG  73
#define HH  256
#define HFCC 512
#define CCLS 2
#define EE  242160
#define KIN (FF + GG)        // 137
#define MM  (BSZ * NN)       // 121080
#define K1PAD 160            // layer-1 K padded to multiple of 32

// ---------------- scratch (device globals; no dynamic alloc allowed) -------
__device__ int   d_degi[NN];
__device__ float d_dis[NN];
__device__ float d_deginv[NN];
__device__ int   d_csr_ptr[NN + 1];
__device__ int   d_cursor[NN];
__device__ int   d_csr_src[EE];
__device__ float d_csr_w[EE];
__device__ float d_hw[(size_t)MM * HH];   // ~124 MB
__device__ float d_h1[(size_t)MM * HH];
__device__ float d_h2[(size_t)MM * HH];
__device__ float d_a1[(size_t)MM * K1PAD]; // concat(x,pe) zero-padded
__device__ float d_wt1[HH * K1PAD];        // W1^T padded
__device__ float d_wt2[HH * HH];           // W2^T
__device__ float d_wt3[HH * HH];           // W3^T
__device__ float d_g[MM];
__device__ float d_zacc[BSZ * HFCC];

__device__ __forceinline__ float eluf(float v) {
    return v > 0.0f ? v : expm1f(v);
}

// ---------------- degree / CSR build ----------------
__global__ void zero_deg_kernel() {
    int i = blockIdx.x * blockDim.x + threadIdx.x;
    if (i < NN) d_degi[i] = 0;
}

__global__ void count_deg_kernel(const int* __restrict__ ei) {
    int e = blockIdx.x * blockDim.x + threadIdx.x;
    if (e < EE) atomicAdd(&d_degi[ei[EE + e]], 1);
}

__global__ void fin_deg_kernel() {
    int i = blockIdx.x * blockDim.x + threadIdx.x;
    if (i < NN) {
        float d = (float)d_degi[i] + 1.0f;
        d_dis[i]    = rsqrtf(d);
        d_deginv[i] = 1.0f / d;
    }
}

// single-block exclusive prefix sum over d_degi -> d_csr_ptr, d_cursor
__global__ __launch_bounds__(1024) void scan_kernel() {
    __shared__ int sh[1024];
    __shared__ int soff;
    const int t = threadIdx.x;
    if (t == 0) soff = 0;
    __syncthreads();
    for (int base = 0; base < NN; base += 1024) {
        int v = (base + t < NN) ? d_degi[base + t] : 0;
        sh[t] = v;
        __syncthreads();
        for (int off = 1; off < 1024; off <<= 1) {
            int add = (t >= off) ? sh[t - off] : 0;
            __syncthreads();
            sh[t] += add;
            __syncthreads();
        }
        int excl = sh[t] - v + soff;
        if (base + t < NN) {
            d_csr_ptr[base + t] = excl;
            d_cursor[base + t]  = excl;
        }
        __syncthreads();
        if (t == 1023) soff += sh[1023];
        __syncthreads();
    }
    if (t == 0) d_csr_ptr[NN] = soff;
}

__global__ void fill_csr_kernel(const int* __restrict__ ei) {
    int e = blockIdx.x * blockDim.x + threadIdx.x;
    if (e < EE) {
        int r = ei[e];
        int c = ei[EE + e];
        int pos = atomicAdd(&d_cursor[c], 1);
        d_csr_src[pos] = r;
        d_csr_w[pos]   = d_dis[r] * d_dis[c];
    }
}

// ---------------- GEMM prep kernels ----------------
__global__ void build_a1_kernel(const float* __restrict__ x,
                                const float* __restrict__ pe) {
    long long i = (long long)blockIdx.x * blockDim.x + threadIdx.x;
    if (i >= (long long)MM * K1PAD) return;
    int m = (int)(i / K1PAD);
    int k = (int)(i % K1PAD);
    float v = 0.0f;
    if (k < FF) v = x[(size_t)m * FF + k];
    else if (k < KIN) v = pe[(size_t)(m % NN) * GG + (k - FF)];
    d_a1[i] = v;
}

// Wt[n][k] = k<Kin ? W[k][n] : 0 ; grid = HH blocks
__global__ void transpose_w_kernel(const float* __restrict__ W, int Kin,
                                   float* __restrict__ Wt, int KPAD) {
    int n = blockIdx.x;
    for (int k = threadIdx.x; k < KPAD; k += blockDim.x)
        Wt[(size_t)n * KPAD + k] = (k < Kin) ? W[(size_t)k * HH + n] : 0.0f;
}

// ================= mma.sync tf32 GEMM (sm_80 baseline PTX) ==================
__device__ __forceinline__ void cp_async16(uint32_t dst, const void* src, int sz) {
    asm volatile("cp.async.cg.shared.global [%0], [%1], 16, %2;"
                 :: "r"(dst), "l"(src), "r"(sz) : "memory");
}

__device__ __forceinline__ void mma_tf32(float* c, const uint32_t* a, const uint32_t* b) {
    asm volatile(
        "mma.sync.aligned.m16n8k8.row.col.f32.tf32.tf32.f32 "
        "{%0,%1,%2,%3}, {%4,%5,%6,%7}, {%8,%9}, {%0,%1,%2,%3};"
        : "+f"(c[0]), "+f"(c[1]), "+f"(c[2]), "+f"(c[3])
        : "r"(a[0]), "r"(a[1]), "r"(a[2]), "r"(a[3]), "r"(b[0]), "r"(b[1]));
}

// hw[M,256] = A[M,KPAD] @ Wt[256,KPAD]^T. CTA 128x128, 8 warps (2m x 4n),
// warp tile 64x32. K chunks of 32, cp.async double buffer, smem stride 36.
#define GSTR 36
#define GBUF (2 * 128 * GSTR)               // floats per buffer (A + B)
#define GSM_BYTES (2 * GBUF * 4)            // 73728

template <int KPAD>
__global__ __launch_bounds__(256, 2) void gemm_mma_kernel(
    const float* __restrict__ A, const float* __restrict__ Wt,
    float* __restrict__ hw)
{
    extern __shared__ float sm[];
    constexpr int NC = KPAD / 32;
    const int t    = threadIdx.x;
    const int lane = t & 31;
    const int wid  = t >> 5;
    const int wm   = wid >> 2;          // 0..1 -> m offset 64*wm
    const int wn   = wid & 3;           // 0..3 -> n offset 32*wn
    const int m0   = blockIdx.x * 128;
    const int n0   = blockIdx.y * 128;
    const int g    = lane >> 2;         // group id 0..7
    const int q    = lane & 3;          // thread in group

    float acc[4][4][4];
    #pragma unroll
    for (int mi = 0; mi < 4; mi++)
        #pragma unroll
        for (int nj = 0; nj < 4; nj++)
            #pragma unroll
            for (int r = 0; r < 4; r++) acc[mi][nj][r] = 0.0f;

    // chunk loader: chunk ci -> buffer buf
    auto load_chunk = [&](int ci, int buf) {
        float* dA = sm + buf * GBUF;
        float* dB = dA + 128 * GSTR;
        const int k0 = ci * 32;
        #pragma unroll
        for (int r = 0; r < 4; r++) {
            int idx = t + r * 256;
            int row = idx >> 3;         // 0..127
            int ch  = idx & 7;          // 16B chunk within 128B row
            int m   = m0 + row;
            int valid = (m < MM);
            const float* srcA = A + (size_t)(valid ? m : 0) * KPAD + k0 + ch * 4;
            cp_async16((uint32_t)__cvta_generic_to_shared(dA + row * GSTR + ch * 4),
                       srcA, valid ? 16 : 0);
            const float* srcB = Wt + (size_t)(n0 + row) * KPAD + k0 + ch * 4;
            cp_async16((uint32_t)__cvta_generic_to_shared(dB + row * GSTR + ch * 4),
                       srcB, 16);
        }
        asm volatile("cp.async.commit_group;" ::: "memory");
    };

    load_chunk(0, 0);
    if (NC > 1) load_chunk(1, 1);
    else        asm volatile("cp.async.commit_group;" ::: "memory");

    #pragma unroll 1
    for (int i = 0; i < NC; i++) {
        asm volatile("cp.async.wait_group 1;" ::: "memory");
        __syncthreads();
        const uint32_t* As = (const uint32_t*)(sm + (i & 1) * GBUF);
        const uint32_t* Bs = As + 128 * GSTR;

        #pragma unroll
        for (int ks = 0; ks < 4; ks++) {
            const int k = ks * 8 + q;
            uint32_t a[4][4], b[4][2];
            #pragma unroll
            for (int mi = 0; mi < 4; mi++) {
                int r = wm * 64 + mi * 16 + g;
                a[mi][0] = As[r * GSTR + k];
                a[mi][1] = As[(r + 8) * GSTR + k];
                a[mi][2] = As[r * GSTR + k + 4];
                a[mi][3] = As[(r + 8) * GSTR + k + 4];
            }
            #pragma unroll
            for (int nj = 0; nj < 4; nj++) {
                int n = wn * 32 + nj * 8 + g;
                b[nj][0] = Bs[n * GSTR + k];
                b[nj][1] = Bs[n * GSTR + k + 4];
            }
            #pragma unroll
            for (int mi = 0; mi < 4; mi++)
                #pragma unroll
                for (int nj = 0; nj < 4; nj++)
                    mma_tf32(acc[mi][nj], a[mi], b[nj]);
        }
        __syncthreads();
        if (i + 2 < NC) load_chunk(i + 2, i & 1);
        else            asm volatile("cp.async.commit_group;" ::: "memory");
    }

    // epilogue: direct stores
    #pragma unroll
    for (int mi = 0; mi < 4; mi++) {
        int r = m0 + wm * 64 + mi * 16 + g;
        #pragma unroll
        for (int nj = 0; nj < 4; nj++) {
            int c = n0 + wn * 32 + nj * 8 + q * 2;
            if (r < MM)
                *reinterpret_cast<float2*>(hw + (size_t)r * HH + c) =
                    make_float2(acc[mi][nj][0], acc[mi][nj][1]);
            if (r + 8 < MM)
                *reinterpret_cast<float2*>(hw + (size_t)(r + 8) * HH + c) =
                    make_float2(acc[mi][nj][2], acc[mi][nj][3]);
        }
    }
}

// ---------------- CSR gather: agg + self-loop + bias + ELU ------------------
// grid: (NN, BSZ/2); each block handles batches b and b+4.
template <bool FUSE_FC>
__global__ __launch_bounds__(256) void gather_kernel(
    const float* __restrict__ hw, const float* __restrict__ bias,
    float* __restrict__ hout,
    const float* __restrict__ fcW, const float* __restrict__ fcb)
{
    __shared__ int   ssrc[256];
    __shared__ float swt[256];
    const int n  = blockIdx.x;
    const int b0 = blockIdx.y;
    const int b1 = blockIdx.y + 4;
    const int t  = threadIdx.x;
    const float* hb0 = hw + (size_t)b0 * NN * HH;
    const float* hb1 = hw + (size_t)b1 * NN * HH;

    const int p0 = d_csr_ptr[n];
    const int p1 = d_csr_ptr[n + 1];

    float acc0 = 0.0f, acc1 = 0.0f;
    for (int base = p0; base < p1; base += 256) {
        int idx = base + t;
        if (idx < p1) {
            ssrc[t] = d_csr_src[idx];
            swt[t]  = d_csr_w[idx];
        }
        __syncthreads();
        int cnt = min(256, p1 - base);
        #pragma unroll 4
        for (int i = 0; i < cnt; i++) {
            size_t ro = (size_t)ssrc[i] * HH + t;
            float w = swt[i];
            acc0 += hb0[ro] * w;
            acc1 += hb1[ro] * w;
        }
        __syncthreads();
    }
    const float di = d_deginv[n];
    const float bs = bias[t];
    float v0 = eluf(acc0 + hb0[(size_t)n * HH + t] * di + bs);
    float v1 = eluf(acc1 + hb1[(size_t)n * HH + t] * di + bs);

    size_t mb0 = ((size_t)b0 * NN + n) * HH + t;
    size_t mb1 = ((size_t)b1 * NN + n) * HH + t;
    if (!FUSE_FC) {
        hout[mb0] = v0;
        hout[mb1] = v1;
    } else {
        float w0 = fcW[3 * t + 0], w1 = fcW[3 * t + 1], w2 = fcW[3 * t + 2];
        float s0 = d_h1[mb0] * w0 + d_h2[mb0] * w1 + v0 * w2;
        float s1 = d_h1[mb1] * w0 + d_h2[mb1] * w1 + v1 * w2;
        __shared__ float red0[8], red1[8];
        int lane = t & 31, warp = t >> 5;
        #pragma unroll
        for (int o = 16; o > 0; o >>= 1) {
            s0 += __shfl_down_sync(0xffffffffu, s0, o);
            s1 += __shfl_down_sync(0xffffffffu, s1, o);
        }
        if (lane == 0) { red0[warp] = s0; red1[warp] = s1; }
        __syncthreads();
        if (t == 0) {
            float g0 = 0.0f, g1 = 0.0f;
            #pragma unroll
            for (int w = 0; w < 8; w++) { g0 += red0[w]; g1 += red1[w]; }
            d_g[(size_t)b0 * NN + n] = g0 + fcb[0];
            d_g[(size_t)b1 * NN + n] = g1 + fcb[0];
        }
    }
}

// ---------------- lin1: g[b,N] @ lin1_W[N,512] (accumulate) ----------------
__global__ void zero_zacc_kernel() {
    int i = blockIdx.x * blockDim.x + threadIdx.x;
    if (i < BSZ * HFCC) d_zacc[i] = 0.0f;
}

#define NCH 256
__global__ __launch_bounds__(128) void lin1_kernel(const float* __restrict__ W)
{
    __shared__ float gs[BSZ][NCH];
    const int j  = blockIdx.x * 128 + threadIdx.x;
    const int n0 = blockIdx.y * NCH;
    const int cn = min(NCH, NN - n0);
    for (int idx = threadIdx.x; idx < BSZ * NCH; idx += 128) {
        int b  = idx >> 8;       // NCH == 256
        int nl = idx & (NCH - 1);
        gs[b][nl] = (nl < cn) ? d_g[(size_t)b * NN + n0 + nl] : 0.0f;
    }
    __syncthreads();
    float acc[BSZ];
    #pragma unroll
    for (int b = 0; b < BSZ; b++) acc[b] = 0.0f;
    for (int nl = 0; nl < cn; nl++) {
        float w = W[(size_t)(n0 + nl) * HFCC + j];
        #pragma unroll
        for (int b = 0; b < BSZ; b++) acc[b] += gs[b][nl] * w;
    }
    #pragma unroll
    for (int b = 0; b < BSZ; b++) atomicAdd(&d_zacc[b * HFCC + j], acc[b]);
}

// ---------------- lin2 + log_softmax ----------------
__global__ __launch_bounds__(256) void lin2_kernel(
    const float* __restrict__ lin1b, const float* __restrict__ lin2W,
    const float* __restrict__ lin2b, float* __restrict__ out)
{
    const int b = blockIdx.x;
    const int t = threadIdx.x;
    float s0 = 0.0f, s1 = 0.0f;
    for (int j = t; j < HFCC; j += 256) {
        float z = d_zacc[b * HFCC + j] + lin1b[j];
        z = eluf(z);
        s0 += z * lin2W[j * 2 + 0];
        s1 += z * lin2W[j * 2 + 1];
    }
    __shared__ float r0[256], r1[256];
    r0[t] = s0; r1[t] = s1;
    __syncthreads();
    for (int o = 128; o > 0; o >>= 1) {
        if (t < o) { r0[t] += r0[t + o]; r1[t] += r1[t + o]; }
        __syncthreads();
    }
    if (t == 0) {
        float o0 = r0[0] + lin2b[0];
        float o1 = r1[0] + lin2b[1];
        float mx = fmaxf(o0, o1);
        float lse = mx + logf(expf(o0 - mx) + expf(o1 - mx));
        out[b * CCLS + 0] = o0 - lse;
        out[b * CCLS + 1] = o1 - lse;
    }
}

// ---------------- launcher ----------------
extern "C" void kernel_launch(void* const* d_in, const int* in_sizes, int n_in,
                              void* d_out, int out_size)
{
    const float* x     = (const float*)d_in[0];
    // d_in[1] = batch (all zeros, unused)
    const int*   ei    = (const int*)d_in[2];   // int32 [2, E]
    const float* pe    = (const float*)d_in[3];
    const float* W1    = (const float*)d_in[4];
    const float* b1    = (const float*)d_in[5];
    const float* W2    = (const float*)d_in[6];
    const float* b2    = (const float*)d_in[7];
    const float* W3    = (const float*)d_in[8];
    const float* b3    = (const float*)d_in[9];
    const float* fcW   = (const float*)d_in[10];
    const float* fcb   = (const float*)d_in[11];
    const float* lin1W = (const float*)d_in[12];
    const float* lin1b = (const float*)d_in[13];
    const float* lin2W = (const float*)d_in[14];
    const float* lin2b = (const float*)d_in[15];
    float* out = (float*)d_out;

    float *hwp, *h1p, *h2p, *a1p, *wt1p, *wt2p, *wt3p;
    cudaGetSymbolAddress((void**)&hwp,  d_hw);
    cudaGetSymbolAddress((void**)&h1p,  d_h1);
    cudaGetSymbolAddress((void**)&h2p,  d_h2);
    cudaGetSymbolAddress((void**)&a1p,  d_a1);
    cudaGetSymbolAddress((void**)&wt1p, d_wt1);
    cudaGetSymbolAddress((void**)&wt2p, d_wt2);
    cudaGetSymbolAddress((void**)&wt3p, d_wt3);

    cudaFuncSetAttribute(gemm_mma_kernel<K1PAD>,
                         cudaFuncAttributeMaxDynamicSharedMemorySize, GSM_BYTES);
    cudaFuncSetAttribute(gemm_mma_kernel<HH>,
                         cudaFuncAttributeMaxDynamicSharedMemorySize, GSM_BYTES);

    // degrees + CSR
    zero_deg_kernel<<<(NN + 255) / 256, 256>>>();
    count_deg_kernel<<<(EE + 255) / 256, 256>>>(ei);
    fin_deg_kernel<<<(NN + 255) / 256, 256>>>();
    scan_kernel<<<1, 1024>>>();
    fill_csr_kernel<<<(EE + 255) / 256, 256>>>(ei);

    // GEMM prep
    {
        long long tot = (long long)MM * K1PAD;
        build_a1_kernel<<<(unsigned)((tot + 255) / 256), 256>>>(x, pe);
        transpose_w_kernel<<<HH, 160>>>(W1, KIN, wt1p, K1PAD);
        transpose_w_kernel<<<HH, 256>>>(W2, HH, wt2p, HH);
        transpose_w_kernel<<<HH, 256>>>(W3, HH, wt3p, HH);
    }

    const dim3 ggrid((MM + 127) / 128, HH / 128);   // (946, 2)
    const dim3 agrid(NN, BSZ / 2);

    // layer 1
    gemm_mma_kernel<K1PAD><<<ggrid, 256, GSM_BYTES>>>(a1p, wt1p, hwp);
    gather_kernel<false><<<agrid, 256>>>(hwp, b1, h1p, nullptr, nullptr);

    // layer 2
    gemm_mma_kernel<HH><<<ggrid, 256, GSM_BYTES>>>(h1p, wt2p, hwp);
    gather_kernel<false><<<agrid, 256>>>(hwp, b2, h2p, nullptr, nullptr);

    // layer 3 (+ fused fc head -> d_g; h3 never materialized)
    gemm_mma_kernel<HH><<<ggrid, 256, GSM_BYTES>>>(h2p, wt3p, hwp);
    gather_kernel<true><<<agrid, 256>>>(hwp, b3, nullptr, fcW, fcb);

    // heads
    zero_zacc_kernel<<<(BSZ * HFCC + 255) / 256, 256>>>();
    lin1_kernel<<<dim3(HFCC / 128, (NN + NCH - 1) / NCH), 128>>>(lin1W);
    lin2_kernel<<<BSZ, 256>>>(lin1b, lin2W, lin2b, out);
}

// round 6
// speedup vs baseline: 3.4352x; 1.1350x over previous
#include <cuda_runtime.h>
#include <cuda_bf16.h>
#include <math.h>
#include <cstdint>

// Problem constants
#define BSZ 8
#define NN  15135
#define FF  64
#define GG  73
#define HH  256
#define HFCC 512
#define CCLS 2
#define EE  242160
#define KIN (FF + GG)        // 137
#define MM  (BSZ * NN)       // 121080
#define K1PAD 192            // layer-1 K padded to multiple of 64

// ---------------- scratch (device globals; no dynamic alloc allowed) -------
__device__ int   d_degi[NN];
__device__ float d_dis[NN];
__device__ float d_deginv[NN];
__device__ int   d_csr_ptr[NN + 1];
__device__ int   d_cursor[NN];
__device__ int   d_csr_src[EE];
__device__ float d_csr_w[EE];
__device__ __align__(16) __nv_bfloat16 d_hw[(size_t)MM * HH];
__device__ __align__(16) __nv_bfloat16 d_h1[(size_t)MM * HH];
__device__ __align__(16) __nv_bfloat16 d_h2[(size_t)MM * HH];
__device__ __align__(16) __nv_bfloat16 d_a1[(size_t)MM * K1PAD];
__device__ __align__(16) __nv_bfloat16 d_wt1[HH * K1PAD];   // W1^T padded
__device__ __align__(16) __nv_bfloat16 d_wt2[HH * HH];      // W2^T
__device__ __align__(16) __nv_bfloat16 d_wt3[HH * HH];      // W3^T
__device__ float d_g[MM];
__device__ float d_zacc[BSZ * HFCC];

__device__ __forceinline__ float eluf(float v) {
    return v > 0.0f ? v : expm1f(v);
}

// ---------------- degree / CSR build ----------------
__global__ void zero_deg_kernel() {
    int i = blockIdx.x * blockDim.x + threadIdx.x;
    if (i < NN) d_degi[i] = 0;
}

__global__ void count_deg_kernel(const int* __restrict__ ei) {
    int e = blockIdx.x * blockDim.x + threadIdx.x;
    if (e < EE) atomicAdd(&d_degi[ei[EE + e]], 1);
}

__global__ void fin_deg_kernel() {
    int i = blockIdx.x * blockDim.x + threadIdx.x;
    if (i < NN) {
        float d = (float)d_degi[i] + 1.0f;
        d_dis[i]    = rsqrtf(d);
        d_deginv[i] = 1.0f / d;
    }
}

// single-block exclusive prefix sum (warp-shuffle based)
__global__ __launch_bounds__(1024) void scan_kernel() {
    __shared__ int wsum[32];
    __shared__ int soff;
    const int t = threadIdx.x;
    const int lane = t & 31, warp = t >> 5;
    if (t == 0) soff = 0;
    __syncthreads();
    for (int base = 0; base < NN; base += 1024) {
        int v = (base + t < NN) ? d_degi[base + t] : 0;
        int incl = v;
        #pragma unroll
        for (int o = 1; o < 32; o <<= 1) {
            int u = __shfl_up_sync(0xffffffffu, incl, o);
            if (lane >= o) incl += u;
        }
        if (lane == 31) wsum[warp] = incl;
        __syncthreads();
        if (warp == 0) {
            int s = wsum[lane];
            #pragma unroll
            for (int o = 1; o < 32; o <<= 1) {
                int u = __shfl_up_sync(0xffffffffu, s, o);
                if (lane >= o) s += u;
            }
            wsum[lane] = s;   // inclusive warp-total scan
        }
        __syncthreads();
        int wbase = (warp > 0) ? wsum[warp - 1] : 0;
        int excl = soff + wbase + incl - v;
        if (base + t < NN) {
            d_csr_ptr[base + t] = excl;
            d_cursor[base + t]  = excl;
        }
        __syncthreads();
        if (t == 0) soff += wsum[31];
        __syncthreads();
    }
    if (t == 0) d_csr_ptr[NN] = soff;
}

__global__ void fill_csr_kernel(const int* __restrict__ ei) {
    int e = blockIdx.x * blockDim.x + threadIdx.x;
    if (e < EE) {
        int r = ei[e];
        int c = ei[EE + e];
        int pos = atomicAdd(&d_cursor[c], 1);
        d_csr_src[pos] = r;
        d_csr_w[pos]   = d_dis[r] * d_dis[c];
    }
}

// ---------------- GEMM prep kernels ----------------
__global__ void build_a1_kernel(const float* __restrict__ x,
                                const float* __restrict__ pe) {
    long long i = (long long)blockIdx.x * blockDim.x + threadIdx.x;
    if (i >= (long long)MM * K1PAD) return;
    int m = (int)(i / K1PAD);
    int k = (int)(i % K1PAD);
    float v = 0.0f;
    if (k < FF) v = x[(size_t)m * FF + k];
    else if (k < KIN) v = pe[(size_t)(m % NN) * GG + (k - FF)];
    d_a1[i] = __float2bfloat16_rn(v);
}

// Wt[n][k] = k<Kin ? W[k][n] : 0 ; grid = HH blocks
__global__ void transpose_w_kernel(const float* __restrict__ W, int Kin,
                                   __nv_bfloat16* __restrict__ Wt, int KPAD) {
    int n = blockIdx.x;
    for (int k = threadIdx.x; k < KPAD; k += blockDim.x)
        Wt[(size_t)n * KPAD + k] =
            __float2bfloat16_rn((k < Kin) ? W[(size_t)k * HH + n] : 0.0f);
}

// ================= mma.sync bf16 GEMM (sm_80 baseline PTX) ==================
__device__ __forceinline__ void cp_async16(uint32_t dst, const void* src, int sz) {
    asm volatile("cp.async.cg.shared.global [%0], [%1], 16, %2;"
                 :: "r"(dst), "l"(src), "r"(sz) : "memory");
}

__device__ __forceinline__ void mma_bf16(float* c, const uint32_t* a, const uint32_t* b) {
    asm volatile(
        "mma.sync.aligned.m16n8k16.row.col.f32.bf16.bf16.f32 "
        "{%0,%1,%2,%3}, {%4,%5,%6,%7}, {%8,%9}, {%0,%1,%2,%3};"
        : "+f"(c[0]), "+f"(c[1]), "+f"(c[2]), "+f"(c[3])
        : "r"(a[0]), "r"(a[1]), "r"(a[2]), "r"(a[3]), "r"(b[0]), "r"(b[1]));
}

// hw[M,256] = A[M,KPAD] @ Wt[256,KPAD]^T, bf16 in / f32 acc / bf16 out.
// CTA 128x128, 8 warps (2m x 4n), warp 64x32. K chunks of 64, double buffer.
#define GSTRU 36                              // smem row stride in u32 (72 bf16)
#define GBUFU (2 * 128 * GSTRU)               // u32 per buffer (A + B rows)
#define GSM_BYTES (2 * GBUFU * 4)             // 73728

template <int KPAD>
__global__ __launch_bounds__(256, 2) void gemm_mma_kernel(
    const __nv_bfloat16* __restrict__ A, const __nv_bfloat16* __restrict__ Wt,
    __nv_bfloat16* __restrict__ hw)
{
    extern __shared__ uint32_t sm[];
    constexpr int NC = KPAD / 64;
    const int t    = threadIdx.x;
    const int lane = t & 31;
    const int wid  = t >> 5;
    const int wm   = wid >> 2;          // 0..1 -> m offset 64*wm
    const int wn   = wid & 3;           // 0..3 -> n offset 32*wn
    const int m0   = blockIdx.x * 128;
    const int n0   = blockIdx.y * 128;
    const int g    = lane >> 2;         // group id 0..7
    const int q    = lane & 3;          // thread in group

    float acc[4][4][4];
    #pragma unroll
    for (int mi = 0; mi < 4; mi++)
        #pragma unroll
        for (int nj = 0; nj < 4; nj++)
            #pragma unroll
            for (int r = 0; r < 4; r++) acc[mi][nj][r] = 0.0f;

    auto load_chunk = [&](int ci, int buf) {
        uint32_t* dA = sm + buf * GBUFU;
        uint32_t* dB = dA + 128 * GSTRU;
        const int k0 = ci * 64;          // bf16 offset
        #pragma unroll
        for (int r = 0; r < 4; r++) {
            int idx = t + r * 256;
            int row = idx >> 3;          // 0..127
            int seg = idx & 7;           // 16B segment within 128B row
            int m   = m0 + row;
            int valid = (m < MM);
            const __nv_bfloat16* srcA = A + (size_t)(valid ? m : 0) * KPAD + k0 + seg * 8;
            cp_async16((uint32_t)__cvta_generic_to_shared(dA + row * GSTRU + seg * 4),
                       srcA, valid ? 16 : 0);
            const __nv_bfloat16* srcB = Wt + (size_t)(n0 + row) * KPAD + k0 + seg * 8;
            cp_async16((uint32_t)__cvta_generic_to_shared(dB + row * GSTRU + seg * 4),
                       srcB, 16);
        }
        asm volatile("cp.async.commit_group;" ::: "memory");
    };

    load_chunk(0, 0);
    if (NC > 1) load_chunk(1, 1);
    else        asm volatile("cp.async.commit_group;" ::: "memory");

    #pragma unroll 1
    for (int i = 0; i < NC; i++) {
        asm volatile("cp.async.wait_group 1;" ::: "memory");
        __syncthreads();
        const uint32_t* As = sm + (i & 1) * GBUFU;
        const uint32_t* Bs = As + 128 * GSTRU;

        #pragma unroll
        for (int ks = 0; ks < 4; ks++) {       // 4 k16 steps per 64-chunk
            const int cb = ks * 8 + q;          // u32 col of a0/b0
            uint32_t a[4][4], b[4][2];
            #pragma unroll
            for (int mi = 0; mi < 4; mi++) {
                int r = wm * 64 + mi * 16 + g;
                a[mi][0] = As[r * GSTRU + cb];
                a[mi][1] = As[(r + 8) * GSTRU + cb];
                a[mi][2] = As[r * GSTRU + cb + 4];
                a[mi][3] = As[(r + 8) * GSTRU + cb + 4];
            }
            #pragma unroll
            for (int nj = 0; nj < 4; nj++) {
                int n = wn * 32 + nj * 8 + g;
                b[nj][0] = Bs[n * GSTRU + cb];
                b[nj][1] = Bs[n * GSTRU + cb + 4];
            }
            #pragma unroll
            for (int mi = 0; mi < 4; mi++)
                #pragma unroll
                for (int nj = 0; nj < 4; nj++)
                    mma_bf16(acc[mi][nj], a[mi], b[nj]);
        }
        __syncthreads();
        if (i + 2 < NC) load_chunk(i + 2, i & 1);
        else            asm volatile("cp.async.commit_group;" ::: "memory");
    }

    // epilogue: bf16x2 stores
    __nv_bfloat162* hw2 = reinterpret_cast<__nv_bfloat162*>(hw);
    #pragma unroll
    for (int mi = 0; mi < 4; mi++) {
        int r = m0 + wm * 64 + mi * 16 + g;
        #pragma unroll
        for (int nj = 0; nj < 4; nj++) {
            int c2 = (n0 + wn * 32 + nj * 8 + q * 2) >> 1;   // bf162 index
            if (r < MM)
                hw2[(size_t)r * 128 + c2] =
                    __floats2bfloat162_rn(acc[mi][nj][0], acc[mi][nj][1]);
            if (r + 8 < MM)
                hw2[(size_t)(r + 8) * 128 + c2] =
                    __floats2bfloat162_rn(acc[mi][nj][2], acc[mi][nj][3]);
        }
    }
}

// ---------------- CSR gather: agg + self-loop + bias + ELU ------------------
// grid: (NN, 4); block 256 = 2 batches x 128 bf162 feature-pairs.
template <bool FUSE_FC>
__global__ __launch_bounds__(256) void gather_kernel(
    const __nv_bfloat162* __restrict__ hw, const float* __restrict__ bias,
    __nv_bfloat162* __restrict__ hout,
    const float* __restrict__ fcW, const float* __restrict__ fcb)
{
    __shared__ int   ssrc[256];
    __shared__ float swt[256];
    __shared__ float red[8];
    const int n  = blockIdx.x;
    const int t  = threadIdx.x;
    const int bl = t >> 7;               // 0/1
    const int fp = t & 127;              // feature pair
    const int b  = blockIdx.y * 2 + bl;
    const __nv_bfloat162* hb = hw + (size_t)b * NN * 128;

    const int p0 = d_csr_ptr[n];
    const int p1 = d_csr_ptr[n + 1];

    float ax = 0.0f, ay = 0.0f;
    for (int base = p0; base < p1; base += 256) {
        int idx = base + t;
        if (idx < p1) {
            ssrc[t] = d_csr_src[idx];
            swt[t]  = d_csr_w[idx];
        }
        __syncthreads();
        int cnt = min(256, p1 - base);
        #pragma unroll 4
        for (int i = 0; i < cnt; i++) {
            __nv_bfloat162 m = hb[(size_t)ssrc[i] * 128 + fp];
            float w = swt[i];
            ax += w * __bfloat162float(m.x);
            ay += w * __bfloat162float(m.y);
        }
        __syncthreads();
    }
    const float di = d_deginv[n];
    const float2 bs = reinterpret_cast<const float2*>(bias)[fp];
    __nv_bfloat162 sm2 = hb[(size_t)n * 128 + fp];
    float vx = eluf(ax + __bfloat162float(sm2.x) * di + bs.x);
    float vy = eluf(ay + __bfloat162float(sm2.y) * di + bs.y);

    size_t mb = ((size_t)b * NN + n) * 128 + fp;
    if (!FUSE_FC) {
        hout[mb] = __floats2bfloat162_rn(vx, vy);
    } else {
        // fc weight index: feat f, layer l -> fcW[3f + l]; f = 2fp, 2fp+1
        const float* fw = fcW + 6 * fp;
        __nv_bfloat162 h1v = reinterpret_cast<const __nv_bfloat162*>(d_h1)[mb];
        __nv_bfloat162 h2v = reinterpret_cast<const __nv_bfloat162*>(d_h2)[mb];
        float s = __bfloat162float(h1v.x) * fw[0] + __bfloat162float(h2v.x) * fw[1]
                + vx * fw[2]
                + __bfloat162float(h1v.y) * fw[3] + __bfloat162float(h2v.y) * fw[4]
                + vy * fw[5];
        int lane = t & 31, warp = t >> 5;
        #pragma unroll
        for (int o = 16; o > 0; o >>= 1) s += __shfl_down_sync(0xffffffffu, s, o);
        if (lane == 0) red[warp] = s;
        __syncthreads();
        if ((t & 127) == 0) {
            int w0 = bl * 4;
            float gsum = red[w0] + red[w0 + 1] + red[w0 + 2] + red[w0 + 3];
            d_g[(size_t)b * NN + n] = gsum + fcb[0];
        }
    }
}

// ---------------- lin1: g[b,N] @ lin1_W[N,512] (accumulate) ----------------
__global__ void zero_zacc_kernel() {
    int i = blockIdx.x * blockDim.x + threadIdx.x;
    if (i < BSZ * HFCC) d_zacc[i] = 0.0f;
}

#define NCH 256
__global__ __launch_bounds__(128) void lin1_kernel(const float* __restrict__ W)
{
    __shared__ float gs[BSZ][NCH];
    const int j  = blockIdx.x * 128 + threadIdx.x;
    const int n0 = blockIdx.y * NCH;
    const int cn = min(NCH, NN - n0);
    for (int idx = threadIdx.x; idx < BSZ * NCH; idx += 128) {
        int b  = idx >> 8;       // NCH == 256
        int nl = idx & (NCH - 1);
        gs[b][nl] = (nl < cn) ? d_g[(size_t)b * NN + n0 + nl] : 0.0f;
    }
    __syncthreads();
    float acc[BSZ];
    #pragma unroll
    for (int b = 0; b < BSZ; b++) acc[b] = 0.0f;
    for (int nl = 0; nl < cn; nl++) {
        float w = W[(size_t)(n0 + nl) * HFCC + j];
        #pragma unroll
        for (int b = 0; b < BSZ; b++) acc[b] += gs[b][nl] * w;
    }
    #pragma unroll
    for (int b = 0; b < BSZ; b++) atomicAdd(&d_zacc[b * HFCC + j], acc[b]);
}

// ---------------- lin2 + log_softmax ----------------
__global__ __launch_bounds__(256) void lin2_kernel(
    const float* __restrict__ lin1b, const float* __restrict__ lin2W,
    const float* __restrict__ lin2b, float* __restrict__ out)
{
    const int b = blockIdx.x;
    const int t = threadIdx.x;
    float s0 = 0.0f, s1 = 0.0f;
    for (int j = t; j < HFCC; j += 256) {
        float z = d_zacc[b * HFCC + j] + lin1b[j];
        z = eluf(z);
        s0 += z * lin2W[j * 2 + 0];
        s1 += z * lin2W[j * 2 + 1];
    }
    __shared__ float r0[256], r1[256];
    r0[t] = s0; r1[t] = s1;
    __syncthreads();
    for (int o = 128; o > 0; o >>= 1) {
        if (t < o) { r0[t] += r0[t + o]; r1[t] += r1[t + o]; }
        __syncthreads();
    }
    if (t == 0) {
        float o0 = r0[0] + lin2b[0];
        float o1 = r1[0] + lin2b[1];
        float mx = fmaxf(o0, o1);
        float lse = mx + logf(expf(o0 - mx) + expf(o1 - mx));
        out[b * CCLS + 0] = o0 - lse;
        out[b * CCLS + 1] = o1 - lse;
    }
}

// ---------------- launcher ----------------
extern "C" void kernel_launch(void* const* d_in, const int* in_sizes, int n_in,
                              void* d_out, int out_size)
{
    const float* x     = (const float*)d_in[0];
    // d_in[1] = batch (all zeros, unused)
    const int*   ei    = (const int*)d_in[2];   // int32 [2, E]
    const float* pe    = (const float*)d_in[3];
    const float* W1    = (const float*)d_in[4];
    const float* b1    = (const float*)d_in[5];
    const float* W2    = (const float*)d_in[6];
    const float* b2    = (const float*)d_in[7];
    const float* W3    = (const float*)d_in[8];
    const float* b3    = (const float*)d_in[9];
    const float* fcW   = (const float*)d_in[10];
    const float* fcb   = (const float*)d_in[11];
    const float* lin1W = (const float*)d_in[12];
    const float* lin1b = (const float*)d_in[13];
    const float* lin2W = (const float*)d_in[14];
    const float* lin2b = (const float*)d_in[15];
    float* out = (float*)d_out;

    __nv_bfloat16 *hwp, *h1p, *h2p, *a1p, *wt1p, *wt2p, *wt3p;
    cudaGetSymbolAddress((void**)&hwp,  d_hw);
    cudaGetSymbolAddress((void**)&h1p,  d_h1);
    cudaGetSymbolAddress((void**)&h2p,  d_h2);
    cudaGetSymbolAddress((void**)&a1p,  d_a1);
    cudaGetSymbolAddress((void**)&wt1p, d_wt1);
    cudaGetSymbolAddress((void**)&wt2p, d_wt2);
    cudaGetSymbolAddress((void**)&wt3p, d_wt3);

    cudaFuncSetAttribute(gemm_mma_kernel<K1PAD>,
                         cudaFuncAttributeMaxDynamicSharedMemorySize, GSM_BYTES);
    cudaFuncSetAttribute(gemm_mma_kernel<HH>,
                         cudaFuncAttributeMaxDynamicSharedMemorySize, GSM_BYTES);

    // degrees + CSR
    zero_deg_kernel<<<(NN + 255) / 256, 256>>>();
    count_deg_kernel<<<(EE + 255) / 256, 256>>>(ei);
    fin_deg_kernel<<<(NN + 255) / 256, 256>>>();
    scan_kernel<<<1, 1024>>>();
    fill_csr_kernel<<<(EE + 255) / 256, 256>>>(ei);

    // GEMM prep
    {
        long long tot = (long long)MM * K1PAD;
        build_a1_kernel<<<(unsigned)((tot + 255) / 256), 256>>>(x, pe);
        transpose_w_kernel<<<HH, 192>>>(W1, KIN, wt1p, K1PAD);
        transpose_w_kernel<<<HH, 256>>>(W2, HH, wt2p, HH);
        transpose_w_kernel<<<HH, 256>>>(W3, HH, wt3p, HH);
    }

    const dim3 ggrid((MM + 127) / 128, HH / 128);   // (946, 2)
    const dim3 agrid(NN, 4);
    __nv_bfloat162* hw2 = reinterpret_cast<__nv_bfloat162*>(hwp);
    __nv_bfloat162* h12 = reinterpret_cast<__nv_bfloat162*>(h1p);
    __nv_bfloat162* h22 = reinterpret_cast<__nv_bfloat162*>(h2p);

    // layer 1
    gemm_mma_kernel<K1PAD><<<ggrid, 256, GSM_BYTES>>>(a1p, wt1p, hwp);
    gather_kernel<false><<<agrid, 256>>>(hw2, b1, h12, nullptr, nullptr);

    // layer 2
    gemm_mma_kernel<HH><<<ggrid, 256, GSM_BYTES>>>(h1p, wt2p, hwp);
    gather_kernel<false><<<agrid, 256>>>(hw2, b2, h22, nullptr, nullptr);

    // layer 3 (+ fused fc head -> d_g; h3 never materialized)
    gemm_mma_kernel<HH><<<ggrid, 256, GSM_BYTES>>>(h2p, wt3p, hwp);
    gather_kernel<true><<<agrid, 256>>>(hw2, b3, nullptr, fcW, fcb);

    // heads
    zero_zacc_kernel<<<(BSZ * HFCC + 255) / 256, 256>>>();
    lin1_kernel<<<dim3(HFCC / 128, (NN + NCH - 1) / NCH), 128>>>(lin1W);
    lin2_kernel<<<BSZ, 256>>>(lin1b, lin2W, lin2b, out);
}

// round 7
// speedup vs baseline: 4.6763x; 1.3613x over previous
#include <cuda_runtime.h>
#include <cuda_bf16.h>
#include <math.h>
#include <cstdint>

// Problem constants
#define BSZ 8
#define NN  15135
#define FF  64
#define GG  73
#define HH  256
#define HFCC 512
#define CCLS 2
#define EE  242160
#define KIN (FF + GG)        // 137
#define MM  (BSZ * NN)       // 121080
#define K1PAD 192            // layer-1 K padded to multiple of 64

// ---------------- scratch (device globals; no dynamic alloc allowed) -------
__device__ int   d_degi[NN];
__device__ float d_dis[NN];
__device__ float d_deginv[NN];
__device__ int   d_csr_ptr[NN + 1];
__device__ int   d_cursor[NN];
__device__ int   d_csr_src[EE];
__device__ float d_csr_w[EE];
__device__ __align__(16) __nv_bfloat16 d_hw[(size_t)MM * HH];
__device__ __align__(16) __nv_bfloat16 d_h1[(size_t)MM * HH];
__device__ __align__(16) __nv_bfloat16 d_h2[(size_t)MM * HH];
__device__ __align__(16) __nv_bfloat16 d_a1[(size_t)MM * K1PAD];
__device__ __align__(16) __nv_bfloat16 d_wt1[HH * K1PAD];   // W1^T padded
__device__ __align__(16) __nv_bfloat16 d_wt2[HH * HH];      // W2^T
__device__ __align__(16) __nv_bfloat16 d_wt3[HH * HH];      // W3^T
__device__ float d_g[MM];
__device__ float d_zacc[BSZ * HFCC];

__device__ __forceinline__ float eluf(float v) {
    return v > 0.0f ? v : expm1f(v);
}

__device__ __forceinline__ float2 bf2f(uint32_t u) {
    __nv_bfloat162 m = *reinterpret_cast<__nv_bfloat162*>(&u);
    return make_float2(__bfloat162float(m.x), __bfloat162float(m.y));
}

// ---------------- degree / CSR build ----------------
__global__ void count_deg_kernel(const int* __restrict__ ei) {
    int e = blockIdx.x * blockDim.x + threadIdx.x;
    if (e < EE) atomicAdd(&d_degi[ei[EE + e]], 1);
}

// single-block exclusive prefix sum (warp shuffle) + dis/deginv
__global__ __launch_bounds__(1024) void scanfin_kernel() {
    __shared__ int wsum[32];
    __shared__ int soff;
    const int t = threadIdx.x;
    const int lane = t & 31, warp = t >> 5;
    if (t == 0) soff = 0;
    __syncthreads();
    for (int base = 0; base < NN; base += 1024) {
        int v = 0;
        if (base + t < NN) {
            v = d_degi[base + t];
            float d = (float)v + 1.0f;
            d_dis[base + t]    = rsqrtf(d);
            d_deginv[base + t] = 1.0f / d;
        }
        int incl = v;
        #pragma unroll
        for (int o = 1; o < 32; o <<= 1) {
            int u = __shfl_up_sync(0xffffffffu, incl, o);
            if (lane >= o) incl += u;
        }
        if (lane == 31) wsum[warp] = incl;
        __syncthreads();
        if (warp == 0) {
            int s = wsum[lane];
            #pragma unroll
            for (int o = 1; o < 32; o <<= 1) {
                int u = __shfl_up_sync(0xffffffffu, s, o);
                if (lane >= o) s += u;
            }
            wsum[lane] = s;
        }
        __syncthreads();
        int wbase = (warp > 0) ? wsum[warp - 1] : 0;
        int excl = soff + wbase + incl - v;
        if (base + t < NN) {
            d_csr_ptr[base + t] = excl;
            d_cursor[base + t]  = excl;
        }
        __syncthreads();
        if (t == 0) soff += wsum[31];
        __syncthreads();
    }
    if (t == 0) d_csr_ptr[NN] = soff;
}

__global__ void fill_csr_kernel(const int* __restrict__ ei) {
    int e = blockIdx.x * blockDim.x + threadIdx.x;
    if (e < EE) {
        int r = ei[e];
        int c = ei[EE + e];
        int pos = atomicAdd(&d_cursor[c], 1);
        d_csr_src[pos] = r;
        d_csr_w[pos]   = d_dis[r] * d_dis[c];
    }
}

// ---------------- GEMM prep kernels ----------------
// pairwise: thread -> one bf162 of a1
__global__ void build_a1_kernel(const float* __restrict__ x,
                                const float* __restrict__ pe) {
    long long i = (long long)blockIdx.x * blockDim.x + threadIdx.x;
    if (i >= (long long)MM * (K1PAD / 2)) return;
    int m  = (int)(i / (K1PAD / 2));
    int k  = (int)(i % (K1PAD / 2)) * 2;
    int nn = m % NN;
    float v0 = 0.0f, v1 = 0.0f;
    if (k < FF)           v0 = x[(size_t)m * FF + k];
    else if (k < KIN)     v0 = pe[(size_t)nn * GG + (k - FF)];
    if (k + 1 < FF)       v1 = x[(size_t)m * FF + k + 1];
    else if (k + 1 < KIN) v1 = pe[(size_t)nn * GG + (k + 1 - FF)];
    reinterpret_cast<__nv_bfloat162*>(d_a1)[i] = __floats2bfloat162_rn(v0, v1);
}

// Wt[n][k] = k<Kin ? W[k][n] : 0 ; grid = HH blocks
__global__ void transpose_w_kernel(const float* __restrict__ W, int Kin,
                                   __nv_bfloat16* __restrict__ Wt, int KPAD) {
    int n = blockIdx.x;
    for (int k = threadIdx.x; k < KPAD; k += blockDim.x)
        Wt[(size_t)n * KPAD + k] =
            __float2bfloat16_rn((k < Kin) ? W[(size_t)k * HH + n] : 0.0f);
}

// ================= mma.sync bf16 GEMM (sm_80 baseline PTX) ==================
__device__ __forceinline__ void cp_async16(uint32_t dst, const void* src, int sz) {
    asm volatile("cp.async.cg.shared.global [%0], [%1], 16, %2;"
                 :: "r"(dst), "l"(src), "r"(sz) : "memory");
}

__device__ __forceinline__ void mma_bf16(float* c, const uint32_t* a, const uint32_t* b) {
    asm volatile(
        "mma.sync.aligned.m16n8k16.row.col.f32.bf16.bf16.f32 "
        "{%0,%1,%2,%3}, {%4,%5,%6,%7}, {%8,%9}, {%0,%1,%2,%3};"
        : "+f"(c[0]), "+f"(c[1]), "+f"(c[2]), "+f"(c[3])
        : "r"(a[0]), "r"(a[1]), "r"(a[2]), "r"(a[3]), "r"(b[0]), "r"(b[1]));
}

#define GSTRU 36                              // smem row stride in u32 (72 bf16)
#define GBUFU (2 * 128 * GSTRU)               // u32 per buffer (A + B rows)
#define GSM_BYTES (2 * GBUFU * 4)             // 73728

template <int KPAD>
__global__ __launch_bounds__(256, 2) void gemm_mma_kernel(
    const __nv_bfloat16* __restrict__ A, const __nv_bfloat16* __restrict__ Wt,
    __nv_bfloat16* __restrict__ hw)
{
    extern __shared__ uint32_t sm[];
    constexpr int NC = KPAD / 64;
    const int t    = threadIdx.x;
    const int lane = t & 31;
    const int wid  = t >> 5;
    const int wm   = wid >> 2;
    const int wn   = wid & 3;
    const int m0   = blockIdx.x * 128;
    const int n0   = blockIdx.y * 128;
    const int g    = lane >> 2;
    const int q    = lane & 3;

    float acc[4][4][4];
    #pragma unroll
    for (int mi = 0; mi < 4; mi++)
        #pragma unroll
        for (int nj = 0; nj < 4; nj++)
            #pragma unroll
            for (int r = 0; r < 4; r++) acc[mi][nj][r] = 0.0f;

    auto load_chunk = [&](int ci, int buf) {
        uint32_t* dA = sm + buf * GBUFU;
        uint32_t* dB = dA + 128 * GSTRU;
        const int k0 = ci * 64;
        #pragma unroll
        for (int r = 0; r < 4; r++) {
            int idx = t + r * 256;
            int row = idx >> 3;
            int seg = idx & 7;
            int m   = m0 + row;
            int valid = (m < MM);
            const __nv_bfloat16* srcA = A + (size_t)(valid ? m : 0) * KPAD + k0 + seg * 8;
            cp_async16((uint32_t)__cvta_generic_to_shared(dA + row * GSTRU + seg * 4),
                       srcA, valid ? 16 : 0);
            const __nv_bfloat16* srcB = Wt + (size_t)(n0 + row) * KPAD + k0 + seg * 8;
            cp_async16((uint32_t)__cvta_generic_to_shared(dB + row * GSTRU + seg * 4),
                       srcB, 16);
        }
        asm volatile("cp.async.commit_group;" ::: "memory");
    };

    load_chunk(0, 0);
    if (NC > 1) load_chunk(1, 1);
    else        asm volatile("cp.async.commit_group;" ::: "memory");

    #pragma unroll 1
    for (int i = 0; i < NC; i++) {
        asm volatile("cp.async.wait_group 1;" ::: "memory");
        __syncthreads();
        const uint32_t* As = sm + (i & 1) * GBUFU;
        const uint32_t* Bs = As + 128 * GSTRU;

        #pragma unroll
        for (int ks = 0; ks < 4; ks++) {
            const int cb = ks * 8 + q;
            uint32_t a[4][4], b[4][2];
            #pragma unroll
            for (int mi = 0; mi < 4; mi++) {
                int r = wm * 64 + mi * 16 + g;
                a[mi][0] = As[r * GSTRU + cb];
                a[mi][1] = As[(r + 8) * GSTRU + cb];
                a[mi][2] = As[r * GSTRU + cb + 4];
                a[mi][3] = As[(r + 8) * GSTRU + cb + 4];
            }
            #pragma unroll
            for (int nj = 0; nj < 4; nj++) {
                int n = wn * 32 + nj * 8 + g;
                b[nj][0] = Bs[n * GSTRU + cb];
                b[nj][1] = Bs[n * GSTRU + cb + 4];
            }
            #pragma unroll
            for (int mi = 0; mi < 4; mi++)
                #pragma unroll
                for (int nj = 0; nj < 4; nj++)
                    mma_bf16(acc[mi][nj], a[mi], b[nj]);
        }
        __syncthreads();
        if (i + 2 < NC) load_chunk(i + 2, i & 1);
        else            asm volatile("cp.async.commit_group;" ::: "memory");
    }

    __nv_bfloat162* hw2 = reinterpret_cast<__nv_bfloat162*>(hw);
    #pragma unroll
    for (int mi = 0; mi < 4; mi++) {
        int r = m0 + wm * 64 + mi * 16 + g;
        #pragma unroll
        for (int nj = 0; nj < 4; nj++) {
            int c2 = (n0 + wn * 32 + nj * 8 + q * 2) >> 1;
            if (r < MM)
                hw2[(size_t)r * 128 + c2] =
                    __floats2bfloat162_rn(acc[mi][nj][0], acc[mi][nj][1]);
            if (r + 8 < MM)
                hw2[(size_t)(r + 8) * 128 + c2] =
                    __floats2bfloat162_rn(acc[mi][nj][2], acc[mi][nj][3]);
        }
    }
}

// ---------------- CSR gather: 1 block per node, 128 thr, 8 batches ---------
template <bool FUSE_FC>
__global__ __launch_bounds__(128) void gather_kernel(
    const uint32_t* __restrict__ hw, const float* __restrict__ bias,
    uint32_t* __restrict__ hout,
    const float* __restrict__ fcW, const float* __restrict__ fcb)
{
    const int n  = blockIdx.x;
    const int fp = threadIdx.x;          // feature pair 0..127

    const int p0 = d_csr_ptr[n];
    const int p1 = d_csr_ptr[n + 1];

    float ax[BSZ], ay[BSZ];
    #pragma unroll
    for (int b = 0; b < BSZ; b++) { ax[b] = 0.0f; ay[b] = 0.0f; }

    #pragma unroll 2
    for (int e = p0; e < p1; e++) {
        int   src = __ldg(&d_csr_src[e]);   // uniform -> broadcast
        float w   = __ldg(&d_csr_w[e]);
        size_t ro = (size_t)src * 128 + fp;
        uint32_t u[BSZ];
        #pragma unroll
        for (int b = 0; b < BSZ; b++) u[b] = __ldg(hw + (size_t)b * NN * 128 + ro);
        #pragma unroll
        for (int b = 0; b < BSZ; b++) {
            float2 m = bf2f(u[b]);
            ax[b] += w * m.x;
            ay[b] += w * m.y;
        }
    }

    const float di = d_deginv[n];
    const float2 bs = reinterpret_cast<const float2*>(bias)[fp];
    size_t so = (size_t)n * 128 + fp;

    if (!FUSE_FC) {
        #pragma unroll
        for (int b = 0; b < BSZ; b++) {
            float2 sm2 = bf2f(__ldg(hw + (size_t)b * NN * 128 + so));
            float vx = eluf(ax[b] + sm2.x * di + bs.x);
            float vy = eluf(ay[b] + sm2.y * di + bs.y);
            __nv_bfloat162 o = __floats2bfloat162_rn(vx, vy);
            hout[(size_t)b * NN * 128 + so] = *reinterpret_cast<uint32_t*>(&o);
        }
    } else {
        const float fw0 = fcW[6 * fp + 0], fw1 = fcW[6 * fp + 1], fw2 = fcW[6 * fp + 2];
        const float fw3 = fcW[6 * fp + 3], fw4 = fcW[6 * fp + 4], fw5 = fcW[6 * fp + 5];
        const uint32_t* h1u = reinterpret_cast<const uint32_t*>(d_h1);
        const uint32_t* h2u = reinterpret_cast<const uint32_t*>(d_h2);
        __shared__ float red[4][BSZ];
        float s[BSZ];
        #pragma unroll
        for (int b = 0; b < BSZ; b++) {
            size_t mb = (size_t)b * NN * 128 + so;
            float2 sm2 = bf2f(__ldg(hw + mb));
            float vx = eluf(ax[b] + sm2.x * di + bs.x);
            float vy = eluf(ay[b] + sm2.y * di + bs.y);
            float2 h1v = bf2f(__ldg(h1u + mb));
            float2 h2v = bf2f(__ldg(h2u + mb));
            s[b] = h1v.x * fw0 + h2v.x * fw1 + vx * fw2
                 + h1v.y * fw3 + h2v.y * fw4 + vy * fw5;
        }
        int lane = fp & 31, warp = fp >> 5;
        #pragma unroll
        for (int b = 0; b < BSZ; b++) {
            float v = s[b];
            #pragma unroll
            for (int o = 16; o > 0; o >>= 1) v += __shfl_down_sync(0xffffffffu, v, o);
            if (lane == 0) red[warp][b] = v;
        }
        __syncthreads();
        if (fp < BSZ) {
            float g = red[0][fp] + red[1][fp] + red[2][fp] + red[3][fp];
            d_g[(size_t)fp * NN + n] = g + fcb[0];
        }
    }
}

// ---------------- lin1: g[b,N] @ lin1_W[N,512] (accumulate) ----------------
#define NCH 256
__global__ __launch_bounds__(128) void lin1_kernel(const float* __restrict__ W)
{
    __shared__ float gs[BSZ][NCH];
    const int j  = blockIdx.x * 128 + threadIdx.x;
    const int n0 = blockIdx.y * NCH;
    const int cn = min(NCH, NN - n0);
    for (int idx = threadIdx.x; idx < BSZ * NCH; idx += 128) {
        int b  = idx >> 8;
        int nl = idx & (NCH - 1);
        gs[b][nl] = (nl < cn) ? d_g[(size_t)b * NN + n0 + nl] : 0.0f;
    }
    __syncthreads();
    float acc[BSZ];
    #pragma unroll
    for (int b = 0; b < BSZ; b++) acc[b] = 0.0f;
    for (int nl = 0; nl < cn; nl++) {
        float w = W[(size_t)(n0 + nl) * HFCC + j];
        #pragma unroll
        for (int b = 0; b < BSZ; b++) acc[b] += gs[b][nl] * w;
    }
    #pragma unroll
    for (int b = 0; b < BSZ; b++) atomicAdd(&d_zacc[b * HFCC + j], acc[b]);
}

// ---------------- lin2 + log_softmax ----------------
__global__ __launch_bounds__(256) void lin2_kernel(
    const float* __restrict__ lin1b, const float* __restrict__ lin2W,
    const float* __restrict__ lin2b, float* __restrict__ out)
{
    const int b = blockIdx.x;
    const int t = threadIdx.x;
    float s0 = 0.0f, s1 = 0.0f;
    for (int j = t; j < HFCC; j += 256) {
        float z = d_zacc[b * HFCC + j] + lin1b[j];
        z = eluf(z);
        s0 += z * lin2W[j * 2 + 0];
        s1 += z * lin2W[j * 2 + 1];
    }
    __shared__ float r0[256], r1[256];
    r0[t] = s0; r1[t] = s1;
    __syncthreads();
    for (int o = 128; o > 0; o >>= 1) {
        if (t < o) { r0[t] += r0[t + o]; r1[t] += r1[t + o]; }
        __syncthreads();
    }
    if (t == 0) {
        float o0 = r0[0] + lin2b[0];
        float o1 = r1[0] + lin2b[1];
        float mx = fmaxf(o0, o1);
        float lse = mx + logf(expf(o0 - mx) + expf(o1 - mx));
        out[b * CCLS + 0] = o0 - lse;
        out[b * CCLS + 1] = o1 - lse;
    }
}

// ---------------- launcher ----------------
extern "C" void kernel_launch(void* const* d_in, const int* in_sizes, int n_in,
                              void* d_out, int out_size)
{
    const float* x     = (const float*)d_in[0];
    const int*   ei    = (const int*)d_in[2];   // int32 [2, E]
    const float* pe    = (const float*)d_in[3];
    const float* W1    = (const float*)d_in[4];
    const float* b1    = (const float*)d_in[5];
    const float* W2    = (const float*)d_in[6];
    const float* b2    = (const float*)d_in[7];
    const float* W3    = (const float*)d_in[8];
    const float* b3    = (const float*)d_in[9];
    const float* fcW   = (const float*)d_in[10];
    const float* fcb   = (const float*)d_in[11];
    const float* lin1W = (const float*)d_in[12];
    const float* lin1b = (const float*)d_in[13];
    const float* lin2W = (const float*)d_in[14];
    const float* lin2b = (const float*)d_in[15];
    float* out = (float*)d_out;

    __nv_bfloat16 *hwp, *h1p, *h2p, *a1p, *wt1p, *wt2p, *wt3p;
    cudaGetSymbolAddress((void**)&hwp,  d_hw);
    cudaGetSymbolAddress((void**)&h1p,  d_h1);
    cudaGetSymbolAddress((void**)&h2p,  d_h2);
    cudaGetSymbolAddress((void**)&a1p,  d_a1);
    cudaGetSymbolAddress((void**)&wt1p, d_wt1);
    cudaGetSymbolAddress((void**)&wt2p, d_wt2);
    cudaGetSymbolAddress((void**)&wt3p, d_wt3);
    int* degip; float* zaccp;
    cudaGetSymbolAddress((void**)&degip, d_degi);
    cudaGetSymbolAddress((void**)&zaccp, d_zacc);

    cudaFuncSetAttribute(gemm_mma_kernel<K1PAD>,
                         cudaFuncAttributeMaxDynamicSharedMemorySize, GSM_BYTES);
    cudaFuncSetAttribute(gemm_mma_kernel<HH>,
                         cudaFuncAttributeMaxDynamicSharedMemorySize, GSM_BYTES);

    // degrees + CSR
    cudaMemsetAsync(degip, 0, NN * sizeof(int));
    count_deg_kernel<<<(EE + 255) / 256, 256>>>(ei);
    scanfin_kernel<<<1, 1024>>>();
    fill_csr_kernel<<<(EE + 255) / 256, 256>>>(ei);

    // GEMM prep
    {
        long long tot = (long long)MM * (K1PAD / 2);
        build_a1_kernel<<<(unsigned)((tot + 255) / 256), 256>>>(x, pe);
        transpose_w_kernel<<<HH, 192>>>(W1, KIN, wt1p, K1PAD);
        transpose_w_kernel<<<HH, 256>>>(W2, HH, wt2p, HH);
        transpose_w_kernel<<<HH, 256>>>(W3, HH, wt3p, HH);
    }

    const dim3 ggrid((MM + 127) / 128, HH / 128);   // (946, 2)
    const uint32_t* hwu = reinterpret_cast<const uint32_t*>(hwp);
    uint32_t* h1u = reinterpret_cast<uint32_t*>(h1p);
    uint32_t* h2u = reinterpret_cast<uint32_t*>(h2p);

    // layer 1
    gemm_mma_kernel<K1PAD><<<ggrid, 256, GSM_BYTES>>>(a1p, wt1p, hwp);
    gather_kernel<false><<<NN, 128>>>(hwu, b1, h1u, nullptr, nullptr);

    // layer 2
    gemm_mma_kernel<HH><<<ggrid, 256, GSM_BYTES>>>(h1p, wt2p, hwp);
    gather_kernel<false><<<NN, 128>>>(hwu, b2, h2u, nullptr, nullptr);

    // layer 3 (+ fused fc head -> d_g)
    gemm_mma_kernel<HH><<<ggrid, 256, GSM_BYTES>>>(h2p, wt3p, hwp);
    gather_kernel<true><<<NN, 128>>>(hwu, b3, nullptr, fcW, fcb);

    // heads
    cudaMemsetAsync(zaccp, 0, BSZ * HFCC * sizeof(float));
    lin1_kernel<<<dim3(HFCC / 128, (NN + NCH - 1) / NCH), 128>>>(lin1W);
    lin2_kernel<<<BSZ, 256>>>(lin1b, lin2W, lin2b, out);
}

// round 8
// speedup vs baseline: 5.3817x; 1.1508x over previous
#include <cuda_runtime.h>
#include <cuda_bf16.h>
#include <math.h>
#include <cstdint>

// Problem constants
#define BSZ 8
#define NN  15135
#define FF  64
#define GG  73
#define HH  256
#define HFCC 512
#define CCLS 2
#define EE  242160
#define KIN (FF + GG)        // 137
#define MM  (BSZ * NN)       // 121080
#define K1PAD 192            // layer-1 K padded to multiple of 64

// ---------------- scratch (device globals; no dynamic alloc allowed) -------
__device__ int   d_degi[NN];
__device__ float d_dis[NN];
__device__ float d_deginv[NN];
__device__ int   d_csr_ptr[NN + 1];
__device__ int   d_cursor[NN];
__device__ int   d_csr_src[EE];
__device__ float d_csr_w[EE];
__device__ __align__(16) __nv_bfloat16 d_hw[(size_t)MM * HH];
__device__ __align__(16) __nv_bfloat16 d_h1[(size_t)MM * HH];
__device__ __align__(16) __nv_bfloat16 d_h2[(size_t)MM * HH];
__device__ __align__(16) __nv_bfloat16 d_a1[(size_t)MM * K1PAD];
__device__ __align__(16) __nv_bfloat16 d_wt1[HH * K1PAD];   // W1^T padded
__device__ __align__(16) __nv_bfloat16 d_wt2[HH * HH];      // W2^T
__device__ __align__(16) __nv_bfloat16 d_wt3[HH * HH];      // W3^T
__device__ float d_g[MM];
__device__ float d_zacc[BSZ * HFCC];

__device__ __forceinline__ float eluf(float v) {
    return v > 0.0f ? v : expm1f(v);
}

__device__ __forceinline__ float2 bf2f(uint32_t u) {
    __nv_bfloat162 m = *reinterpret_cast<__nv_bfloat162*>(&u);
    return make_float2(__bfloat162float(m.x), __bfloat162float(m.y));
}

// accumulate 8 bf16 lanes of u into a[0..7] with weight w
__device__ __forceinline__ void acc8(float* a, uint4 u, float w) {
    float2 m;
    m = bf2f(u.x); a[0] += w * m.x; a[1] += w * m.y;
    m = bf2f(u.y); a[2] += w * m.x; a[3] += w * m.y;
    m = bf2f(u.z); a[4] += w * m.x; a[5] += w * m.y;
    m = bf2f(u.w); a[6] += w * m.x; a[7] += w * m.y;
}

// ---------------- degree / CSR build ----------------
__global__ void count_deg_kernel(const int* __restrict__ ei) {
    int e = blockIdx.x * blockDim.x + threadIdx.x;
    if (e < EE) atomicAdd(&d_degi[ei[EE + e]], 1);
}

// single-block exclusive prefix sum (warp shuffle) + dis/deginv
__global__ __launch_bounds__(1024) void scanfin_kernel() {
    __shared__ int wsum[32];
    __shared__ int soff;
    const int t = threadIdx.x;
    const int lane = t & 31, warp = t >> 5;
    if (t == 0) soff = 0;
    __syncthreads();
    for (int base = 0; base < NN; base += 1024) {
        int v = 0;
        if (base + t < NN) {
            v = d_degi[base + t];
            float d = (float)v + 1.0f;
            d_dis[base + t]    = rsqrtf(d);
            d_deginv[base + t] = 1.0f / d;
        }
        int incl = v;
        #pragma unroll
        for (int o = 1; o < 32; o <<= 1) {
            int u = __shfl_up_sync(0xffffffffu, incl, o);
            if (lane >= o) incl += u;
        }
        if (lane == 31) wsum[warp] = incl;
        __syncthreads();
        if (warp == 0) {
            int s = wsum[lane];
            #pragma unroll
            for (int o = 1; o < 32; o <<= 1) {
                int u = __shfl_up_sync(0xffffffffu, s, o);
                if (lane >= o) s += u;
            }
            wsum[lane] = s;
        }
        __syncthreads();
        int wbase = (warp > 0) ? wsum[warp - 1] : 0;
        int excl = soff + wbase + incl - v;
        if (base + t < NN) {
            d_csr_ptr[base + t] = excl;
            d_cursor[base + t]  = excl;
        }
        __syncthreads();
        if (t == 0) soff += wsum[31];
        __syncthreads();
    }
    if (t == 0) d_csr_ptr[NN] = soff;
}

__global__ void fill_csr_kernel(const int* __restrict__ ei) {
    int e = blockIdx.x * blockDim.x + threadIdx.x;
    if (e < EE) {
        int r = ei[e];
        int c = ei[EE + e];
        int pos = atomicAdd(&d_cursor[c], 1);
        d_csr_src[pos] = r;
        d_csr_w[pos]   = d_dis[r] * d_dis[c];
    }
}

// ---------------- GEMM prep kernels ----------------
__global__ void build_a1_kernel(const float* __restrict__ x,
                                const float* __restrict__ pe) {
    long long i = (long long)blockIdx.x * blockDim.x + threadIdx.x;
    if (i >= (long long)MM * (K1PAD / 2)) return;
    int m  = (int)(i / (K1PAD / 2));
    int k  = (int)(i % (K1PAD / 2)) * 2;
    int nn = m % NN;
    float v0 = 0.0f, v1 = 0.0f;
    if (k < FF)           v0 = x[(size_t)m * FF + k];
    else if (k < KIN)     v0 = pe[(size_t)nn * GG + (k - FF)];
    if (k + 1 < FF)       v1 = x[(size_t)m * FF + k + 1];
    else if (k + 1 < KIN) v1 = pe[(size_t)nn * GG + (k + 1 - FF)];
    reinterpret_cast<__nv_bfloat162*>(d_a1)[i] = __floats2bfloat162_rn(v0, v1);
}

__global__ void transpose_w_kernel(const float* __restrict__ W, int Kin,
                                   __nv_bfloat16* __restrict__ Wt, int KPAD) {
    int n = blockIdx.x;
    for (int k = threadIdx.x; k < KPAD; k += blockDim.x)
        Wt[(size_t)n * KPAD + k] =
            __float2bfloat16_rn((k < Kin) ? W[(size_t)k * HH + n] : 0.0f);
}

// ================= mma.sync bf16 GEMM (sm_80 baseline PTX) ==================
__device__ __forceinline__ void cp_async16(uint32_t dst, const void* src, int sz) {
    asm volatile("cp.async.cg.shared.global [%0], [%1], 16, %2;"
                 :: "r"(dst), "l"(src), "r"(sz) : "memory");
}

__device__ __forceinline__ void mma_bf16(float* c, const uint32_t* a, const uint32_t* b) {
    asm volatile(
        "mma.sync.aligned.m16n8k16.row.col.f32.bf16.bf16.f32 "
        "{%0,%1,%2,%3}, {%4,%5,%6,%7}, {%8,%9}, {%0,%1,%2,%3};"
        : "+f"(c[0]), "+f"(c[1]), "+f"(c[2]), "+f"(c[3])
        : "r"(a[0]), "r"(a[1]), "r"(a[2]), "r"(a[3]), "r"(b[0]), "r"(b[1]));
}

#define GSTRU 36
#define GBUFU (2 * 128 * GSTRU)
#define GSM_BYTES (2 * GBUFU * 4)

template <int KPAD>
__global__ __launch_bounds__(256, 2) void gemm_mma_kernel(
    const __nv_bfloat16* __restrict__ A, const __nv_bfloat16* __restrict__ Wt,
    __nv_bfloat16* __restrict__ hw)
{
    extern __shared__ uint32_t sm[];
    constexpr int NC = KPAD / 64;
    const int t    = threadIdx.x;
    const int lane = t & 31;
    const int wid  = t >> 5;
    const int wm   = wid >> 2;
    const int wn   = wid & 3;
    const int m0   = blockIdx.x * 128;
    const int n0   = blockIdx.y * 128;
    const int g    = lane >> 2;
    const int q    = lane & 3;

    float acc[4][4][4];
    #pragma unroll
    for (int mi = 0; mi < 4; mi++)
        #pragma unroll
        for (int nj = 0; nj < 4; nj++)
            #pragma unroll
            for (int r = 0; r < 4; r++) acc[mi][nj][r] = 0.0f;

    auto load_chunk = [&](int ci, int buf) {
        uint32_t* dA = sm + buf * GBUFU;
        uint32_t* dB = dA + 128 * GSTRU;
        const int k0 = ci * 64;
        #pragma unroll
        for (int r = 0; r < 4; r++) {
            int idx = t + r * 256;
            int row = idx >> 3;
            int seg = idx & 7;
            int m   = m0 + row;
            int valid = (m < MM);
            const __nv_bfloat16* srcA = A + (size_t)(valid ? m : 0) * KPAD + k0 + seg * 8;
            cp_async16((uint32_t)__cvta_generic_to_shared(dA + row * GSTRU + seg * 4),
                       srcA, valid ? 16 : 0);
            const __nv_bfloat16* srcB = Wt + (size_t)(n0 + row) * KPAD + k0 + seg * 8;
            cp_async16((uint32_t)__cvta_generic_to_shared(dB + row * GSTRU + seg * 4),
                       srcB, 16);
        }
        asm volatile("cp.async.commit_group;" ::: "memory");
    };

    load_chunk(0, 0);
    if (NC > 1) load_chunk(1, 1);
    else        asm volatile("cp.async.commit_group;" ::: "memory");

    #pragma unroll 1
    for (int i = 0; i < NC; i++) {
        asm volatile("cp.async.wait_group 1;" ::: "memory");
        __syncthreads();
        const uint32_t* As = sm + (i & 1) * GBUFU;
        const uint32_t* Bs = As + 128 * GSTRU;

        #pragma unroll
        for (int ks = 0; ks < 4; ks++) {
            const int cb = ks * 8 + q;
            uint32_t a[4][4], b[4][2];
            #pragma unroll
            for (int mi = 0; mi < 4; mi++) {
                int r = wm * 64 + mi * 16 + g;
                a[mi][0] = As[r * GSTRU + cb];
                a[mi][1] = As[(r + 8) * GSTRU + cb];
                a[mi][2] = As[r * GSTRU + cb + 4];
                a[mi][3] = As[(r + 8) * GSTRU + cb + 4];
            }
            #pragma unroll
            for (int nj = 0; nj < 4; nj++) {
                int n = wn * 32 + nj * 8 + g;
                b[nj][0] = Bs[n * GSTRU + cb];
                b[nj][1] = Bs[n * GSTRU + cb + 4];
            }
            #pragma unroll
            for (int mi = 0; mi < 4; mi++)
                #pragma unroll
                for (int nj = 0; nj < 4; nj++)
                    mma_bf16(acc[mi][nj], a[mi], b[nj]);
        }
        __syncthreads();
        if (i + 2 < NC) load_chunk(i + 2, i & 1);
        else            asm volatile("cp.async.commit_group;" ::: "memory");
    }

    __nv_bfloat162* hw2 = reinterpret_cast<__nv_bfloat162*>(hw);
    #pragma unroll
    for (int mi = 0; mi < 4; mi++) {
        int r = m0 + wm * 64 + mi * 16 + g;
        #pragma unroll
        for (int nj = 0; nj < 4; nj++) {
            int c2 = (n0 + wn * 32 + nj * 8 + q * 2) >> 1;
            if (r < MM)
                hw2[(size_t)r * 128 + c2] =
                    __floats2bfloat162_rn(acc[mi][nj][0], acc[mi][nj][1]);
            if (r + 8 < MM)
                hw2[(size_t)(r + 8) * 128 + c2] =
                    __floats2bfloat162_rn(acc[mi][nj][2], acc[mi][nj][3]);
        }
    }
}

// ---------------- CSR gather: LDG.128, 1 block/node, 128 thr ----------------
// thread t: fq = t&31 -> 16B chunk (features 8fq..8fq+7); bp = t>>5 -> batches
// 2bp, 2bp+1. Per edge: 2 x LDG.128. Row = 32 uint4.
template <bool FUSE_FC>
__global__ __launch_bounds__(128) void gather_kernel(
    const uint4* __restrict__ hw4, const float* __restrict__ bias,
    uint4* __restrict__ hout4,
    const float* __restrict__ fcW, const float* __restrict__ fcb)
{
    const int n  = blockIdx.x;
    const int t  = threadIdx.x;
    const int fq = t & 31;
    const int bp = t >> 5;
    const int b0 = 2 * bp, b1 = 2 * bp + 1;
    const size_t plane = (size_t)NN * 32;
    const uint4* hp0 = hw4 + (size_t)b0 * plane;
    const uint4* hp1 = hw4 + (size_t)b1 * plane;

    // FUSE_FC: stage fc weights (768 floats) into shared, coalesced
    __shared__ float sfw[FUSE_FC ? 768 : 1];
    if (FUSE_FC) {
        #pragma unroll
        for (int i = t; i < 768; i += 128) sfw[i] = fcW[i];
        __syncthreads();
    }

    const int p0 = d_csr_ptr[n];
    const int p1 = d_csr_ptr[n + 1];

    float a0[8], a1v[8];
    #pragma unroll
    for (int i = 0; i < 8; i++) { a0[i] = 0.0f; a1v[i] = 0.0f; }

    #pragma unroll 2
    for (int e = p0; e < p1; e++) {
        int   src = __ldg(&d_csr_src[e]);
        float w   = __ldg(&d_csr_w[e]);
        size_t ro = (size_t)src * 32 + fq;
        uint4 u0 = __ldg(hp0 + ro);
        uint4 u1 = __ldg(hp1 + ro);
        acc8(a0,  u0, w);
        acc8(a1v, u1, w);
    }

    const float di = d_deginv[n];
    const float4 bsa = reinterpret_cast<const float4*>(bias)[2 * fq];
    const float4 bsb = reinterpret_cast<const float4*>(bias)[2 * fq + 1];
    const float bs[8] = {bsa.x, bsa.y, bsa.z, bsa.w, bsb.x, bsb.y, bsb.z, bsb.w};

    size_t so = (size_t)n * 32 + fq;
    // self-loop rows
    float s0[8], s1[8];
    {
        uint4 u0 = __ldg(hp0 + so);
        uint4 u1 = __ldg(hp1 + so);
        #pragma unroll
        for (int i = 0; i < 8; i++) { s0[i] = 0.0f; s1[i] = 0.0f; }
        acc8(s0, u0, di);
        acc8(s1, u1, di);
    }
    float v0[8], v1[8];
    #pragma unroll
    for (int i = 0; i < 8; i++) {
        v0[i] = eluf(a0[i]  + s0[i] + bs[i]);
        v1[i] = eluf(a1v[i] + s1[i] + bs[i]);
    }

    if (!FUSE_FC) {
        uint4 o0, o1;
        __nv_bfloat162 p;
        p = __floats2bfloat162_rn(v0[0], v0[1]); o0.x = *reinterpret_cast<uint32_t*>(&p);
        p = __floats2bfloat162_rn(v0[2], v0[3]); o0.y = *reinterpret_cast<uint32_t*>(&p);
        p = __floats2bfloat162_rn(v0[4], v0[5]); o0.z = *reinterpret_cast<uint32_t*>(&p);
        p = __floats2bfloat162_rn(v0[6], v0[7]); o0.w = *reinterpret_cast<uint32_t*>(&p);
        p = __floats2bfloat162_rn(v1[0], v1[1]); o1.x = *reinterpret_cast<uint32_t*>(&p);
        p = __floats2bfloat162_rn(v1[2], v1[3]); o1.y = *reinterpret_cast<uint32_t*>(&p);
        p = __floats2bfloat162_rn(v1[4], v1[5]); o1.z = *reinterpret_cast<uint32_t*>(&p);
        p = __floats2bfloat162_rn(v1[6], v1[7]); o1.w = *reinterpret_cast<uint32_t*>(&p);
        hout4[(size_t)b0 * plane + so] = o0;
        hout4[(size_t)b1 * plane + so] = o1;
    } else {
        // fc: feature f = 8*fq + i; weights sfw[3f + l]
        const uint4* h1p0 = reinterpret_cast<const uint4*>(d_h1) + (size_t)b0 * plane;
        const uint4* h1p1 = reinterpret_cast<const uint4*>(d_h1) + (size_t)b1 * plane;
        const uint4* h2p0 = reinterpret_cast<const uint4*>(d_h2) + (size_t)b0 * plane;
        const uint4* h2p1 = reinterpret_cast<const uint4*>(d_h2) + (size_t)b1 * plane;
        uint4 h1u0 = __ldg(h1p0 + so), h1u1 = __ldg(h1p1 + so);
        uint4 h2u0 = __ldg(h2p0 + so), h2u1 = __ldg(h2p1 + so);
        float h10[8], h11[8], h20[8], h21[8];
        #pragma unroll
        for (int i = 0; i < 8; i++) { h10[i]=h11[i]=h20[i]=h21[i]=0.0f; }
        acc8(h10, h1u0, 1.0f); acc8(h11, h1u1, 1.0f);
        acc8(h20, h2u0, 1.0f); acc8(h21, h2u1, 1.0f);
        float g0 = 0.0f, g1 = 0.0f;
        #pragma unroll
        for (int i = 0; i < 8; i++) {
            const float* fw = &sfw[24 * fq + 3 * i];
            g0 += h10[i] * fw[0] + h20[i] * fw[1] + v0[i] * fw[2];
            g1 += h11[i] * fw[0] + h21[i] * fw[1] + v1[i] * fw[2];
        }
        // warp covers full feature row for its batch pair
        #pragma unroll
        for (int o = 16; o > 0; o >>= 1) {
            g0 += __shfl_down_sync(0xffffffffu, g0, o);
            g1 += __shfl_down_sync(0xffffffffu, g1, o);
        }
        if (fq == 0) {
            float fb = fcb[0];
            d_g[(size_t)b0 * NN + n] = g0 + fb;
            d_g[(size_t)b1 * NN + n] = g1 + fb;
        }
    }
}

// ---------------- lin1: g[b,N] @ lin1_W[N,512] (accumulate) ----------------
#define NCH 256
__global__ __launch_bounds__(128) void lin1_kernel(const float* __restrict__ W)
{
    __shared__ float gs[BSZ][NCH];
    const int j  = blockIdx.x * 128 + threadIdx.x;
    const int n0 = blockIdx.y * NCH;
    const int cn = min(NCH, NN - n0);
    for (int idx = threadIdx.x; idx < BSZ * NCH; idx += 128) {
        int b  = idx >> 8;
        int nl = idx & (NCH - 1);
        gs[b][nl] = (nl < cn) ? d_g[(size_t)b * NN + n0 + nl] : 0.0f;
    }
    __syncthreads();
    float acc[BSZ];
    #pragma unroll
    for (int b = 0; b < BSZ; b++) acc[b] = 0.0f;
    for (int nl = 0; nl < cn; nl++) {
        float w = W[(size_t)(n0 + nl) * HFCC + j];
        #pragma unroll
        for (int b = 0; b < BSZ; b++) acc[b] += gs[b][nl] * w;
    }
    #pragma unroll
    for (int b = 0; b < BSZ; b++) atomicAdd(&d_zacc[b * HFCC + j], acc[b]);
}

// ---------------- lin2 + log_softmax ----------------
__global__ __launch_bounds__(256) void lin2_kernel(
    const float* __restrict__ lin1b, const float* __restrict__ lin2W,
    const float* __restrict__ lin2b, float* __restrict__ out)
{
    const int b = blockIdx.x;
    const int t = threadIdx.x;
    float s0 = 0.0f, s1 = 0.0f;
    for (int j = t; j < HFCC; j += 256) {
        float z = d_zacc[b * HFCC + j] + lin1b[j];
        z = eluf(z);
        s0 += z * lin2W[j * 2 + 0];
        s1 += z * lin2W[j * 2 + 1];
    }
    __shared__ float r0[256], r1[256];
    r0[t] = s0; r1[t] = s1;
    __syncthreads();
    for (int o = 128; o > 0; o >>= 1) {
        if (t < o) { r0[t] += r0[t + o]; r1[t] += r1[t + o]; }
        __syncthreads();
    }
    if (t == 0) {
        float o0 = r0[0] + lin2b[0];
        float o1 = r1[0] + lin2b[1];
        float mx = fmaxf(o0, o1);
        float lse = mx + logf(expf(o0 - mx) + expf(o1 - mx));
        out[b * CCLS + 0] = o0 - lse;
        out[b * CCLS + 1] = o1 - lse;
    }
}

// ---------------- launcher ----------------
extern "C" void kernel_launch(void* const* d_in, const int* in_sizes, int n_in,
                              void* d_out, int out_size)
{
    const float* x     = (const float*)d_in[0];
    const int*   ei    = (const int*)d_in[2];   // int32 [2, E]
    const float* pe    = (const float*)d_in[3];
    const float* W1    = (const float*)d_in[4];
    const float* b1    = (const float*)d_in[5];
    const float* W2    = (const float*)d_in[6];
    const float* b2    = (const float*)d_in[7];
    const float* W3    = (const float*)d_in[8];
    const float* b3    = (const float*)d_in[9];
    const float* fcW   = (const float*)d_in[10];
    const float* fcb   = (const float*)d_in[11];
    const float* lin1W = (const float*)d_in[12];
    const float* lin1b = (const float*)d_in[13];
    const float* lin2W = (const float*)d_in[14];
    const float* lin2b = (const float*)d_in[15];
    float* out = (float*)d_out;

    __nv_bfloat16 *hwp, *h1p, *h2p, *a1p, *wt1p, *wt2p, *wt3p;
    cudaGetSymbolAddress((void**)&hwp,  d_hw);
    cudaGetSymbolAddress((void**)&h1p,  d_h1);
    cudaGetSymbolAddress((void**)&h2p,  d_h2);
    cudaGetSymbolAddress((void**)&a1p,  d_a1);
    cudaGetSymbolAddress((void**)&wt1p, d_wt1);
    cudaGetSymbolAddress((void**)&wt2p, d_wt2);
    cudaGetSymbolAddress((void**)&wt3p, d_wt3);
    int* degip; float* zaccp;
    cudaGetSymbolAddress((void**)&degip, d_degi);
    cudaGetSymbolAddress((void**)&zaccp, d_zacc);

    cudaFuncSetAttribute(gemm_mma_kernel<K1PAD>,
                         cudaFuncAttributeMaxDynamicSharedMemorySize, GSM_BYTES);
    cudaFuncSetAttribute(gemm_mma_kernel<HH>,
                         cudaFuncAttributeMaxDynamicSharedMemorySize, GSM_BYTES);

    // degrees + CSR
    cudaMemsetAsync(degip, 0, NN * sizeof(int));
    count_deg_kernel<<<(EE + 255) / 256, 256>>>(ei);
    scanfin_kernel<<<1, 1024>>>();
    fill_csr_kernel<<<(EE + 255) / 256, 256>>>(ei);

    // GEMM prep
    {
        long long tot = (long long)MM * (K1PAD / 2);
        build_a1_kernel<<<(unsigned)((tot + 255) / 256), 256>>>(x, pe);
        transpose_w_kernel<<<HH, 192>>>(W1, KIN, wt1p, K1PAD);
        transpose_w_kernel<<<HH, 256>>>(W2, HH, wt2p, HH);
        transpose_w_kernel<<<HH, 256>>>(W3, HH, wt3p, HH);
    }

    const dim3 ggrid((MM + 127) / 128, HH / 128);
    const uint4* hw4 = reinterpret_cast<const uint4*>(hwp);
    uint4* h14 = reinterpret_cast<uint4*>(h1p);
    uint4* h24 = reinterpret_cast<uint4*>(h2p);

    // layer 1
    gemm_mma_kernel<K1PAD><<<ggrid, 256, GSM_BYTES>>>(a1p, wt1p, hwp);
    gather_kernel<false><<<NN, 128>>>(hw4, b1, h14, nullptr, nullptr);

    // layer 2
    gemm_mma_kernel<HH><<<ggrid, 256, GSM_BYTES>>>(h1p, wt2p, hwp);
    gather_kernel<false><<<NN, 128>>>(hw4, b2, h24, nullptr, nullptr);

    // layer 3 (+ fused fc head -> d_g)
    gemm_mma_kernel<HH><<<ggrid, 256, GSM_BYTES>>>(h2p, wt3p, hwp);
    gather_kernel<true><<<NN, 128>>>(hw4, b3, nullptr, fcW, fcb);

    // heads
    cudaMemsetAsync(zaccp, 0, BSZ * HFCC * sizeof(float));
    lin1_kernel<<<dim3(HFCC / 128, (NN + NCH - 1) / NCH), 128>>>(lin1W);
    lin2_kernel<<<BSZ, 256>>>(lin1b, lin2W, lin2b, out);
}

// round 9
// speedup vs baseline: 5.7690x; 1.0720x over previous
#include <cuda_runtime.h>
#include <cuda_bf16.h>
#include <math.h>
#include <cstdint>

// Problem constants
#define BSZ 8
#define NN  15135
#define FF  64
#define GG  73
#define HH  256
#define HFCC 512
#define CCLS 2
#define EE  242160
#define KIN (FF + GG)        // 137
#define MM  (BSZ * NN)       // 121080
#define K1PAD 192            // layer-1 K padded to multiple of 64

// ---------------- scratch (device globals; no dynamic alloc allowed) -------
__device__ int   d_degi[NN];
__device__ float d_dis[NN];
__device__ float d_deginv[NN];
__device__ int   d_csr_ptr[NN + 1];
__device__ int   d_cursor[NN];
__device__ int   d_csr_src[EE];
__device__ float d_csr_w[EE];
__device__ __align__(16) __nv_bfloat16 d_hw[(size_t)MM * HH];
__device__ __align__(16) __nv_bfloat16 d_h1[(size_t)MM * HH];
__device__ __align__(16) __nv_bfloat16 d_h2[(size_t)MM * HH];
__device__ __align__(16) __nv_bfloat16 d_ag1[(size_t)MM * K1PAD];  // aggregated concat input
__device__ __align__(16) __nv_bfloat16 d_xb[(size_t)MM * FF];      // x in bf16
__device__ __align__(16) __nv_bfloat16 d_wt1[HH * K1PAD];   // W1^T padded
__device__ __align__(16) __nv_bfloat16 d_wt2[HH * HH];      // W2^T
__device__ __align__(16) __nv_bfloat16 d_wt3[HH * HH];      // W3^T
__device__ float d_g[MM];
__device__ float d_zacc[BSZ * HFCC];

__device__ __forceinline__ float eluf(float v) {
    return v > 0.0f ? v : expm1f(v);
}

__device__ __forceinline__ float2 bf2f(uint32_t u) {
    __nv_bfloat162 m = *reinterpret_cast<__nv_bfloat162*>(&u);
    return make_float2(__bfloat162float(m.x), __bfloat162float(m.y));
}

// accumulate 8 bf16 lanes of u into a[0..7] with weight w
__device__ __forceinline__ void acc8(float* a, uint4 u, float w) {
    float2 m;
    m = bf2f(u.x); a[0] += w * m.x; a[1] += w * m.y;
    m = bf2f(u.y); a[2] += w * m.x; a[3] += w * m.y;
    m = bf2f(u.z); a[4] += w * m.x; a[5] += w * m.y;
    m = bf2f(u.w); a[6] += w * m.x; a[7] += w * m.y;
}

__device__ __forceinline__ uint4 pack8(const float* v) {
    uint4 o;
    __nv_bfloat162 p;
    p = __floats2bfloat162_rn(v[0], v[1]); o.x = *reinterpret_cast<uint32_t*>(&p);
    p = __floats2bfloat162_rn(v[2], v[3]); o.y = *reinterpret_cast<uint32_t*>(&p);
    p = __floats2bfloat162_rn(v[4], v[5]); o.z = *reinterpret_cast<uint32_t*>(&p);
    p = __floats2bfloat162_rn(v[6], v[7]); o.w = *reinterpret_cast<uint32_t*>(&p);
    return o;
}

// ---------------- degree / CSR build ----------------
__global__ void count_deg_kernel(const int* __restrict__ ei) {
    int e = blockIdx.x * blockDim.x + threadIdx.x;
    if (e < EE) atomicAdd(&d_degi[ei[EE + e]], 1);
}

// single-block exclusive prefix sum (warp shuffle) + dis/deginv
__global__ __launch_bounds__(1024) void scanfin_kernel() {
    __shared__ int wsum[32];
    __shared__ int soff;
    const int t = threadIdx.x;
    const int lane = t & 31, warp = t >> 5;
    if (t == 0) soff = 0;
    __syncthreads();
    for (int base = 0; base < NN; base += 1024) {
        int v = 0;
        if (base + t < NN) {
            v = d_degi[base + t];
            float d = (float)v + 1.0f;
            d_dis[base + t]    = rsqrtf(d);
            d_deginv[base + t] = 1.0f / d;
        }
        int incl = v;
        #pragma unroll
        for (int o = 1; o < 32; o <<= 1) {
            int u = __shfl_up_sync(0xffffffffu, incl, o);
            if (lane >= o) incl += u;
        }
        if (lane == 31) wsum[warp] = incl;
        __syncthreads();
        if (warp == 0) {
            int s = wsum[lane];
            #pragma unroll
            for (int o = 1; o < 32; o <<= 1) {
                int u = __shfl_up_sync(0xffffffffu, s, o);
                if (lane >= o) s += u;
            }
            wsum[lane] = s;
        }
        __syncthreads();
        int wbase = (warp > 0) ? wsum[warp - 1] : 0;
        int excl = soff + wbase + incl - v;
        if (base + t < NN) {
            d_csr_ptr[base + t] = excl;
            d_cursor[base + t]  = excl;
        }
        __syncthreads();
        if (t == 0) soff += wsum[31];
        __syncthreads();
    }
    if (t == 0) d_csr_ptr[NN] = soff;
}

__global__ void fill_csr_kernel(const int* __restrict__ ei) {
    int e = blockIdx.x * blockDim.x + threadIdx.x;
    if (e < EE) {
        int r = ei[e];
        int c = ei[EE + e];
        int pos = atomicAdd(&d_cursor[c], 1);
        d_csr_src[pos] = r;
        d_csr_w[pos]   = d_dis[r] * d_dis[c];
    }
}

// ---------------- prep kernels ----------------
// x fp32 -> bf16, one uint4 (8 bf16) per thread
__global__ void convert_x_kernel(const float* __restrict__ x) {
    long long i = (long long)blockIdx.x * blockDim.x + threadIdx.x;
    if (i >= (long long)MM * 8) return;
    const float4* src = reinterpret_cast<const float4*>(x) + 2 * i;
    float4 v0 = src[0], v1 = src[1];
    float v[8] = {v0.x, v0.y, v0.z, v0.w, v1.x, v1.y, v1.z, v1.w};
    reinterpret_cast<uint4*>(d_xb)[i] = pack8(v);
}

// Wt[n][k] = k<Kin ? W[k][n] : 0 ; grid = HH blocks
__global__ void transpose_w_kernel(const float* __restrict__ W, int Kin,
                                   __nv_bfloat16* __restrict__ Wt, int KPAD) {
    int n = blockIdx.x;
    for (int k = threadIdx.x; k < KPAD; k += blockDim.x)
        Wt[(size_t)n * KPAD + k] =
            __float2bfloat16_rn((k < Kin) ? W[(size_t)k * HH + n] : 0.0f);
}

// ---------------- layer-1 pre-aggregation (A_norm . h before GEMM) ---------
// aggregate x: 2 nodes/block; 64 threads per node = 8 batches x 8 uint4 chunks
__global__ __launch_bounds__(128) void gather_x_kernel() {
    const int t = threadIdx.x;
    const int n = blockIdx.x * 2 + (t >> 6);
    if (n >= NN) return;
    const int b  = (t >> 3) & 7;
    const int fq = t & 7;
    const uint4* xp = reinterpret_cast<const uint4*>(d_xb) + (size_t)b * NN * 8;

    const int p0 = d_csr_ptr[n];
    const int p1 = d_csr_ptr[n + 1];
    float a[8];
    #pragma unroll
    for (int i = 0; i < 8; i++) a[i] = 0.0f;

    #pragma unroll 2
    for (int e = p0; e < p1; e++) {
        int   src = __ldg(&d_csr_src[e]);
        float w   = __ldg(&d_csr_w[e]);
        acc8(a, __ldg(xp + (size_t)src * 8 + fq), w);
    }
    acc8(a, __ldg(xp + (size_t)n * 8 + fq), d_deginv[n]);   // self loop

    // ag1 row = 192 bf16 = 24 uint4; x part at chunk fq
    reinterpret_cast<uint4*>(d_ag1)[((size_t)b * NN + n) * 24 + fq] = pack8(a);
}

// aggregate pe (batch-independent), broadcast into all 8 batch rows of ag1
__global__ __launch_bounds__(128) void gather_pe_kernel(const float* __restrict__ pe) {
    const int n = blockIdx.x;
    const int t = threadIdx.x;
    float a = 0.0f;
    if (t < GG) {
        const int p0 = d_csr_ptr[n];
        const int p1 = d_csr_ptr[n + 1];
        #pragma unroll 2
        for (int e = p0; e < p1; e++) {
            int   src = __ldg(&d_csr_src[e]);
            float w   = __ldg(&d_csr_w[e]);
            a += w * __ldg(&pe[(size_t)src * GG + t]);
        }
        a += d_deginv[n] * __ldg(&pe[(size_t)n * GG + t]);
    }
    __nv_bfloat16 v = __float2bfloat16_rn(t < GG ? a : 0.0f);
    // cols 64..191 (t: 0..127); t >= 73 writes zero padding
    #pragma unroll
    for (int b = 0; b < BSZ; b++)
        d_ag1[((size_t)b * NN + n) * K1PAD + FF + t] = v;
}

// ================= mma.sync bf16 GEMM (sm_80 baseline PTX) ==================
__device__ __forceinline__ void cp_async16(uint32_t dst, const void* src, int sz) {
    asm volatile("cp.async.cg.shared.global [%0], [%1], 16, %2;"
                 :: "r"(dst), "l"(src), "r"(sz) : "memory");
}

__device__ __forceinline__ void mma_bf16(float* c, const uint32_t* a, const uint32_t* b) {
    asm volatile(
        "mma.sync.aligned.m16n8k16.row.col.f32.bf16.bf16.f32 "
        "{%0,%1,%2,%3}, {%4,%5,%6,%7}, {%8,%9}, {%0,%1,%2,%3};"
        : "+f"(c[0]), "+f"(c[1]), "+f"(c[2]), "+f"(c[3])
        : "r"(a[0]), "r"(a[1]), "r"(a[2]), "r"(a[3]), "r"(b[0]), "r"(b[1]));
}

#define GSTRU 36
#define GBUFU (2 * 128 * GSTRU)
#define GSM_BYTES (2 * GBUFU * 4)

// EPI: fused bias + ELU epilogue (layer 1 writes h1 directly)
template <int KPAD, bool EPI>
__global__ __launch_bounds__(256, 2) void gemm_mma_kernel(
    const __nv_bfloat16* __restrict__ A, const __nv_bfloat16* __restrict__ Wt,
    __nv_bfloat16* __restrict__ hw, const float* __restrict__ bias)
{
    extern __shared__ uint32_t sm[];
    constexpr int NC = KPAD / 64;
    const int t    = threadIdx.x;
    const int lane = t & 31;
    const int wid  = t >> 5;
    const int wm   = wid >> 2;
    const int wn   = wid & 3;
    const int m0   = blockIdx.x * 128;
    const int n0   = blockIdx.y * 128;
    const int g    = lane >> 2;
    const int q    = lane & 3;

    float acc[4][4][4];
    #pragma unroll
    for (int mi = 0; mi < 4; mi++)
        #pragma unroll
        for (int nj = 0; nj < 4; nj++)
            #pragma unroll
            for (int r = 0; r < 4; r++) acc[mi][nj][r] = 0.0f;

    auto load_chunk = [&](int ci, int buf) {
        uint32_t* dA = sm + buf * GBUFU;
        uint32_t* dB = dA + 128 * GSTRU;
        const int k0 = ci * 64;
        #pragma unroll
        for (int r = 0; r < 4; r++) {
            int idx = t + r * 256;
            int row = idx >> 3;
            int seg = idx & 7;
            int m   = m0 + row;
            int valid = (m < MM);
            const __nv_bfloat16* srcA = A + (size_t)(valid ? m : 0) * KPAD + k0 + seg * 8;
            cp_async16((uint32_t)__cvta_generic_to_shared(dA + row * GSTRU + seg * 4),
                       srcA, valid ? 16 : 0);
            const __nv_bfloat16* srcB = Wt + (size_t)(n0 + row) * KPAD + k0 + seg * 8;
            cp_async16((uint32_t)__cvta_generic_to_shared(dB + row * GSTRU + seg * 4),
                       srcB, 16);
        }
        asm volatile("cp.async.commit_group;" ::: "memory");
    };

    load_chunk(0, 0);
    if (NC > 1) load_chunk(1, 1);
    else        asm volatile("cp.async.commit_group;" ::: "memory");

    #pragma unroll 1
    for (int i = 0; i < NC; i++) {
        asm volatile("cp.async.wait_group 1;" ::: "memory");
        __syncthreads();
        const uint32_t* As = sm + (i & 1) * GBUFU;
        const uint32_t* Bs = As + 128 * GSTRU;

        #pragma unroll
        for (int ks = 0; ks < 4; ks++) {
            const int cb = ks * 8 + q;
            uint32_t a[4][4], b[4][2];
            #pragma unroll
            for (int mi = 0; mi < 4; mi++) {
                int r = wm * 64 + mi * 16 + g;
                a[mi][0] = As[r * GSTRU + cb];
                a[mi][1] = As[(r + 8) * GSTRU + cb];
                a[mi][2] = As[r * GSTRU + cb + 4];
                a[mi][3] = As[(r + 8) * GSTRU + cb + 4];
            }
            #pragma unroll
            for (int nj = 0; nj < 4; nj++) {
                int n = wn * 32 + nj * 8 + g;
                b[nj][0] = Bs[n * GSTRU + cb];
                b[nj][1] = Bs[n * GSTRU + cb + 4];
            }
            #pragma unroll
            for (int mi = 0; mi < 4; mi++)
                #pragma unroll
                for (int nj = 0; nj < 4; nj++)
                    mma_bf16(acc[mi][nj], a[mi], b[nj]);
        }
        __syncthreads();
        if (i + 2 < NC) load_chunk(i + 2, i & 1);
        else            asm volatile("cp.async.commit_group;" ::: "memory");
    }

    __nv_bfloat162* hw2 = reinterpret_cast<__nv_bfloat162*>(hw);
    #pragma unroll
    for (int mi = 0; mi < 4; mi++) {
        int r = m0 + wm * 64 + mi * 16 + g;
        #pragma unroll
        for (int nj = 0; nj < 4; nj++) {
            int c  = n0 + wn * 32 + nj * 8 + q * 2;
            float v0 = acc[mi][nj][0], v1 = acc[mi][nj][1];
            float v2 = acc[mi][nj][2], v3 = acc[mi][nj][3];
            if (EPI) {
                float2 bv = *reinterpret_cast<const float2*>(bias + c);
                v0 = eluf(v0 + bv.x); v1 = eluf(v1 + bv.y);
                v2 = eluf(v2 + bv.x); v3 = eluf(v3 + bv.y);
            }
            int c2 = c >> 1;
            if (r < MM)
                hw2[(size_t)r * 128 + c2] = __floats2bfloat162_rn(v0, v1);
            if (r + 8 < MM)
                hw2[(size_t)(r + 8) * 128 + c2] = __floats2bfloat162_rn(v2, v3);
        }
    }
}

// ---------------- CSR gather (layers 2/3): LDG.128, 1 block/node ------------
template <bool FUSE_FC>
__global__ __launch_bounds__(128) void gather_kernel(
    const uint4* __restrict__ hw4, const float* __restrict__ bias,
    uint4* __restrict__ hout4,
    const float* __restrict__ fcW, const float* __restrict__ fcb)
{
    const int n  = blockIdx.x;
    const int t  = threadIdx.x;
    const int fq = t & 31;
    const int bp = t >> 5;
    const int b0 = 2 * bp, b1 = 2 * bp + 1;
    const size_t plane = (size_t)NN * 32;
    const uint4* hp0 = hw4 + (size_t)b0 * plane;
    const uint4* hp1 = hw4 + (size_t)b1 * plane;

    __shared__ float sfw[FUSE_FC ? 768 : 1];
    if (FUSE_FC) {
        #pragma unroll
        for (int i = t; i < 768; i += 128) sfw[i] = fcW[i];
        __syncthreads();
    }

    const int p0 = d_csr_ptr[n];
    const int p1 = d_csr_ptr[n + 1];

    float a0[8], a1v[8];
    #pragma unroll
    for (int i = 0; i < 8; i++) { a0[i] = 0.0f; a1v[i] = 0.0f; }

    #pragma unroll 2
    for (int e = p0; e < p1; e++) {
        int   src = __ldg(&d_csr_src[e]);
        float w   = __ldg(&d_csr_w[e]);
        size_t ro = (size_t)src * 32 + fq;
        uint4 u0 = __ldg(hp0 + ro);
        uint4 u1 = __ldg(hp1 + ro);
        acc8(a0,  u0, w);
        acc8(a1v, u1, w);
    }

    const float di = d_deginv[n];
    const float4 bsa = reinterpret_cast<const float4*>(bias)[2 * fq];
    const float4 bsb = reinterpret_cast<const float4*>(bias)[2 * fq + 1];
    const float bs[8] = {bsa.x, bsa.y, bsa.z, bsa.w, bsb.x, bsb.y, bsb.z, bsb.w};

    size_t so = (size_t)n * 32 + fq;
    acc8(a0,  __ldg(hp0 + so), di);
    acc8(a1v, __ldg(hp1 + so), di);

    float v0[8], v1[8];
    #pragma unroll
    for (int i = 0; i < 8; i++) {
        v0[i] = eluf(a0[i]  + bs[i]);
        v1[i] = eluf(a1v[i] + bs[i]);
    }

    if (!FUSE_FC) {
        hout4[(size_t)b0 * plane + so] = pack8(v0);
        hout4[(size_t)b1 * plane + so] = pack8(v1);
    } else {
        const uint4* h1p0 = reinterpret_cast<const uint4*>(d_h1) + (size_t)b0 * plane;
        const uint4* h1p1 = reinterpret_cast<const uint4*>(d_h1) + (size_t)b1 * plane;
        const uint4* h2p0 = reinterpret_cast<const uint4*>(d_h2) + (size_t)b0 * plane;
        const uint4* h2p1 = reinterpret_cast<const uint4*>(d_h2) + (size_t)b1 * plane;
        float h10[8], h11[8], h20[8], h21[8];
        #pragma unroll
        for (int i = 0; i < 8; i++) { h10[i]=h11[i]=h20[i]=h21[i]=0.0f; }
        acc8(h10, __ldg(h1p0 + so), 1.0f); acc8(h11, __ldg(h1p1 + so), 1.0f);
        acc8(h20, __ldg(h2p0 + so), 1.0f); acc8(h21, __ldg(h2p1 + so), 1.0f);
        float g0 = 0.0f, g1 = 0.0f;
        #pragma unroll
        for (int i = 0; i < 8; i++) {
            const float* fw = &sfw[24 * fq + 3 * i];
            g0 += h10[i] * fw[0] + h20[i] * fw[1] + v0[i] * fw[2];
            g1 += h11[i] * fw[0] + h21[i] * fw[1] + v1[i] * fw[2];
        }
        #pragma unroll
        for (int o = 16; o > 0; o >>= 1) {
            g0 += __shfl_down_sync(0xffffffffu, g0, o);
            g1 += __shfl_down_sync(0xffffffffu, g1, o);
        }
        if (fq == 0) {
            float fb = fcb[0];
            d_g[(size_t)b0 * NN + n] = g0 + fb;
            d_g[(size_t)b1 * NN + n] = g1 + fb;
        }
    }
}

// ---------------- lin1: g[b,N] @ lin1_W[N,512] (accumulate) ----------------
#define NCH 256
__global__ __launch_bounds__(128) void lin1_kernel(const float* __restrict__ W)
{
    __shared__ float gs[BSZ][NCH];
    const int j  = blockIdx.x * 128 + threadIdx.x;
    const int n0 = blockIdx.y * NCH;
    const int cn = min(NCH, NN - n0);
    for (int idx = threadIdx.x; idx < BSZ * NCH; idx += 128) {
        int b  = idx >> 8;
        int nl = idx & (NCH - 1);
        gs[b][nl] = (nl < cn) ? d_g[(size_t)b * NN + n0 + nl] : 0.0f;
    }
    __syncthreads();
    float acc[BSZ];
    #pragma unroll
    for (int b = 0; b < BSZ; b++) acc[b] = 0.0f;
    for (int nl = 0; nl < cn; nl++) {
        float w = W[(size_t)(n0 + nl) * HFCC + j];
        #pragma unroll
        for (int b = 0; b < BSZ; b++) acc[b] += gs[b][nl] * w;
    }
    #pragma unroll
    for (int b = 0; b < BSZ; b++) atomicAdd(&d_zacc[b * HFCC + j], acc[b]);
}

// ---------------- lin2 + log_softmax ----------------
__global__ __launch_bounds__(256) void lin2_kernel(
    const float* __restrict__ lin1b, const float* __restrict__ lin2W,
    const float* __restrict__ lin2b, float* __restrict__ out)
{
    const int b = blockIdx.x;
    const int t = threadIdx.x;
    float s0 = 0.0f, s1 = 0.0f;
    for (int j = t; j < HFCC; j += 256) {
        float z = d_zacc[b * HFCC + j] + lin1b[j];
        z = eluf(z);
        s0 += z * lin2W[j * 2 + 0];
        s1 += z * lin2W[j * 2 + 1];
    }
    __shared__ float r0[256], r1[256];
    r0[t] = s0; r1[t] = s1;
    __syncthreads();
    for (int o = 128; o > 0; o >>= 1) {
        if (t < o) { r0[t] += r0[t + o]; r1[t] += r1[t + o]; }
        __syncthreads();
    }
    if (t == 0) {
        float o0 = r0[0] + lin2b[0];
        float o1 = r1[0] + lin2b[1];
        float mx = fmaxf(o0, o1);
        float lse = mx + logf(expf(o0 - mx) + expf(o1 - mx));
        out[b * CCLS + 0] = o0 - lse;
        out[b * CCLS + 1] = o1 - lse;
    }
}

// ---------------- launcher ----------------
extern "C" void kernel_launch(void* const* d_in, const int* in_sizes, int n_in,
                              void* d_out, int out_size)
{
    const float* x     = (const float*)d_in[0];
    const int*   ei    = (const int*)d_in[2];   // int32 [2, E]
    const float* pe    = (const float*)d_in[3];
    const float* W1    = (const float*)d_in[4];
    const float* b1    = (const float*)d_in[5];
    const float* W2    = (const float*)d_in[6];
    const float* b2    = (const float*)d_in[7];
    const float* W3    = (const float*)d_in[8];
    const float* b3    = (const float*)d_in[9];
    const float* fcW   = (const float*)d_in[10];
    const float* fcb   = (const float*)d_in[11];
    const float* lin1W = (const float*)d_in[12];
    const float* lin1b = (const float*)d_in[13];
    const float* lin2W = (const float*)d_in[14];
    const float* lin2b = (const float*)d_in[15];
    float* out = (float*)d_out;

    __nv_bfloat16 *hwp, *h1p, *h2p, *ag1p, *wt1p, *wt2p, *wt3p;
    cudaGetSymbolAddress((void**)&hwp,  d_hw);
    cudaGetSymbolAddress((void**)&h1p,  d_h1);
    cudaGetSymbolAddress((void**)&h2p,  d_h2);
    cudaGetSymbolAddress((void**)&ag1p, d_ag1);
    cudaGetSymbolAddress((void**)&wt1p, d_wt1);
    cudaGetSymbolAddress((void**)&wt2p, d_wt2);
    cudaGetSymbolAddress((void**)&wt3p, d_wt3);
    int* degip; float* zaccp;
    cudaGetSymbolAddress((void**)&degip, d_degi);
    cudaGetSymbolAddress((void**)&zaccp, d_zacc);

    cudaFuncSetAttribute((void*)gemm_mma_kernel<K1PAD, true>,
                         cudaFuncAttributeMaxDynamicSharedMemorySize, GSM_BYTES);
    cudaFuncSetAttribute((void*)gemm_mma_kernel<HH, false>,
                         cudaFuncAttributeMaxDynamicSharedMemorySize, GSM_BYTES);

    // degrees + CSR
    cudaMemsetAsync(degip, 0, NN * sizeof(int));
    count_deg_kernel<<<(EE + 255) / 256, 256>>>(ei);
    scanfin_kernel<<<1, 1024>>>();
    fill_csr_kernel<<<(EE + 255) / 256, 256>>>(ei);

    // prep: x->bf16, W transposes
    convert_x_kernel<<<(MM * 8 + 255) / 256, 256>>>(x);
    transpose_w_kernel<<<HH, 192>>>(W1, KIN, wt1p, K1PAD);
    transpose_w_kernel<<<HH, 256>>>(W2, HH, wt2p, HH);
    transpose_w_kernel<<<HH, 256>>>(W3, HH, wt3p, HH);

    // layer 1: pre-aggregate input, then GEMM with fused bias+ELU -> h1
    gather_x_kernel<<<(NN + 1) / 2, 128>>>();
    gather_pe_kernel<<<NN, 128>>>(pe);

    const dim3 ggrid((MM + 127) / 128, HH / 128);
    const uint4* hw4 = reinterpret_cast<const uint4*>(hwp);
    uint4* h14 = reinterpret_cast<uint4*>(h1p);
    uint4* h24 = reinterpret_cast<uint4*>(h2p);

    gemm_mma_kernel<K1PAD, true><<<ggrid, 256, GSM_BYTES>>>(ag1p, wt1p, h1p, b1);

    // layer 2
    gemm_mma_kernel<HH, false><<<ggrid, 256, GSM_BYTES>>>(h1p, wt2p, hwp, nullptr);
    gather_kernel<false><<<NN, 128>>>(hw4, b2, h24, nullptr, nullptr);

    // layer 3 (+ fused fc head -> d_g)
    gemm_mma_kernel<HH, false><<<ggrid, 256, GSM_BYTES>>>(h2p, wt3p, hwp, nullptr);
    gather_kernel<true><<<NN, 128>>>(hw4, b3, nullptr, fcW, fcb);

    // heads
    cudaMemsetAsync(zaccp, 0, BSZ * HFCC * sizeof(float));
    lin1_kernel<<<dim3(HFCC / 128, (NN + NCH - 1) / NCH), 128>>>(lin1W);
    lin2_kernel<<<BSZ, 256>>>(lin1b, lin2W, lin2b, out);
}

// round 10
// speedup vs baseline: 5.9057x; 1.0237x over previous
#include <cuda_runtime.h>
#include <cuda_bf16.h>
#include <math.h>
#include <cstdint>

// Problem constants
#define BSZ 8
#define NN  15135
#define FF  64
#define GG  73
#define HH  256
#define HFCC 512
#define CCLS 2
#define EE  242160
#define KIN (FF + GG)        // 137
#define MM  (BSZ * NN)       // 121080
#define K1PAD 192            // layer-1 K padded to multiple of 64
#define SCANB 15             // ceil(NN/1024)

// ---------------- scratch (device globals; no dynamic alloc allowed) -------
__device__ int   d_degi[NN];
__device__ float d_dis[NN];
__device__ float d_deginv[NN];
__device__ int   d_csr_ptr[NN + 1];
__device__ int   d_cursor[NN];
__device__ int2  d_ew[EE];            // packed (src, weight-bits)
__device__ int   d_bsum[16];
__device__ int   d_boff[16];
__device__ __align__(16) __nv_bfloat16 d_hw[(size_t)MM * HH];
__device__ __align__(16) __nv_bfloat16 d_h1[(size_t)MM * HH];
__device__ __align__(16) __nv_bfloat16 d_h2[(size_t)MM * HH];
__device__ __align__(16) __nv_bfloat16 d_ag1[(size_t)MM * K1PAD];  // aggregated concat input
__device__ __align__(16) __nv_bfloat16 d_xb[(size_t)MM * FF];      // x in bf16
__device__ __align__(16) __nv_bfloat16 d_peb[(size_t)NN * GG];     // pe in bf16
__device__ __align__(16) __nv_bfloat16 d_wt1[HH * K1PAD];   // W1^T padded
__device__ __align__(16) __nv_bfloat16 d_wt2[HH * HH];      // W2^T
__device__ __align__(16) __nv_bfloat16 d_wt3[HH * HH];      // W3^T
__device__ float d_g[MM];
__device__ float d_zacc[BSZ * HFCC];

__device__ __forceinline__ float eluf(float v) {
    return v > 0.0f ? v : expm1f(v);
}

__device__ __forceinline__ float2 bf2f(uint32_t u) {
    __nv_bfloat162 m = *reinterpret_cast<__nv_bfloat162*>(&u);
    return make_float2(__bfloat162float(m.x), __bfloat162float(m.y));
}

// accumulate 8 bf16 lanes of u into a[0..7] with weight w
__device__ __forceinline__ void acc8(float* a, uint4 u, float w) {
    float2 m;
    m = bf2f(u.x); a[0] += w * m.x; a[1] += w * m.y;
    m = bf2f(u.y); a[2] += w * m.x; a[3] += w * m.y;
    m = bf2f(u.z); a[4] += w * m.x; a[5] += w * m.y;
    m = bf2f(u.w); a[6] += w * m.x; a[7] += w * m.y;
}

__device__ __forceinline__ uint4 pack8(const float* v) {
    uint4 o;
    __nv_bfloat162 p;
    p = __floats2bfloat162_rn(v[0], v[1]); o.x = *reinterpret_cast<uint32_t*>(&p);
    p = __floats2bfloat162_rn(v[2], v[3]); o.y = *reinterpret_cast<uint32_t*>(&p);
    p = __floats2bfloat162_rn(v[4], v[5]); o.z = *reinterpret_cast<uint32_t*>(&p);
    p = __floats2bfloat162_rn(v[6], v[7]); o.w = *reinterpret_cast<uint32_t*>(&p);
    return o;
}

// ---------------- degree / CSR build ----------------
__global__ void count_deg_kernel(const int* __restrict__ ei) {
    int e = blockIdx.x * blockDim.x + threadIdx.x;
    if (e < EE) atomicAdd(&d_degi[ei[EE + e]], 1);
}

// multi-block scan, stage 1: per-block local exclusive scan + block total.
// Also computes dis/deginv (elementwise).
__global__ __launch_bounds__(1024) void scan_part_kernel() {
    __shared__ int wsum[32];
    const int b = blockIdx.x, t = threadIdx.x;
    const int i = b * 1024 + t;
    const int lane = t & 31, warp = t >> 5;
    int v = 0;
    if (i < NN) {
        v = d_degi[i];
        float d = (float)v + 1.0f;
        d_dis[i]    = rsqrtf(d);
        d_deginv[i] = 1.0f / d;
    }
    int incl = v;
    #pragma unroll
    for (int o = 1; o < 32; o <<= 1) {
        int u = __shfl_up_sync(0xffffffffu, incl, o);
        if (lane >= o) incl += u;
    }
    if (lane == 31) wsum[warp] = incl;
    __syncthreads();
    if (warp == 0) {
        int s = wsum[lane];
        #pragma unroll
        for (int o = 1; o < 32; o <<= 1) {
            int u = __shfl_up_sync(0xffffffffu, s, o);
            if (lane >= o) s += u;
        }
        wsum[lane] = s;
    }
    __syncthreads();
    int wbase = (warp > 0) ? wsum[warp - 1] : 0;
    if (i < NN) d_csr_ptr[i] = wbase + incl - v;   // local exclusive
    if (t == 1023) d_bsum[b] = wsum[31];           // block total
}

// stage 2: scan the 15 block totals (one warp)
__global__ void scan_tops_kernel() {
    const int t = threadIdx.x;   // 32 threads
    int v = (t < SCANB) ? d_bsum[t] : 0;
    int incl = v;
    #pragma unroll
    for (int o = 1; o < 32; o <<= 1) {
        int u = __shfl_up_sync(0xffffffffu, incl, o);
        if (t >= o) incl += u;
    }
    if (t < SCANB) d_boff[t] = incl - v;
    if (t == SCANB - 1) d_csr_ptr[NN] = incl;
}

// stage 3: add block offsets
__global__ __launch_bounds__(1024) void scan_final_kernel() {
    const int i = blockIdx.x * 1024 + threadIdx.x;
    if (i < NN) {
        int p = d_csr_ptr[i] + d_boff[blockIdx.x];
        d_csr_ptr[i] = p;
        d_cursor[i]  = p;
    }
}

__global__ void fill_csr_kernel(const int* __restrict__ ei) {
    int e = blockIdx.x * blockDim.x + threadIdx.x;
    if (e < EE) {
        int r = ei[e];
        int c = ei[EE + e];
        int pos = atomicAdd(&d_cursor[c], 1);
        d_ew[pos] = make_int2(r, __float_as_int(d_dis[r] * d_dis[c]));
    }
}

// ---------------- prep: fused x->bf16 (uint4 granules) + pe->bf16 ----------
#define XITEMS ((long long)MM * 8)
#define PEITEMS ((long long)NN * GG)
__global__ void convert_kernel(const float* __restrict__ x,
                               const float* __restrict__ pe) {
    long long i = (long long)blockIdx.x * blockDim.x + threadIdx.x;
    if (i < XITEMS) {
        const float4* src = reinterpret_cast<const float4*>(x) + 2 * i;
        float4 v0 = src[0], v1 = src[1];
        float v[8] = {v0.x, v0.y, v0.z, v0.w, v1.x, v1.y, v1.z, v1.w};
        reinterpret_cast<uint4*>(d_xb)[i] = pack8(v);
    } else {
        long long j = i - XITEMS;
        if (j < PEITEMS) d_peb[j] = __float2bfloat16_rn(pe[j]);
    }
}

// fused W1/W2/W3 transpose: grid (HH, 3)
__global__ void transpose_all_kernel(const float* __restrict__ W1,
                                     const float* __restrict__ W2,
                                     const float* __restrict__ W3) {
    const int n = blockIdx.x;
    const int which = blockIdx.y;
    if (which == 0) {
        for (int k = threadIdx.x; k < K1PAD; k += blockDim.x)
            d_wt1[(size_t)n * K1PAD + k] =
                __float2bfloat16_rn((k < KIN) ? W1[(size_t)k * HH + n] : 0.0f);
    } else {
        const float* W = (which == 1) ? W2 : W3;
        __nv_bfloat16* Wt = (which == 1) ? d_wt2 : d_wt3;
        for (int k = threadIdx.x; k < HH; k += blockDim.x)
            Wt[(size_t)n * HH + k] = __float2bfloat16_rn(W[(size_t)k * HH + n]);
    }
}

// ---------------- layer-1 pre-aggregation (A_norm . h before GEMM) ---------
// aggregate x: 2 nodes/block; 64 threads per node = 8 batches x 8 uint4 chunks
__global__ __launch_bounds__(128) void gather_x_kernel() {
    const int t = threadIdx.x;
    const int n = blockIdx.x * 2 + (t >> 6);
    if (n >= NN) return;
    const int b  = (t >> 3) & 7;
    const int fq = t & 7;
    const uint4* xp = reinterpret_cast<const uint4*>(d_xb) + (size_t)b * NN * 8;

    const int p0 = d_csr_ptr[n];
    const int p1 = d_csr_ptr[n + 1];
    float a[8];
    #pragma unroll
    for (int i = 0; i < 8; i++) a[i] = 0.0f;

    #pragma unroll 4
    for (int e = p0; e < p1; e++) {
        int2  ew = __ldg(&d_ew[e]);
        float w  = __int_as_float(ew.y);
        acc8(a, __ldg(xp + (size_t)ew.x * 8 + fq), w);
    }
    acc8(a, __ldg(xp + (size_t)n * 8 + fq), d_deginv[n]);   // self loop

    reinterpret_cast<uint4*>(d_ag1)[((size_t)b * NN + n) * 24 + fq] = pack8(a);
}

// aggregate pe (batch-independent, bf16 source), broadcast into all 8 rows
__global__ __launch_bounds__(128) void gather_pe_kernel() {
    const int n = blockIdx.x;
    const int t = threadIdx.x;
    float a = 0.0f;
    if (t < GG) {
        const int p0 = d_csr_ptr[n];
        const int p1 = d_csr_ptr[n + 1];
        #pragma unroll 4
        for (int e = p0; e < p1; e++) {
            int2  ew = __ldg(&d_ew[e]);
            float w  = __int_as_float(ew.y);
            a += w * __bfloat162float(__ldg(&d_peb[(size_t)ew.x * GG + t]));
        }
        a += d_deginv[n] * __bfloat162float(__ldg(&d_peb[(size_t)n * GG + t]));
    }
    __nv_bfloat16 v = __float2bfloat16_rn(t < GG ? a : 0.0f);
    #pragma unroll
    for (int b = 0; b < BSZ; b++)
        d_ag1[((size_t)b * NN + n) * K1PAD + FF + t] = v;
}

// ================= mma.sync bf16 GEMM (sm_80 baseline PTX) ==================
__device__ __forceinline__ void cp_async16(uint32_t dst, const void* src, int sz) {
    asm volatile("cp.async.cg.shared.global [%0], [%1], 16, %2;"
                 :: "r"(dst), "l"(src), "r"(sz) : "memory");
}

__device__ __forceinline__ void mma_bf16(float* c, const uint32_t* a, const uint32_t* b) {
    asm volatile(
        "mma.sync.aligned.m16n8k16.row.col.f32.bf16.bf16.f32 "
        "{%0,%1,%2,%3}, {%4,%5,%6,%7}, {%8,%9}, {%0,%1,%2,%3};"
        : "+f"(c[0]), "+f"(c[1]), "+f"(c[2]), "+f"(c[3])
        : "r"(a[0]), "r"(a[1]), "r"(a[2]), "r"(a[3]), "r"(b[0]), "r"(b[1]));
}

#define GSTRU 36
#define GBUFU (2 * 128 * GSTRU)
#define GSM_BYTES (2 * GBUFU * 4)

// EPI: fused bias + ELU epilogue (layer 1 writes h1 directly)
template <int KPAD, bool EPI>
__global__ __launch_bounds__(256, 2) void gemm_mma_kernel(
    const __nv_bfloat16* __restrict__ A, const __nv_bfloat16* __restrict__ Wt,
    __nv_bfloat16* __restrict__ hw, const float* __restrict__ bias)
{
    extern __shared__ uint32_t sm[];
    constexpr int NC = KPAD / 64;
    const int t    = threadIdx.x;
    const int lane = t & 31;
    const int wid  = t >> 5;
    const int wm   = wid >> 2;
    const int wn   = wid & 3;
    const int m0   = blockIdx.x * 128;
    const int n0   = blockIdx.y * 128;
    const int g    = lane >> 2;
    const int q    = lane & 3;

    float acc[4][4][4];
    #pragma unroll
    for (int mi = 0; mi < 4; mi++)
        #pragma unroll
        for (int nj = 0; nj < 4; nj++)
            #pragma unroll
            for (int r = 0; r < 4; r++) acc[mi][nj][r] = 0.0f;

    auto load_chunk = [&](int ci, int buf) {
        uint32_t* dA = sm + buf * GBUFU;
        uint32_t* dB = dA + 128 * GSTRU;
        const int k0 = ci * 64;
        #pragma unroll
        for (int r = 0; r < 4; r++) {
            int idx = t + r * 256;
            int row = idx >> 3;
            int seg = idx & 7;
            int m   = m0 + row;
            int valid = (m < MM);
            const __nv_bfloat16* srcA = A + (size_t)(valid ? m : 0) * KPAD + k0 + seg * 8;
            cp_async16((uint32_t)__cvta_generic_to_shared(dA + row * GSTRU + seg * 4),
                       srcA, valid ? 16 : 0);
            const __nv_bfloat16* srcB = Wt + (size_t)(n0 + row) * KPAD + k0 + seg * 8;
            cp_async16((uint32_t)__cvta_generic_to_shared(dB + row * GSTRU + seg * 4),
                       srcB, 16);
        }
        asm volatile("cp.async.commit_group;" ::: "memory");
    };

    load_chunk(0, 0);
    if (NC > 1) load_chunk(1, 1);
    else        asm volatile("cp.async.commit_group;" ::: "memory");

    #pragma unroll 1
    for (int i = 0; i < NC; i++) {
        asm volatile("cp.async.wait_group 1;" ::: "memory");
        __syncthreads();
        const uint32_t* As = sm + (i & 1) * GBUFU;
        const uint32_t* Bs = As + 128 * GSTRU;

        #pragma unroll
        for (int ks = 0; ks < 4; ks++) {
            const int cb = ks * 8 + q;
            uint32_t a[4][4], b[4][2];
            #pragma unroll
            for (int mi = 0; mi < 4; mi++) {
                int r = wm * 64 + mi * 16 + g;
                a[mi][0] = As[r * GSTRU + cb];
                a[mi][1] = As[(r + 8) * GSTRU + cb];
                a[mi][2] = As[r * GSTRU + cb + 4];
                a[mi][3] = As[(r + 8) * GSTRU + cb + 4];
            }
            #pragma unroll
            for (int nj = 0; nj < 4; nj++) {
                int n = wn * 32 + nj * 8 + g;
                b[nj][0] = Bs[n * GSTRU + cb];
                b[nj][1] = Bs[n * GSTRU + cb + 4];
            }
            #pragma unroll
            for (int mi = 0; mi < 4; mi++)
                #pragma unroll
                for (int nj = 0; nj < 4; nj++)
                    mma_bf16(acc[mi][nj], a[mi], b[nj]);
        }
        __syncthreads();
        if (i + 2 < NC) load_chunk(i + 2, i & 1);
        else            asm volatile("cp.async.commit_group;" ::: "memory");
    }

    __nv_bfloat162* hw2 = reinterpret_cast<__nv_bfloat162*>(hw);
    #pragma unroll
    for (int mi = 0; mi < 4; mi++) {
        int r = m0 + wm * 64 + mi * 16 + g;
        #pragma unroll
        for (int nj = 0; nj < 4; nj++) {
            int c  = n0 + wn * 32 + nj * 8 + q * 2;
            float v0 = acc[mi][nj][0], v1 = acc[mi][nj][1];
            float v2 = acc[mi][nj][2], v3 = acc[mi][nj][3];
            if (EPI) {
                float2 bv = *reinterpret_cast<const float2*>(bias + c);
                v0 = eluf(v0 + bv.x); v1 = eluf(v1 + bv.y);
                v2 = eluf(v2 + bv.x); v3 = eluf(v3 + bv.y);
            }
            int c2 = c >> 1;
            if (r < MM)
                hw2[(size_t)r * 128 + c2] = __floats2bfloat162_rn(v0, v1);
            if (r + 8 < MM)
                hw2[(size_t)(r + 8) * 128 + c2] = __floats2bfloat162_rn(v2, v3);
        }
    }
}

// ---------------- CSR gather (layers 2/3): LDG.128, 1 block/node ------------
template <bool FUSE_FC>
__global__ __launch_bounds__(128) void gather_kernel(
    const uint4* __restrict__ hw4, const float* __restrict__ bias,
    uint4* __restrict__ hout4,
    const float* __restrict__ fcW, const float* __restrict__ fcb)
{
    const int n  = blockIdx.x;
    const int t  = threadIdx.x;
    const int fq = t & 31;
    const int bp = t >> 5;
    const int b0 = 2 * bp, b1 = 2 * bp + 1;
    const size_t plane = (size_t)NN * 32;
    const uint4* hp0 = hw4 + (size_t)b0 * plane;
    const uint4* hp1 = hw4 + (size_t)b1 * plane;

    __shared__ float sfw[FUSE_FC ? 768 : 1];
    if (FUSE_FC) {
        #pragma unroll
        for (int i = t; i < 768; i += 128) sfw[i] = fcW[i];
        __syncthreads();
    }

    const int p0 = d_csr_ptr[n];
    const int p1 = d_csr_ptr[n + 1];

    float a0[8], a1v[8];
    #pragma unroll
    for (int i = 0; i < 8; i++) { a0[i] = 0.0f; a1v[i] = 0.0f; }

    #pragma unroll 4
    for (int e = p0; e < p1; e++) {
        int2  ew = __ldg(&d_ew[e]);
        float w  = __int_as_float(ew.y);
        size_t ro = (size_t)ew.x * 32 + fq;
        uint4 u0 = __ldg(hp0 + ro);
        uint4 u1 = __ldg(hp1 + ro);
        acc8(a0,  u0, w);
        acc8(a1v, u1, w);
    }

    const float di = d_deginv[n];
    const float4 bsa = reinterpret_cast<const float4*>(bias)[2 * fq];
    const float4 bsb = reinterpret_cast<const float4*>(bias)[2 * fq + 1];
    const float bs[8] = {bsa.x, bsa.y, bsa.z, bsa.w, bsb.x, bsb.y, bsb.z, bsb.w};

    size_t so = (size_t)n * 32 + fq;
    acc8(a0,  __ldg(hp0 + so), di);
    acc8(a1v, __ldg(hp1 + so), di);

    float v0[8], v1[8];
    #pragma unroll
    for (int i = 0; i < 8; i++) {
        v0[i] = eluf(a0[i]  + bs[i]);
        v1[i] = eluf(a1v[i] + bs[i]);
    }

    if (!FUSE_FC) {
        hout4[(size_t)b0 * plane + so] = pack8(v0);
        hout4[(size_t)b1 * plane + so] = pack8(v1);
    } else {
        const uint4* h1p0 = reinterpret_cast<const uint4*>(d_h1) + (size_t)b0 * plane;
        const uint4* h1p1 = reinterpret_cast<const uint4*>(d_h1) + (size_t)b1 * plane;
        const uint4* h2p0 = reinterpret_cast<const uint4*>(d_h2) + (size_t)b0 * plane;
        const uint4* h2p1 = reinterpret_cast<const uint4*>(d_h2) + (size_t)b1 * plane;
        float h10[8], h11[8], h20[8], h21[8];
        #pragma unroll
        for (int i = 0; i < 8; i++) { h10[i]=h11[i]=h20[i]=h21[i]=0.0f; }
        acc8(h10, __ldg(h1p0 + so), 1.0f); acc8(h11, __ldg(h1p1 + so), 1.0f);
        acc8(h20, __ldg(h2p0 + so), 1.0f); acc8(h21, __ldg(h2p1 + so), 1.0f);
        float g0 = 0.0f, g1 = 0.0f;
        #pragma unroll
        for (int i = 0; i < 8; i++) {
            const float* fw = &sfw[24 * fq + 3 * i];
            g0 += h10[i] * fw[0] + h20[i] * fw[1] + v0[i] * fw[2];
            g1 += h11[i] * fw[0] + h21[i] * fw[1] + v1[i] * fw[2];
        }
        #pragma unroll
        for (int o = 16; o > 0; o >>= 1) {
            g0 += __shfl_down_sync(0xffffffffu, g0, o);
            g1 += __shfl_down_sync(0xffffffffu, g1, o);
        }
        if (fq == 0) {
            float fb = fcb[0];
            d_g[(size_t)b0 * NN + n] = g0 + fb;
            d_g[(size_t)b1 * NN + n] = g1 + fb;
        }
    }
}

// ---------------- lin1: g[b,N] @ lin1_W[N,512] (accumulate) ----------------
#define NCH 256
__global__ __launch_bounds__(128) void lin1_kernel(const float* __restrict__ W)
{
    __shared__ float gs[BSZ][NCH];
    const int j  = blockIdx.x * 128 + threadIdx.x;
    const int n0 = blockIdx.y * NCH;
    const int cn = min(NCH, NN - n0);
    for (int idx = threadIdx.x; idx < BSZ * NCH; idx += 128) {
        int b  = idx >> 8;
        int nl = idx & (NCH - 1);
        gs[b][nl] = (nl < cn) ? d_g[(size_t)b * NN + n0 + nl] : 0.0f;
    }
    __syncthreads();
    float acc[BSZ];
    #pragma unroll
    for (int b = 0; b < BSZ; b++) acc[b] = 0.0f;
    for (int nl = 0; nl < cn; nl++) {
        float w = W[(size_t)(n0 + nl) * HFCC + j];
        #pragma unroll
        for (int b = 0; b < BSZ; b++) acc[b] += gs[b][nl] * w;
    }
    #pragma unroll
    for (int b = 0; b < BSZ; b++) atomicAdd(&d_zacc[b * HFCC + j], acc[b]);
}

// ---------------- lin2 + log_softmax ----------------
__global__ __launch_bounds__(256) void lin2_kernel(
    const float* __restrict__ lin1b, const float* __restrict__ lin2W,
    const float* __restrict__ lin2b, float* __restrict__ out)
{
    const int b = blockIdx.x;
    const int t = threadIdx.x;
    float s0 = 0.0f, s1 = 0.0f;
    for (int j = t; j < HFCC; j += 256) {
        float z = d_zacc[b * HFCC + j] + lin1b[j];
        z = eluf(z);
        s0 += z * lin2W[j * 2 + 0];
        s1 += z * lin2W[j * 2 + 1];
    }
    __shared__ float r0[256], r1[256];
    r0[t] = s0; r1[t] = s1;
    __syncthreads();
    for (int o = 128; o > 0; o >>= 1) {
        if (t < o) { r0[t] += r0[t + o]; r1[t] += r1[t + o]; }
        __syncthreads();
    }
    if (t == 0) {
        float o0 = r0[0] + lin2b[0];
        float o1 = r1[0] + lin2b[1];
        float mx = fmaxf(o0, o1);
        float lse = mx + logf(expf(o0 - mx) + expf(o1 - mx));
        out[b * CCLS + 0] = o0 - lse;
        out[b * CCLS + 1] = o1 - lse;
    }
}

// ---------------- launcher ----------------
extern "C" void kernel_launch(void* const* d_in, const int* in_sizes, int n_in,
                              void* d_out, int out_size)
{
    const float* x     = (const float*)d_in[0];
    const int*   ei    = (const int*)d_in[2];   // int32 [2, E]
    const float* pe    = (const float*)d_in[3];
    const float* W1    = (const float*)d_in[4];
    const float* b1    = (const float*)d_in[5];
    const float* W2    = (const float*)d_in[6];
    const float* b2    = (const float*)d_in[7];
    const float* W3    = (const float*)d_in[8];
    const float* b3    = (const float*)d_in[9];
    const float* fcW   = (const float*)d_in[10];
    const float* fcb   = (const float*)d_in[11];
    const float* lin1W = (const float*)d_in[12];
    const float* lin1b = (const float*)d_in[13];
    const float* lin2W = (const float*)d_in[14];
    const float* lin2b = (const float*)d_in[15];
    float* out = (float*)d_out;

    __nv_bfloat16 *hwp, *h1p, *h2p, *ag1p, *wt1p, *wt2p, *wt3p;
    cudaGetSymbolAddress((void**)&hwp,  d_hw);
    cudaGetSymbolAddress((void**)&h1p,  d_h1);
    cudaGetSymbolAddress((void**)&h2p,  d_h2);
    cudaGetSymbolAddress((void**)&ag1p, d_ag1);
    cudaGetSymbolAddress((void**)&wt1p, d_wt1);
    cudaGetSymbolAddress((void**)&wt2p, d_wt2);
    cudaGetSymbolAddress((void**)&wt3p, d_wt3);
    int* degip; float* zaccp;
    cudaGetSymbolAddress((void**)&degip, d_degi);
    cudaGetSymbolAddress((void**)&zaccp, d_zacc);

    cudaFuncSetAttribute((void*)gemm_mma_kernel<K1PAD, true>,
                         cudaFuncAttributeMaxDynamicSharedMemorySize, GSM_BYTES);
    cudaFuncSetAttribute((void*)gemm_mma_kernel<HH, false>,
                         cudaFuncAttributeMaxDynamicSharedMemorySize, GSM_BYTES);

    // degrees + CSR (multi-block scan)
    cudaMemsetAsync(degip, 0, NN * sizeof(int));
    count_deg_kernel<<<(EE + 255) / 256, 256>>>(ei);
    scan_part_kernel<<<SCANB, 1024>>>();
    scan_tops_kernel<<<1, 32>>>();
    scan_final_kernel<<<SCANB, 1024>>>();
    fill_csr_kernel<<<(EE + 255) / 256, 256>>>(ei);

    // prep: fused converts + fused transposes
    {
        long long tot = XITEMS + PEITEMS;
        convert_kernel<<<(unsigned)((tot + 255) / 256), 256>>>(x, pe);
        transpose_all_kernel<<<dim3(HH, 3), 256>>>(W1, W2, W3);
    }

    // layer 1: pre-aggregate input, then GEMM with fused bias+ELU -> h1
    gather_x_kernel<<<(NN + 1) / 2, 128>>>();
    gather_pe_kernel<<<NN, 128>>>();

    const dim3 ggrid((MM + 127) / 128, HH / 128);
    const uint4* hw4 = reinterpret_cast<const uint4*>(hwp);
    uint4* h24 = reinterpret_cast<uint4*>(h2p);

    gemm_mma_kernel<K1PAD, true><<<ggrid, 256, GSM_BYTES>>>(ag1p, wt1p, h1p, b1);

    // layer 2
    gemm_mma_kernel<HH, false><<<ggrid, 256, GSM_BYTES>>>(h1p, wt2p, hwp, nullptr);
    gather_kernel<false><<<NN, 128>>>(hw4, b2, h24, nullptr, nullptr);

    // layer 3 (+ fused fc head -> d_g)
    gemm_mma_kernel<HH, false><<<ggrid, 256, GSM_BYTES>>>(h2p, wt3p, hwp, nullptr);
    gather_kernel<true><<<NN, 128>>>(hw4, b3, nullptr, fcW, fcb);

    // heads
    cudaMemsetAsync(zaccp, 0, BSZ * HFCC * sizeof(float));
    lin1_kernel<<<dim3(HFCC / 128, (NN + NCH - 1) / NCH), 128>>>(lin1W);
    lin2_kernel<<<BSZ, 256>>>(lin1b, lin2W, lin2b, out);
}

// round 11
// speedup vs baseline: 6.0408x; 1.0229x over previous
#include <cuda_runtime.h>
#include <cuda_bf16.h>
#include <math.h>
#include <cstdint>

// Problem constants
#define BSZ 8
#define NN  15135
#define FF  64
#define GG  73
#define HH  256
#define HFCC 512
#define CCLS 2
#define EE  242160
#define KIN (FF + GG)        // 137
#define MM  (BSZ * NN)       // 121080
#define K1PAD 192            // layer-1 K padded to multiple of 64
#define SCANB 15             // ceil(NN/1024)

// ---------------- scratch (device globals; no dynamic alloc allowed) -------
__device__ int   d_degi[NN];
__device__ float d_dis[NN];
__device__ float d_deginv[NN];
__device__ int   d_csr_ptr[NN + 1];
__device__ int   d_cursor[NN];
__device__ int2  d_ew[EE];            // packed (src, weight-bits)
__device__ int   d_bsum[16];
__device__ __align__(16) __nv_bfloat16 d_hw[(size_t)MM * HH];
__device__ __align__(16) __nv_bfloat16 d_h1[(size_t)MM * HH];
__device__ __align__(16) __nv_bfloat16 d_h2[(size_t)MM * HH];
__device__ __align__(16) __nv_bfloat16 d_ag1[(size_t)MM * K1PAD];  // aggregated concat input
__device__ __align__(16) __nv_bfloat16 d_xb[(size_t)MM * FF];      // x in bf16
__device__ __align__(16) __nv_bfloat16 d_peb[(size_t)NN * GG];     // pe in bf16
__device__ __align__(16) __nv_bfloat16 d_wt1[HH * K1PAD];   // W1^T padded
__device__ __align__(16) __nv_bfloat16 d_wt2[HH * HH];      // W2^T
__device__ __align__(16) __nv_bfloat16 d_wt3[HH * HH];      // W3^T
__device__ float d_g[MM];
__device__ float d_zacc[BSZ * HFCC];

__device__ __forceinline__ float eluf(float v) {
    return v > 0.0f ? v : expm1f(v);
}

__device__ __forceinline__ float2 bf2f(uint32_t u) {
    __nv_bfloat162 m = *reinterpret_cast<__nv_bfloat162*>(&u);
    return make_float2(__bfloat162float(m.x), __bfloat162float(m.y));
}

// accumulate 8 bf16 lanes of u into a[0..7] with weight w
__device__ __forceinline__ void acc8(float* a, uint4 u, float w) {
    float2 m;
    m = bf2f(u.x); a[0] += w * m.x; a[1] += w * m.y;
    m = bf2f(u.y); a[2] += w * m.x; a[3] += w * m.y;
    m = bf2f(u.z); a[4] += w * m.x; a[5] += w * m.y;
    m = bf2f(u.w); a[6] += w * m.x; a[7] += w * m.y;
}

__device__ __forceinline__ uint4 pack8(const float* v) {
    uint4 o;
    __nv_bfloat162 p;
    p = __floats2bfloat162_rn(v[0], v[1]); o.x = *reinterpret_cast<uint32_t*>(&p);
    p = __floats2bfloat162_rn(v[2], v[3]); o.y = *reinterpret_cast<uint32_t*>(&p);
    p = __floats2bfloat162_rn(v[4], v[5]); o.z = *reinterpret_cast<uint32_t*>(&p);
    p = __floats2bfloat162_rn(v[6], v[7]); o.w = *reinterpret_cast<uint32_t*>(&p);
    return o;
}

// ---------------- fused prep: degree count + converts + transposes ---------
#define XITEMS ((long long)MM * 8)
#define PEITEMS ((long long)NN * GG)
#define NB_DEG  ((EE + 255) / 256)                              // 946
#define NB_CONV ((int)((XITEMS + PEITEMS + 255) / 256))         // ~8100
#define NB_TR   (HH * 3)                                        // 768
#define NB_PREP (NB_DEG + NB_CONV + NB_TR)

__global__ __launch_bounds__(256) void prep_all_kernel(
    const int* __restrict__ ei,
    const float* __restrict__ x, const float* __restrict__ pe,
    const float* __restrict__ W1, const float* __restrict__ W2,
    const float* __restrict__ W3)
{
    const int bid = blockIdx.x;
    const int t   = threadIdx.x;
    if (bid < NB_DEG) {
        int e = bid * 256 + t;
        if (e < EE) atomicAdd(&d_degi[ei[EE + e]], 1);
    } else if (bid < NB_DEG + NB_CONV) {
        long long i = (long long)(bid - NB_DEG) * 256 + t;
        if (i < XITEMS) {
            const float4* src = reinterpret_cast<const float4*>(x) + 2 * i;
            float4 v0 = src[0], v1 = src[1];
            float v[8] = {v0.x, v0.y, v0.z, v0.w, v1.x, v1.y, v1.z, v1.w};
            reinterpret_cast<uint4*>(d_xb)[i] = pack8(v);
        } else {
            long long j = i - XITEMS;
            if (j < PEITEMS) d_peb[j] = __float2bfloat16_rn(pe[j]);
        }
    } else {
        int j = bid - NB_DEG - NB_CONV;     // 0..767
        int n = j & 255;
        int which = j >> 8;
        if (which == 0) {
            if (t < K1PAD)
                d_wt1[(size_t)n * K1PAD + t] =
                    __float2bfloat16_rn((t < KIN) ? W1[(size_t)t * HH + n] : 0.0f);
        } else {
            const float* W = (which == 1) ? W2 : W3;
            __nv_bfloat16* Wt = (which == 1) ? d_wt2 : d_wt3;
            Wt[(size_t)n * HH + t] = __float2bfloat16_rn(W[(size_t)t * HH + n]);
        }
    }
}

// ---------------- CSR scan ----------------
// stage 1: per-block local exclusive scan + block total + dis/deginv
__global__ __launch_bounds__(1024) void scan_part_kernel() {
    __shared__ int wsum[32];
    const int b = blockIdx.x, t = threadIdx.x;
    const int i = b * 1024 + t;
    const int lane = t & 31, warp = t >> 5;
    int v = 0;
    if (i < NN) {
        v = d_degi[i];
        float d = (float)v + 1.0f;
        d_dis[i]    = rsqrtf(d);
        d_deginv[i] = 1.0f / d;
    }
    int incl = v;
    #pragma unroll
    for (int o = 1; o < 32; o <<= 1) {
        int u = __shfl_up_sync(0xffffffffu, incl, o);
        if (lane >= o) incl += u;
    }
    if (lane == 31) wsum[warp] = incl;
    __syncthreads();
    if (warp == 0) {
        int s = wsum[lane];
        #pragma unroll
        for (int o = 1; o < 32; o <<= 1) {
            int u = __shfl_up_sync(0xffffffffu, s, o);
            if (lane >= o) s += u;
        }
        wsum[lane] = s;
    }
    __syncthreads();
    int wbase = (warp > 0) ? wsum[warp - 1] : 0;
    if (i < NN) d_csr_ptr[i] = wbase + incl - v;   // local exclusive
    if (t == 1023) d_bsum[b] = wsum[31];           // block total
}

// stage 2 (fused): each block re-scans the 15 block sums, adds its offset
__global__ __launch_bounds__(1024) void scan_final_kernel() {
    __shared__ int soff_sh;
    const int t = threadIdx.x;
    if (t < 32) {
        int v = (t < SCANB) ? d_bsum[t] : 0;
        int incl = v;
        #pragma unroll
        for (int o = 1; o < 32; o <<= 1) {
            int u = __shfl_up_sync(0xffffffffu, incl, o);
            if (t >= o) incl += u;
        }
        if (t == (int)blockIdx.x) soff_sh = incl - v;
        if (blockIdx.x == 0 && t == SCANB - 1) d_csr_ptr[NN] = incl;
    }
    __syncthreads();
    const int i = blockIdx.x * 1024 + t;
    if (i < NN) {
        int p = d_csr_ptr[i] + soff_sh;
        d_csr_ptr[i] = p;
        d_cursor[i]  = p;
    }
}

__global__ void fill_csr_kernel(const int* __restrict__ ei) {
    int e = blockIdx.x * blockDim.x + threadIdx.x;
    if (e < EE) {
        int r = ei[e];
        int c = ei[EE + e];
        int pos = atomicAdd(&d_cursor[c], 1);
        d_ew[pos] = make_int2(r, __float_as_int(d_dis[r] * d_dis[c]));
    }
}

// ---------------- layer-1 pre-aggregation (fused x + pe) -------------------
// blocks [0, GXB): x-aggregate, 2 nodes/block, 64 thr/node (8 batch x 8 chunk)
// blocks [GXB, GXB+NN): pe-aggregate (batch-independent), broadcast to 8 rows
#define GXB ((NN + 1) / 2)
__global__ __launch_bounds__(128) void gather_l1_kernel() {
    const int t = threadIdx.x;
    if (blockIdx.x < GXB) {
        const int n = blockIdx.x * 2 + (t >> 6);
        if (n >= NN) return;
        const int b  = (t >> 3) & 7;
        const int fq = t & 7;
        const uint4* xp = reinterpret_cast<const uint4*>(d_xb) + (size_t)b * NN * 8;

        const int p0 = d_csr_ptr[n];
        const int p1 = d_csr_ptr[n + 1];
        float a[8];
        #pragma unroll
        for (int i = 0; i < 8; i++) a[i] = 0.0f;

        #pragma unroll 4
        for (int e = p0; e < p1; e++) {
            int2  ew = __ldg(&d_ew[e]);
            float w  = __int_as_float(ew.y);
            acc8(a, __ldg(xp + (size_t)ew.x * 8 + fq), w);
        }
        acc8(a, __ldg(xp + (size_t)n * 8 + fq), d_deginv[n]);   // self loop

        reinterpret_cast<uint4*>(d_ag1)[((size_t)b * NN + n) * 24 + fq] = pack8(a);
    } else {
        const int n = blockIdx.x - GXB;
        float a = 0.0f;
        if (t < GG) {
            const int p0 = d_csr_ptr[n];
            const int p1 = d_csr_ptr[n + 1];
            #pragma unroll 4
            for (int e = p0; e < p1; e++) {
                int2  ew = __ldg(&d_ew[e]);
                float w  = __int_as_float(ew.y);
                a += w * __bfloat162float(__ldg(&d_peb[(size_t)ew.x * GG + t]));
            }
            a += d_deginv[n] * __bfloat162float(__ldg(&d_peb[(size_t)n * GG + t]));
        }
        __nv_bfloat16 v = __float2bfloat16_rn(t < GG ? a : 0.0f);
        #pragma unroll
        for (int b = 0; b < BSZ; b++)
            d_ag1[((size_t)b * NN + n) * K1PAD + FF + t] = v;
    }
}

// ================= mma.sync bf16 GEMM (sm_80 baseline PTX) ==================
__device__ __forceinline__ void cp_async16(uint32_t dst, const void* src, int sz) {
    asm volatile("cp.async.cg.shared.global [%0], [%1], 16, %2;"
                 :: "r"(dst), "l"(src), "r"(sz) : "memory");
}

__device__ __forceinline__ void mma_bf16(float* c, const uint32_t* a, const uint32_t* b) {
    asm volatile(
        "mma.sync.aligned.m16n8k16.row.col.f32.bf16.bf16.f32 "
        "{%0,%1,%2,%3}, {%4,%5,%6,%7}, {%8,%9}, {%0,%1,%2,%3};"
        : "+f"(c[0]), "+f"(c[1]), "+f"(c[2]), "+f"(c[3])
        : "r"(a[0]), "r"(a[1]), "r"(a[2]), "r"(a[3]), "r"(b[0]), "r"(b[1]));
}

#define GSTRU 36
#define GBUFU (2 * 128 * GSTRU)
#define GSM_BYTES (2 * GBUFU * 4)

// EPI: fused bias + ELU epilogue (layer 1 writes h1 directly)
template <int KPAD, bool EPI>
__global__ __launch_bounds__(256, 2) void gemm_mma_kernel(
    const __nv_bfloat16* __restrict__ A, const __nv_bfloat16* __restrict__ Wt,
    __nv_bfloat16* __restrict__ hw, const float* __restrict__ bias)
{
    extern __shared__ uint32_t sm[];
    constexpr int NC = KPAD / 64;
    const int t    = threadIdx.x;
    const int lane = t & 31;
    const int wid  = t >> 5;
    const int wm   = wid >> 2;
    const int wn   = wid & 3;
    const int m0   = blockIdx.x * 128;
    const int n0   = blockIdx.y * 128;
    const int g    = lane >> 2;
    const int q    = lane & 3;

    float acc[4][4][4];
    #pragma unroll
    for (int mi = 0; mi < 4; mi++)
        #pragma unroll
        for (int nj = 0; nj < 4; nj++)
            #pragma unroll
            for (int r = 0; r < 4; r++) acc[mi][nj][r] = 0.0f;

    auto load_chunk = [&](int ci, int buf) {
        uint32_t* dA = sm + buf * GBUFU;
        uint32_t* dB = dA + 128 * GSTRU;
        const int k0 = ci * 64;
        #pragma unroll
        for (int r = 0; r < 4; r++) {
            int idx = t + r * 256;
            int row = idx >> 3;
            int seg = idx & 7;
            int m   = m0 + row;
            int valid = (m < MM);
            const __nv_bfloat16* srcA = A + (size_t)(valid ? m : 0) * KPAD + k0 + seg * 8;
            cp_async16((uint32_t)__cvta_generic_to_shared(dA + row * GSTRU + seg * 4),
                       srcA, valid ? 16 : 0);
            const __nv_bfloat16* srcB = Wt + (size_t)(n0 + row) * KPAD + k0 + seg * 8;
            cp_async16((uint32_t)__cvta_generic_to_shared(dB + row * GSTRU + seg * 4),
                       srcB, 16);
        }
        asm volatile("cp.async.commit_group;" ::: "memory");
    };

    load_chunk(0, 0);
    if (NC > 1) load_chunk(1, 1);
    else        asm volatile("cp.async.commit_group;" ::: "memory");

    #pragma unroll 1
    for (int i = 0; i < NC; i++) {
        asm volatile("cp.async.wait_group 1;" ::: "memory");
        __syncthreads();
        const uint32_t* As = sm + (i & 1) * GBUFU;
        const uint32_t* Bs = As + 128 * GSTRU;

        #pragma unroll
        for (int ks = 0; ks < 4; ks++) {
            const int cb = ks * 8 + q;
            uint32_t a[4][4], b[4][2];
            #pragma unroll
            for (int mi = 0; mi < 4; mi++) {
                int r = wm * 64 + mi * 16 + g;
                a[mi][0] = As[r * GSTRU + cb];
                a[mi][1] = As[(r + 8) * GSTRU + cb];
                a[mi][2] = As[r * GSTRU + cb + 4];
                a[mi][3] = As[(r + 8) * GSTRU + cb + 4];
            }
            #pragma unroll
            for (int nj = 0; nj < 4; nj++) {
                int n = wn * 32 + nj * 8 + g;
                b[nj][0] = Bs[n * GSTRU + cb];
                b[nj][1] = Bs[n * GSTRU + cb + 4];
            }
            #pragma unroll
            for (int mi = 0; mi < 4; mi++)
                #pragma unroll
                for (int nj = 0; nj < 4; nj++)
                    mma_bf16(acc[mi][nj], a[mi], b[nj]);
        }
        __syncthreads();
        if (i + 2 < NC) load_chunk(i + 2, i & 1);
        else            asm volatile("cp.async.commit_group;" ::: "memory");
    }

    __nv_bfloat162* hw2 = reinterpret_cast<__nv_bfloat162*>(hw);
    #pragma unroll
    for (int mi = 0; mi < 4; mi++) {
        int r = m0 + wm * 64 + mi * 16 + g;
        #pragma unroll
        for (int nj = 0; nj < 4; nj++) {
            int c  = n0 + wn * 32 + nj * 8 + q * 2;
            float v0 = acc[mi][nj][0], v1 = acc[mi][nj][1];
            float v2 = acc[mi][nj][2], v3 = acc[mi][nj][3];
            if (EPI) {
                float2 bv = *reinterpret_cast<const float2*>(bias + c);
                v0 = eluf(v0 + bv.x); v1 = eluf(v1 + bv.y);
                v2 = eluf(v2 + bv.x); v3 = eluf(v3 + bv.y);
            }
            int c2 = c >> 1;
            if (r < MM)
                hw2[(size_t)r * 128 + c2] = __floats2bfloat162_rn(v0, v1);
            if (r + 8 < MM)
                hw2[(size_t)(r + 8) * 128 + c2] = __floats2bfloat162_rn(v2, v3);
        }
    }
}

// ---------------- CSR gather (layers 2/3): LDG.128, 1 block/node ------------
template <bool FUSE_FC>
__global__ __launch_bounds__(128) void gather_kernel(
    const uint4* __restrict__ hw4, const float* __restrict__ bias,
    uint4* __restrict__ hout4,
    const float* __restrict__ fcW, const float* __restrict__ fcb)
{
    const int n  = blockIdx.x;
    const int t  = threadIdx.x;
    const int fq = t & 31;
    const int bp = t >> 5;
    const int b0 = 2 * bp, b1 = 2 * bp + 1;
    const size_t plane = (size_t)NN * 32;
    const uint4* hp0 = hw4 + (size_t)b0 * plane;
    const uint4* hp1 = hw4 + (size_t)b1 * plane;

    __shared__ float sfw[FUSE_FC ? 768 : 1];
    if (FUSE_FC) {
        #pragma unroll
        for (int i = t; i < 768; i += 128) sfw[i] = fcW[i];
        __syncthreads();
    }

    const int p0 = d_csr_ptr[n];
    const int p1 = d_csr_ptr[n + 1];

    float a0[8], a1v[8];
    #pragma unroll
    for (int i = 0; i < 8; i++) { a0[i] = 0.0f; a1v[i] = 0.0f; }

    #pragma unroll 4
    for (int e = p0; e < p1; e++) {
        int2  ew = __ldg(&d_ew[e]);
        float w  = __int_as_float(ew.y);
        size_t ro = (size_t)ew.x * 32 + fq;
        uint4 u0 = __ldg(hp0 + ro);
        uint4 u1 = __ldg(hp1 + ro);
        acc8(a0,  u0, w);
        acc8(a1v, u1, w);
    }

    const float di = d_deginv[n];
    const float4 bsa = reinterpret_cast<const float4*>(bias)[2 * fq];
    const float4 bsb = reinterpret_cast<const float4*>(bias)[2 * fq + 1];
    const float bs[8] = {bsa.x, bsa.y, bsa.z, bsa.w, bsb.x, bsb.y, bsb.z, bsb.w};

    size_t so = (size_t)n * 32 + fq;
    acc8(a0,  __ldg(hp0 + so), di);
    acc8(a1v, __ldg(hp1 + so), di);

    float v0[8], v1[8];
    #pragma unroll
    for (int i = 0; i < 8; i++) {
        v0[i] = eluf(a0[i]  + bs[i]);
        v1[i] = eluf(a1v[i] + bs[i]);
    }

    if (!FUSE_FC) {
        hout4[(size_t)b0 * plane + so] = pack8(v0);
        hout4[(size_t)b1 * plane + so] = pack8(v1);
    } else {
        const uint4* h1p0 = reinterpret_cast<const uint4*>(d_h1) + (size_t)b0 * plane;
        const uint4* h1p1 = reinterpret_cast<const uint4*>(d_h1) + (size_t)b1 * plane;
        const uint4* h2p0 = reinterpret_cast<const uint4*>(d_h2) + (size_t)b0 * plane;
        const uint4* h2p1 = reinterpret_cast<const uint4*>(d_h2) + (size_t)b1 * plane;
        float h10[8], h11[8], h20[8], h21[8];
        #pragma unroll
        for (int i = 0; i < 8; i++) { h10[i]=h11[i]=h20[i]=h21[i]=0.0f; }
        acc8(h10, __ldg(h1p0 + so), 1.0f); acc8(h11, __ldg(h1p1 + so), 1.0f);
        acc8(h20, __ldg(h2p0 + so), 1.0f); acc8(h21, __ldg(h2p1 + so), 1.0f);
        float g0 = 0.0f, g1 = 0.0f;
        #pragma unroll
        for (int i = 0; i < 8; i++) {
            const float* fw = &sfw[24 * fq + 3 * i];
            g0 += h10[i] * fw[0] + h20[i] * fw[1] + v0[i] * fw[2];
            g1 += h11[i] * fw[0] + h21[i] * fw[1] + v1[i] * fw[2];
        }
        #pragma unroll
        for (int o = 16; o > 0; o >>= 1) {
            g0 += __shfl_down_sync(0xffffffffu, g0, o);
            g1 += __shfl_down_sync(0xffffffffu, g1, o);
        }
        if (fq == 0) {
            float fb = fcb[0];
            d_g[(size_t)b0 * NN + n] = g0 + fb;
            d_g[(size_t)b1 * NN + n] = g1 + fb;
        }
    }
}

// ---------------- lin1: g[b,N] @ lin1_W[N,512] (accumulate) ----------------
#define NCH 256
__global__ __launch_bounds__(128) void lin1_kernel(const float* __restrict__ W)
{
    __shared__ float gs[BSZ][NCH];
    const int j  = blockIdx.x * 128 + threadIdx.x;
    const int n0 = blockIdx.y * NCH;
    const int cn = min(NCH, NN - n0);
    for (int idx = threadIdx.x; idx < BSZ * NCH; idx += 128) {
        int b  = idx >> 8;
        int nl = idx & (NCH - 1);
        gs[b][nl] = (nl < cn) ? d_g[(size_t)b * NN + n0 + nl] : 0.0f;
    }
    __syncthreads();
    float acc[BSZ];
    #pragma unroll
    for (int b = 0; b < BSZ; b++) acc[b] = 0.0f;
    for (int nl = 0; nl < cn; nl++) {
        float w = W[(size_t)(n0 + nl) * HFCC + j];
        #pragma unroll
        for (int b = 0; b < BSZ; b++) acc[b] += gs[b][nl] * w;
    }
    #pragma unroll
    for (int b = 0; b < BSZ; b++) atomicAdd(&d_zacc[b * HFCC + j], acc[b]);
}

// ---------------- lin2 + log_softmax ----------------
__global__ __launch_bounds__(256) void lin2_kernel(
    const float* __restrict__ lin1b, const float* __restrict__ lin2W,
    const float* __restrict__ lin2b, float* __restrict__ out)
{
    const int b = blockIdx.x;
    const int t = threadIdx.x;
    float s0 = 0.0f, s1 = 0.0f;
    for (int j = t; j < HFCC; j += 256) {
        float z = d_zacc[b * HFCC + j] + lin1b[j];
        z = eluf(z);
        s0 += z * lin2W[j * 2 + 0];
        s1 += z * lin2W[j * 2 + 1];
    }
    __shared__ float r0[256], r1[256];
    r0[t] = s0; r1[t] = s1;
    __syncthreads();
    for (int o = 128; o > 0; o >>= 1) {
        if (t < o) { r0[t] += r0[t + o]; r1[t] += r1[t + o]; }
        __syncthreads();
    }
    if (t == 0) {
        float o0 = r0[0] + lin2b[0];
        float o1 = r1[0] + lin2b[1];
        float mx = fmaxf(o0, o1);
        float lse = mx + logf(expf(o0 - mx) + expf(o1 - mx));
        out[b * CCLS + 0] = o0 - lse;
        out[b * CCLS + 1] = o1 - lse;
    }
}

// ---------------- launcher ----------------
extern "C" void kernel_launch(void* const* d_in, const int* in_sizes, int n_in,
                              void* d_out, int out_size)
{
    const float* x     = (const float*)d_in[0];
    const int*   ei    = (const int*)d_in[2];   // int32 [2, E]
    const float* pe    = (const float*)d_in[3];
    const float* W1    = (const float*)d_in[4];
    const float* b1    = (const float*)d_in[5];
    const float* W2    = (const float*)d_in[6];
    const float* b2    = (const float*)d_in[7];
    const float* W3    = (const float*)d_in[8];
    const float* b3    = (const float*)d_in[9];
    const float* fcW   = (const float*)d_in[10];
    const float* fcb   = (const float*)d_in[11];
    const float* lin1W = (const float*)d_in[12];
    const float* lin1b = (const float*)d_in[13];
    const float* lin2W = (const float*)d_in[14];
    const float* lin2b = (const float*)d_in[15];
    float* out = (float*)d_out;

    __nv_bfloat16 *hwp, *h1p, *h2p, *ag1p, *wt1p, *wt2p, *wt3p;
    cudaGetSymbolAddress((void**)&hwp,  d_hw);
    cudaGetSymbolAddress((void**)&h1p,  d_h1);
    cudaGetSymbolAddress((void**)&h2p,  d_h2);
    cudaGetSymbolAddress((void**)&ag1p, d_ag1);
    cudaGetSymbolAddress((void**)&wt1p, d_wt1);
    cudaGetSymbolAddress((void**)&wt2p, d_wt2);
    cudaGetSymbolAddress((void**)&wt3p, d_wt3);
    int* degip; float* zaccp;
    cudaGetSymbolAddress((void**)&degip, d_degi);
    cudaGetSymbolAddress((void**)&zaccp, d_zacc);

    cudaFuncSetAttribute((void*)gemm_mma_kernel<K1PAD, true>,
                         cudaFuncAttributeMaxDynamicSharedMemorySize, GSM_BYTES);
    cudaFuncSetAttribute((void*)gemm_mma_kernel<HH, false>,
                         cudaFuncAttributeMaxDynamicSharedMemorySize, GSM_BYTES);

    // fused prep: degree count + converts + transposes (all independent)
    cudaMemsetAsync(degip, 0, NN * sizeof(int));
    prep_all_kernel<<<NB_PREP, 256>>>(ei, x, pe, W1, W2, W3);

    // CSR scan + fill
    scan_part_kernel<<<SCANB, 1024>>>();
    scan_final_kernel<<<SCANB, 1024>>>();
    fill_csr_kernel<<<(EE + 255) / 256, 256>>>(ei);

    // layer 1: fused pre-aggregation (x + pe), then GEMM with bias+ELU -> h1
    gather_l1_kernel<<<GXB + NN, 128>>>();

    const dim3 ggrid((MM + 127) / 128, HH / 128);
    const uint4* hw4 = reinterpret_cast<const uint4*>(hwp);
    uint4* h24 = reinterpret_cast<uint4*>(h2p);

    gemm_mma_kernel<K1PAD, true><<<ggrid, 256, GSM_BYTES>>>(ag1p, wt1p, h1p, b1);

    // layer 2
    gemm_mma_kernel<HH, false><<<ggrid, 256, GSM_BYTES>>>(h1p, wt2p, hwp, nullptr);
    gather_kernel<false><<<NN, 128>>>(hw4, b2, h24, nullptr, nullptr);

    // layer 3 (+ fused fc head -> d_g)
    gemm_mma_kernel<HH, false><<<ggrid, 256, GSM_BYTES>>>(h2p, wt3p, hwp, nullptr);
    gather_kernel<true><<<NN, 128>>>(hw4, b3, nullptr, fcW, fcb);

    // heads
    cudaMemsetAsync(zaccp, 0, BSZ * HFCC * sizeof(float));
    lin1_kernel<<<dim3(HFCC / 128, (NN + NCH - 1) / NCH), 128>>>(lin1W);
    lin2_kernel<<<BSZ, 256>>>(lin1b, lin2W, lin2b, out);
}

// round 12
// speedup vs baseline: 6.1069x; 1.0110x over previous
#include <cuda_runtime.h>
#include <cuda_bf16.h>
#include <math.h>
#include <cstdint>

// Problem constants
#define BSZ 8
#define NN  15135
#define FF  64
#define GG  73
#define HH  256
#define HFCC 512
#define CCLS 2
#define EE  242160
#define KIN (FF + GG)        // 137
#define MM  (BSZ * NN)       // 121080
#define K1PAD 192            // layer-1 K padded to multiple of 64
#define SCANB 15             // ceil(NN/1024)

// ---------------- scratch (device globals; no dynamic alloc allowed) -------
__device__ int   d_degi[NN];
__device__ float d_dis[NN];
__device__ float d_deginv[NN];
__device__ int   d_csr_ptr[NN + 1];
__device__ int   d_rank[EE];          // per-edge rank within its dst column
__device__ int2  d_ew[EE];            // packed (src, weight-bits)
__device__ int   d_bsum[16];
__device__ __align__(16) __nv_bfloat16 d_hw[(size_t)MM * HH];
__device__ __align__(16) __nv_bfloat16 d_h1[(size_t)MM * HH];
__device__ __align__(16) __nv_bfloat16 d_h2[(size_t)MM * HH];
__device__ __align__(16) __nv_bfloat16 d_ag1[(size_t)MM * K1PAD];  // aggregated concat input
__device__ __align__(16) __nv_bfloat16 d_xb[(size_t)MM * FF];      // x in bf16
__device__ __align__(16) __nv_bfloat16 d_peb[(size_t)NN * GG];     // pe in bf16
__device__ __align__(16) __nv_bfloat16 d_wt1[HH * K1PAD];   // W1^T padded
__device__ __align__(16) __nv_bfloat16 d_wt2[HH * HH];      // W2^T
__device__ __align__(16) __nv_bfloat16 d_wt3[HH * HH];      // W3^T
__device__ float d_g[MM];
__device__ float d_zacc[BSZ * HFCC];

__device__ __forceinline__ float eluf(float v) {
    return v > 0.0f ? v : expm1f(v);
}

__device__ __forceinline__ float2 bf2f(uint32_t u) {
    __nv_bfloat162 m = *reinterpret_cast<__nv_bfloat162*>(&u);
    return make_float2(__bfloat162float(m.x), __bfloat162float(m.y));
}

// accumulate 8 bf16 lanes of u into a[0..7] with weight w
__device__ __forceinline__ void acc8(float* a, uint4 u, float w) {
    float2 m;
    m = bf2f(u.x); a[0] += w * m.x; a[1] += w * m.y;
    m = bf2f(u.y); a[2] += w * m.x; a[3] += w * m.y;
    m = bf2f(u.z); a[4] += w * m.x; a[5] += w * m.y;
    m = bf2f(u.w); a[6] += w * m.x; a[7] += w * m.y;
}

__device__ __forceinline__ uint4 pack8(const float* v) {
    uint4 o;
    __nv_bfloat162 p;
    p = __floats2bfloat162_rn(v[0], v[1]); o.x = *reinterpret_cast<uint32_t*>(&p);
    p = __floats2bfloat162_rn(v[2], v[3]); o.y = *reinterpret_cast<uint32_t*>(&p);
    p = __floats2bfloat162_rn(v[4], v[5]); o.z = *reinterpret_cast<uint32_t*>(&p);
    p = __floats2bfloat162_rn(v[6], v[7]); o.w = *reinterpret_cast<uint32_t*>(&p);
    return o;
}

// ---------------- fused prep: degree count(+rank) + converts + transposes --
#define XITEMS ((long long)MM * 8)
#define PEITEMS ((long long)NN * GG)
#define NB_DEG  ((EE + 255) / 256)                              // 946
#define NB_CONV ((int)((XITEMS + PEITEMS + 255) / 256))         // ~8100
#define NB_TR   (HH * 3)                                        // 768
#define NB_PREP (NB_DEG + NB_CONV + NB_TR)

__global__ __launch_bounds__(256) void prep_all_kernel(
    const int* __restrict__ ei,
    const float* __restrict__ x, const float* __restrict__ pe,
    const float* __restrict__ W1, const float* __restrict__ W2,
    const float* __restrict__ W3)
{
    const int bid = blockIdx.x;
    const int t   = threadIdx.x;
    if (bid < NB_DEG) {
        int e = bid * 256 + t;
        if (e < EE) d_rank[e] = atomicAdd(&d_degi[ei[EE + e]], 1);
    } else if (bid < NB_DEG + NB_CONV) {
        long long i = (long long)(bid - NB_DEG) * 256 + t;
        if (i < XITEMS) {
            const float4* src = reinterpret_cast<const float4*>(x) + 2 * i;
            float4 v0 = src[0], v1 = src[1];
            float v[8] = {v0.x, v0.y, v0.z, v0.w, v1.x, v1.y, v1.z, v1.w};
            reinterpret_cast<uint4*>(d_xb)[i] = pack8(v);
        } else {
            long long j = i - XITEMS;
            if (j < PEITEMS) d_peb[j] = __float2bfloat16_rn(pe[j]);
        }
    } else {
        int j = bid - NB_DEG - NB_CONV;     // 0..767
        int n = j & 255;
        int which = j >> 8;
        if (which == 0) {
            if (t < K1PAD)
                d_wt1[(size_t)n * K1PAD + t] =
                    __float2bfloat16_rn((t < KIN) ? W1[(size_t)t * HH + n] : 0.0f);
        } else {
            const float* W = (which == 1) ? W2 : W3;
            __nv_bfloat16* Wt = (which == 1) ? d_wt2 : d_wt3;
            Wt[(size_t)n * HH + t] = __float2bfloat16_rn(W[(size_t)t * HH + n]);
        }
    }
}

// ---------------- CSR scan ----------------
// stage 1: per-block local exclusive scan + block total + dis/deginv
__global__ __launch_bounds__(1024) void scan_part_kernel() {
    __shared__ int wsum[32];
    const int b = blockIdx.x, t = threadIdx.x;
    const int i = b * 1024 + t;
    const int lane = t & 31, warp = t >> 5;
    int v = 0;
    if (i < NN) {
        v = d_degi[i];
        float d = (float)v + 1.0f;
        d_dis[i]    = rsqrtf(d);
        d_deginv[i] = 1.0f / d;
    }
    int incl = v;
    #pragma unroll
    for (int o = 1; o < 32; o <<= 1) {
        int u = __shfl_up_sync(0xffffffffu, incl, o);
        if (lane >= o) incl += u;
    }
    if (lane == 31) wsum[warp] = incl;
    __syncthreads();
    if (warp == 0) {
        int s = wsum[lane];
        #pragma unroll
        for (int o = 1; o < 32; o <<= 1) {
            int u = __shfl_up_sync(0xffffffffu, s, o);
            if (lane >= o) s += u;
        }
        wsum[lane] = s;
    }
    __syncthreads();
    int wbase = (warp > 0) ? wsum[warp - 1] : 0;
    if (i < NN) d_csr_ptr[i] = wbase + incl - v;   // local exclusive
    if (t == 1023) d_bsum[b] = wsum[31];           // block total
}

// stage 2 (fused): each block re-scans the 15 block sums, adds its offset
__global__ __launch_bounds__(1024) void scan_final_kernel() {
    __shared__ int soff_sh;
    const int t = threadIdx.x;
    if (t < 32) {
        int v = (t < SCANB) ? d_bsum[t] : 0;
        int incl = v;
        #pragma unroll
        for (int o = 1; o < 32; o <<= 1) {
            int u = __shfl_up_sync(0xffffffffu, incl, o);
            if (t >= o) incl += u;
        }
        if (t == (int)blockIdx.x) soff_sh = incl - v;
        if (blockIdx.x == 0 && t == SCANB - 1) d_csr_ptr[NN] = incl;
    }
    __syncthreads();
    const int i = blockIdx.x * 1024 + t;
    if (i < NN) d_csr_ptr[i] += soff_sh;
}

// atomic-free fill: pos = csr_ptr[dst] + rank (recorded during count)
__global__ void fill_csr_kernel(const int* __restrict__ ei) {
    int e = blockIdx.x * blockDim.x + threadIdx.x;
    if (e < EE) {
        int r = ei[e];
        int c = ei[EE + e];
        int pos = d_csr_ptr[c] + d_rank[e];
        d_ew[pos] = make_int2(r, __float_as_int(d_dis[r] * d_dis[c]));
    }
}

// ---------------- layer-1 pre-aggregation (fused x + pe) -------------------
#define GXB ((NN + 1) / 2)
__global__ __launch_bounds__(128) void gather_l1_kernel() {
    const int t = threadIdx.x;
    if (blockIdx.x < GXB) {
        const int n = blockIdx.x * 2 + (t >> 6);
        if (n >= NN) return;
        const int b  = (t >> 3) & 7;
        const int fq = t & 7;
        const uint4* xp = reinterpret_cast<const uint4*>(d_xb) + (size_t)b * NN * 8;

        const int p0 = d_csr_ptr[n];
        const int p1 = d_csr_ptr[n + 1];
        float a[8];
        #pragma unroll
        for (int i = 0; i < 8; i++) a[i] = 0.0f;

        #pragma unroll 4
        for (int e = p0; e < p1; e++) {
            int2  ew = __ldg(&d_ew[e]);
            float w  = __int_as_float(ew.y);
            acc8(a, __ldg(xp + (size_t)ew.x * 8 + fq), w);
        }
        acc8(a, __ldg(xp + (size_t)n * 8 + fq), d_deginv[n]);   // self loop

        reinterpret_cast<uint4*>(d_ag1)[((size_t)b * NN + n) * 24 + fq] = pack8(a);
    } else {
        const int n = blockIdx.x - GXB;
        float a = 0.0f;
        if (t < GG) {
            const int p0 = d_csr_ptr[n];
            const int p1 = d_csr_ptr[n + 1];
            #pragma unroll 4
            for (int e = p0; e < p1; e++) {
                int2  ew = __ldg(&d_ew[e]);
                float w  = __int_as_float(ew.y);
                a += w * __bfloat162float(__ldg(&d_peb[(size_t)ew.x * GG + t]));
            }
            a += d_deginv[n] * __bfloat162float(__ldg(&d_peb[(size_t)n * GG + t]));
        }
        __nv_bfloat16 v = __float2bfloat16_rn(t < GG ? a : 0.0f);
        #pragma unroll
        for (int b = 0; b < BSZ; b++)
            d_ag1[((size_t)b * NN + n) * K1PAD + FF + t] = v;
    }
}

// ================= mma.sync bf16 GEMM with ldmatrix =========================
__device__ __forceinline__ void cp_async16(uint32_t dst, const void* src, int sz) {
    asm volatile("cp.async.cg.shared.global [%0], [%1], 16, %2;"
                 :: "r"(dst), "l"(src), "r"(sz) : "memory");
}

__device__ __forceinline__ void mma_bf16(float* c, const uint32_t* a, const uint32_t* b) {
    asm volatile(
        "mma.sync.aligned.m16n8k16.row.col.f32.bf16.bf16.f32 "
        "{%0,%1,%2,%3}, {%4,%5,%6,%7}, {%8,%9}, {%0,%1,%2,%3};"
        : "+f"(c[0]), "+f"(c[1]), "+f"(c[2]), "+f"(c[3])
        : "r"(a[0]), "r"(a[1]), "r"(a[2]), "r"(a[3]), "r"(b[0]), "r"(b[1]));
}

__device__ __forceinline__ void ldsm_x4(uint32_t* r, uint32_t addr) {
    asm volatile("ldmatrix.sync.aligned.m8n8.x4.shared.b16 {%0,%1,%2,%3}, [%4];"
                 : "=r"(r[0]), "=r"(r[1]), "=r"(r[2]), "=r"(r[3]) : "r"(addr));
}

#define GSTRU 36
#define GBUFU (2 * 128 * GSTRU)
#define GSM_BYTES (2 * GBUFU * 4)

// EPI: fused bias + ELU epilogue (layer 1 writes h1 directly)
template <int KPAD, bool EPI>
__global__ __launch_bounds__(256, 2) void gemm_mma_kernel(
    const __nv_bfloat16* __restrict__ A, const __nv_bfloat16* __restrict__ Wt,
    __nv_bfloat16* __restrict__ hw, const float* __restrict__ bias)
{
    extern __shared__ uint32_t sm[];
    constexpr int NC = KPAD / 64;
    const int t    = threadIdx.x;
    const int lane = t & 31;
    const int wid  = t >> 5;
    const int wm   = wid >> 2;
    const int wn   = wid & 3;
    const int m0   = blockIdx.x * 128;
    const int n0   = blockIdx.y * 128;
    const int g    = lane >> 2;
    const int q    = lane & 3;

    // ldmatrix per-lane address components (bytes, relative to buffer start)
    const int mid  = lane >> 3;          // matrix id 0..3
    const int mrow = lane & 7;           // row within 8x8 matrix
    // A: mid0: (r, c0) mid1: (r+8, c0) mid2: (r, c4) mid3: (r+8, c4)
    const uint32_t offA = (uint32_t)(((wm * 64 + mrow + (mid & 1) * 8) * GSTRU
                                      + (mid >> 1) * 4) * 4);
    // B: mid0: (nj0, c0) mid1: (nj0, c4) mid2: (nj1, c0) mid3: (nj1, c4)
    const uint32_t offB = (uint32_t)((128 * GSTRU                // B region after A
                                      + (wn * 32 + (mid >> 1) * 8 + mrow) * GSTRU
                                      + (mid & 1) * 4) * 4);
    const uint32_t sbase = (uint32_t)__cvta_generic_to_shared(sm);

    float acc[4][4][4];
    #pragma unroll
    for (int mi = 0; mi < 4; mi++)
        #pragma unroll
        for (int nj = 0; nj < 4; nj++)
            #pragma unroll
            for (int r = 0; r < 4; r++) acc[mi][nj][r] = 0.0f;

    auto load_chunk = [&](int ci, int buf) {
        uint32_t* dA = sm + buf * GBUFU;
        uint32_t* dB = dA + 128 * GSTRU;
        const int k0 = ci * 64;
        #pragma unroll
        for (int r = 0; r < 4; r++) {
            int idx = t + r * 256;
            int row = idx >> 3;
            int seg = idx & 7;
            int m   = m0 + row;
            int valid = (m < MM);
            const __nv_bfloat16* srcA = A + (size_t)(valid ? m : 0) * KPAD + k0 + seg * 8;
            cp_async16((uint32_t)__cvta_generic_to_shared(dA + row * GSTRU + seg * 4),
                       srcA, valid ? 16 : 0);
            const __nv_bfloat16* srcB = Wt + (size_t)(n0 + row) * KPAD + k0 + seg * 8;
            cp_async16((uint32_t)__cvta_generic_to_shared(dB + row * GSTRU + seg * 4),
                       srcB, 16);
        }
        asm volatile("cp.async.commit_group;" ::: "memory");
    };

    load_chunk(0, 0);
    if (NC > 1) load_chunk(1, 1);
    else        asm volatile("cp.async.commit_group;" ::: "memory");

    #pragma unroll 1
    for (int i = 0; i < NC; i++) {
        asm volatile("cp.async.wait_group 1;" ::: "memory");
        __syncthreads();
        const uint32_t bufb = sbase + (uint32_t)((i & 1) * GBUFU * 4);
        const uint32_t aA = bufb + offA;
        const uint32_t aB = bufb + offB;

        #pragma unroll
        for (int ks = 0; ks < 4; ks++) {
            const uint32_t kso = (uint32_t)(ks * 32);   // ks*8 u32 = 32 bytes
            uint32_t a[4][4], b[4][2];
            #pragma unroll
            for (int mi = 0; mi < 4; mi++)
                ldsm_x4(a[mi], aA + (uint32_t)(mi * 16 * GSTRU * 4) + kso);
            {
                uint32_t r0[4], r1[4];
                ldsm_x4(r0, aB + kso);
                ldsm_x4(r1, aB + (uint32_t)(16 * GSTRU * 4) + kso);
                b[0][0] = r0[0]; b[0][1] = r0[1]; b[1][0] = r0[2]; b[1][1] = r0[3];
                b[2][0] = r1[0]; b[2][1] = r1[1]; b[3][0] = r1[2]; b[3][1] = r1[3];
            }
            #pragma unroll
            for (int mi = 0; mi < 4; mi++)
                #pragma unroll
                for (int nj = 0; nj < 4; nj++)
                    mma_bf16(acc[mi][nj], a[mi], b[nj]);
        }
        __syncthreads();
        if (i + 2 < NC) load_chunk(i + 2, i & 1);
        else            asm volatile("cp.async.commit_group;" ::: "memory");
    }

    __nv_bfloat162* hw2 = reinterpret_cast<__nv_bfloat162*>(hw);
    #pragma unroll
    for (int mi = 0; mi < 4; mi++) {
        int r = m0 + wm * 64 + mi * 16 + g;
        #pragma unroll
        for (int nj = 0; nj < 4; nj++) {
            int c  = n0 + wn * 32 + nj * 8 + q * 2;
            float v0 = acc[mi][nj][0], v1 = acc[mi][nj][1];
            float v2 = acc[mi][nj][2], v3 = acc[mi][nj][3];
            if (EPI) {
                float2 bv = *reinterpret_cast<const float2*>(bias + c);
                v0 = eluf(v0 + bv.x); v1 = eluf(v1 + bv.y);
                v2 = eluf(v2 + bv.x); v3 = eluf(v3 + bv.y);
            }
            int c2 = c >> 1;
            if (r < MM)
                hw2[(size_t)r * 128 + c2] = __floats2bfloat162_rn(v0, v1);
            if (r + 8 < MM)
                hw2[(size_t)(r + 8) * 128 + c2] = __floats2bfloat162_rn(v2, v3);
        }
    }
}

// ---------------- CSR gather (layers 2/3): LDG.128, 1 block/node ------------
template <bool FUSE_FC>
__global__ __launch_bounds__(128) void gather_kernel(
    const uint4* __restrict__ hw4, const float* __restrict__ bias,
    uint4* __restrict__ hout4,
    const float* __restrict__ fcW, const float* __restrict__ fcb)
{
    const int n  = blockIdx.x;
    const int t  = threadIdx.x;
    const int fq = t & 31;
    const int bp = t >> 5;
    const int b0 = 2 * bp, b1 = 2 * bp + 1;
    const size_t plane = (size_t)NN * 32;
    const uint4* hp0 = hw4 + (size_t)b0 * plane;
    const uint4* hp1 = hw4 + (size_t)b1 * plane;

    __shared__ float sfw[FUSE_FC ? 768 : 1];
    if (FUSE_FC) {
        #pragma unroll
        for (int i = t; i < 768; i += 128) sfw[i] = fcW[i];
        __syncthreads();
    }

    const int p0 = d_csr_ptr[n];
    const int p1 = d_csr_ptr[n + 1];

    float a0[8], a1v[8];
    #pragma unroll
    for (int i = 0; i < 8; i++) { a0[i] = 0.0f; a1v[i] = 0.0f; }

    #pragma unroll 4
    for (int e = p0; e < p1; e++) {
        int2  ew = __ldg(&d_ew[e]);
        float w  = __int_as_float(ew.y);
        size_t ro = (size_t)ew.x * 32 + fq;
        uint4 u0 = __ldg(hp0 + ro);
        uint4 u1 = __ldg(hp1 + ro);
        acc8(a0,  u0, w);
        acc8(a1v, u1, w);
    }

    const float di = d_deginv[n];
    const float4 bsa = reinterpret_cast<const float4*>(bias)[2 * fq];
    const float4 bsb = reinterpret_cast<const float4*>(bias)[2 * fq + 1];
    const float bs[8] = {bsa.x, bsa.y, bsa.z, bsa.w, bsb.x, bsb.y, bsb.z, bsb.w};

    size_t so = (size_t)n * 32 + fq;
    acc8(a0,  __ldg(hp0 + so), di);
    acc8(a1v, __ldg(hp1 + so), di);

    float v0[8], v1[8];
    #pragma unroll
    for (int i = 0; i < 8; i++) {
        v0[i] = eluf(a0[i]  + bs[i]);
        v1[i] = eluf(a1v[i] + bs[i]);
    }

    if (!FUSE_FC) {
        hout4[(size_t)b0 * plane + so] = pack8(v0);
        hout4[(size_t)b1 * plane + so] = pack8(v1);
    } else {
        const uint4* h1p0 = reinterpret_cast<const uint4*>(d_h1) + (size_t)b0 * plane;
        const uint4* h1p1 = reinterpret_cast<const uint4*>(d_h1) + (size_t)b1 * plane;
        const uint4* h2p0 = reinterpret_cast<const uint4*>(d_h2) + (size_t)b0 * plane;
        const uint4* h2p1 = reinterpret_cast<const uint4*>(d_h2) + (size_t)b1 * plane;
        float h10[8], h11[8], h20[8], h21[8];
        #pragma unroll
        for (int i = 0; i < 8; i++) { h10[i]=h11[i]=h20[i]=h21[i]=0.0f; }
        acc8(h10, __ldg(h1p0 + so), 1.0f); acc8(h11, __ldg(h1p1 + so), 1.0f);
        acc8(h20, __ldg(h2p0 + so), 1.0f); acc8(h21, __ldg(h2p1 + so), 1.0f);
        float g0 = 0.0f, g1 = 0.0f;
        #pragma unroll
        for (int i = 0; i < 8; i++) {
            const float* fw = &sfw[24 * fq + 3 * i];
            g0 += h10[i] * fw[0] + h20[i] * fw[1] + v0[i] * fw[2];
            g1 += h11[i] * fw[0] + h21[i] * fw[1] + v1[i] * fw[2];
        }
        #pragma unroll
        for (int o = 16; o > 0; o >>= 1) {
            g0 += __shfl_down_sync(0xffffffffu, g0, o);
            g1 += __shfl_down_sync(0xffffffffu, g1, o);
        }
        if (fq == 0) {
            float fb = fcb[0];
            d_g[(size_t)b0 * NN + n] = g0 + fb;
            d_g[(size_t)b1 * NN + n] = g1 + fb;
        }
    }
}

// ---------------- lin1: g[b,N] @ lin1_W[N,512] (accumulate) ----------------
#define NCH 256
__global__ __launch_bounds__(128) void lin1_kernel(const float* __restrict__ W)
{
    __shared__ float gs[BSZ][NCH];
    const int j  = blockIdx.x * 128 + threadIdx.x;
    const int n0 = blockIdx.y * NCH;
    const int cn = min(NCH, NN - n0);
    for (int idx = threadIdx.x; idx < BSZ * NCH; idx += 128) {
        int b  = idx >> 8;
        int nl = idx & (NCH - 1);
        gs[b][nl] = (nl < cn) ? d_g[(size_t)b * NN + n0 + nl] : 0.0f;
    }
    __syncthreads();
    float acc[BSZ];
    #pragma unroll
    for (int b = 0; b < BSZ; b++) acc[b] = 0.0f;
    for (int nl = 0; nl < cn; nl++) {
        float w = W[(size_t)(n0 + nl) * HFCC + j];
        #pragma unroll
        for (int b = 0; b < BSZ; b++) acc[b] += gs[b][nl] * w;
    }
    #pragma unroll
    for (int b = 0; b < BSZ; b++) atomicAdd(&d_zacc[b * HFCC + j], acc[b]);
}

// ---------------- lin2 + log_softmax ----------------
__global__ __launch_bounds__(256) void lin2_kernel(
    const float* __restrict__ lin1b, const float* __restrict__ lin2W,
    const float* __restrict__ lin2b, float* __restrict__ out)
{
    const int b = blockIdx.x;
    const int t = threadIdx.x;
    float s0 = 0.0f, s1 = 0.0f;
    for (int j = t; j < HFCC; j += 256) {
        float z = d_zacc[b * HFCC + j] + lin1b[j];
        z = eluf(z);
        s0 += z * lin2W[j * 2 + 0];
        s1 += z * lin2W[j * 2 + 1];
    }
    __shared__ float r0[256], r1[256];
    r0[t] = s0; r1[t] = s1;
    __syncthreads();
    for (int o = 128; o > 0; o >>= 1) {
        if (t < o) { r0[t] += r0[t + o]; r1[t] += r1[t + o]; }
        __syncthreads();
    }
    if (t == 0) {
        float o0 = r0[0] + lin2b[0];
        float o1 = r1[0] + lin2b[1];
        float mx = fmaxf(o0, o1);
        float lse = mx + logf(expf(o0 - mx) + expf(o1 - mx));
        out[b * CCLS + 0] = o0 - lse;
        out[b * CCLS + 1] = o1 - lse;
    }
}

// ---------------- launcher ----------------
extern "C" void kernel_launch(void* const* d_in, const int* in_sizes, int n_in,
                              void* d_out, int out_size)
{
    const float* x     = (const float*)d_in[0];
    const int*   ei    = (const int*)d_in[2];   // int32 [2, E]
    const float* pe    = (const float*)d_in[3];
    const float* W1    = (const float*)d_in[4];
    const float* b1    = (const float*)d_in[5];
    const float* W2    = (const float*)d_in[6];
    const float* b2    = (const float*)d_in[7];
    const float* W3    = (const float*)d_in[8];
    const float* b3    = (const float*)d_in[9];
    const float* fcW   = (const float*)d_in[10];
    const float* fcb   = (const float*)d_in[11];
    const float* lin1W = (const float*)d_in[12];
    const float* lin1b = (const float*)d_in[13];
    const float* lin2W = (const float*)d_in[14];
    const float* lin2b = (const float*)d_in[15];
    float* out = (float*)d_out;

    __nv_bfloat16 *hwp, *h1p, *h2p, *ag1p, *wt1p, *wt2p, *wt3p;
    cudaGetSymbolAddress((void**)&hwp,  d_hw);
    cudaGetSymbolAddress((void**)&h1p,  d_h1);
    cudaGetSymbolAddress((void**)&h2p,  d_h2);
    cudaGetSymbolAddress((void**)&ag1p, d_ag1);
    cudaGetSymbolAddress((void**)&wt1p, d_wt1);
    cudaGetSymbolAddress((void**)&wt2p, d_wt2);
    cudaGetSymbolAddress((void**)&wt3p, d_wt3);
    int* degip; float* zaccp;
    cudaGetSymbolAddress((void**)&degip, d_degi);
    cudaGetSymbolAddress((void**)&zaccp, d_zacc);

    cudaFuncSetAttribute((void*)gemm_mma_kernel<K1PAD, true>,
                         cudaFuncAttributeMaxDynamicSharedMemorySize, GSM_BYTES);
    cudaFuncSetAttribute((void*)gemm_mma_kernel<HH, false>,
                         cudaFuncAttributeMaxDynamicSharedMemorySize, GSM_BYTES);

    // fused prep: degree count(+rank) + converts + transposes
    cudaMemsetAsync(degip, 0, NN * sizeof(int));
    prep_all_kernel<<<NB_PREP, 256>>>(ei, x, pe, W1, W2, W3);

    // CSR scan + atomic-free fill
    scan_part_kernel<<<SCANB, 1024>>>();
    scan_final_kernel<<<SCANB, 1024>>>();
    fill_csr_kernel<<<(EE + 255) / 256, 256>>>(ei);

    // layer 1: fused pre-aggregation (x + pe), then GEMM with bias+ELU -> h1
    gather_l1_kernel<<<GXB + NN, 128>>>();

    const dim3 ggrid((MM + 127) / 128, HH / 128);
    const uint4* hw4 = reinterpret_cast<const uint4*>(hwp);
    uint4* h24 = reinterpret_cast<uint4*>(h2p);

    gemm_mma_kernel<K1PAD, true><<<ggrid, 256, GSM_BYTES>>>(ag1p, wt1p, h1p, b1);

    // layer 2
    gemm_mma_kernel<HH, false><<<ggrid, 256, GSM_BYTES>>>(h1p, wt2p, hwp, nullptr);
    gather_kernel<false><<<NN, 128>>>(hw4, b2, h24, nullptr, nullptr);

    // layer 3 (+ fused fc head -> d_g)
    gemm_mma_kernel<HH, false><<<ggrid, 256, GSM_BYTES>>>(h2p, wt3p, hwp, nullptr);
    gather_kernel<true><<<NN, 128>>>(hw4, b3, nullptr, fcW, fcb);

    // heads
    cudaMemsetAsync(zaccp, 0, BSZ * HFCC * sizeof(float));
    lin1_kernel<<<dim3(HFCC / 128, (NN + NCH - 1) / NCH), 128>>>(lin1W);
    lin2_kernel<<<BSZ, 256>>>(lin1b, lin2W, lin2b, out);
}